// round 8
// baseline (speedup 1.0000x reference)
#include <cuda_runtime.h>
#include <cuda_bf16.h>
#include <cstdint>
#include <math.h>

#define B_ 4
#define S_ 2048
#define E_ 1024
#define H_ 4
#define D_ 256
#define BH_ 16
#define MSZ (B_*S_*E_)

typedef __nv_bfloat16 bf16;

// ================= device scratch =================
__device__ bf16 g_HSh[MSZ], g_HSl[MSZ];
__device__ bf16 g_WqTh[E_*E_], g_WqTl[E_*E_];
__device__ bf16 g_WkTh[E_*E_], g_WkTl[E_*E_];
__device__ bf16 g_WvTh[E_*E_], g_WvTl[E_*E_];
__device__ bf16 g_WoTh[E_*E_], g_WoTl[E_*E_];
__device__ bf16 g_memTh[H_*D_*D_], g_memTl[H_*D_*D_];
__device__ bf16 g_Qh[MSZ], g_Ql[MSZ], g_Kh[MSZ], g_Kl[MSZ];
__device__ bf16 g_SQh[MSZ], g_SQl[MSZ], g_SKh[MSZ], g_SKl[MSZ];
__device__ bf16 g_ABh[MSZ], g_ABl[MSZ];
__device__ bf16 g_VTh[MSZ], g_VTl[MSZ];
__device__ bf16 g_UTh[MSZ], g_UTl[MSZ];
__device__ bf16 g_SKTh[MSZ], g_SKTl[MSZ];
__device__ float g_Vf[MSZ], g_Uf[MSZ], g_SKf[MSZ], g_AO[MSZ];
__device__ float g_Zq[BH_*S_], g_Zk[BH_*S_];
__device__ float g_Zpart[BH_*8*D_];

// ================= helpers =================
__device__ __forceinline__ uint32_t smem_u32(const void* p){
    uint32_t a;
    asm("{ .reg .u64 t; cvta.to.shared.u64 t, %1; cvt.u32.u64 %0, t; }" : "=r"(a) : "l"(p));
    return a;
}
#define SWZ(o) ((o) ^ (((o) >> 3) & 0x70))

#define CP_ASYNC(daddr, gptr) \
    asm volatile("cp.async.cg.shared.global [%0], [%1], 16;" :: "r"(daddr), "l"(gptr) : "memory")
#define CP_COMMIT() asm volatile("cp.async.commit_group;" ::: "memory")
#define CP_WAIT(n)  asm volatile("cp.async.wait_group %0;" :: "n"(n) : "memory")

__device__ __forceinline__ void ldm_x4(uint32_t& r0, uint32_t& r1, uint32_t& r2, uint32_t& r3, uint32_t a){
    asm volatile("ldmatrix.sync.aligned.m8n8.x4.shared.b16 {%0,%1,%2,%3}, [%4];"
        : "=r"(r0), "=r"(r1), "=r"(r2), "=r"(r3) : "r"(a));
}
__device__ __forceinline__ void mma16816(float* c, const uint32_t* a, const uint32_t* b){
    asm volatile("mma.sync.aligned.m16n8k16.row.col.f32.bf16.bf16.f32 "
        "{%0,%1,%2,%3}, {%4,%5,%6,%7}, {%8,%9}, {%0,%1,%2,%3};"
        : "+f"(c[0]), "+f"(c[1]), "+f"(c[2]), "+f"(c[3])
        : "r"(a[0]), "r"(a[1]), "r"(a[2]), "r"(a[3]), "r"(b[0]), "r"(b[1]));
}

__device__ __forceinline__ void store_split(bf16* ph, bf16* pl, size_t i, float v){
    bf16 h = __float2bfloat16(v);
    ph[i] = h;
    pl[i] = __float2bfloat16(v - __bfloat162float(h));
}

enum { EP_F32=0, EP_SIGQK=1, EP_BIAS=2, EP_AMEM=3, EP_DELTA=4, EP_MEMUPD=5 };

// ================= 512-thread HMMA GEMM (validated) =================
#define G5_STG 98304
#define G5_SMEM (2*G5_STG)

__global__ void __launch_bounds__(512,1) tc_gemm(
    const bf16* __restrict__ Ahg, const bf16* __restrict__ Alg,
    const bf16* __restrict__ Bhg, const bf16* __restrict__ Blg,
    int K, int lda, int ldb, int ldc,
    long sAb, long sAh, long sBb, long sBh, long sCb, long sCh,
    int mode,
    float* __restrict__ C, bf16* __restrict__ O1h, bf16* __restrict__ O1l,
    bf16* __restrict__ O2h, bf16* __restrict__ O2l,
    const float* __restrict__ rowdiv, const float* __restrict__ mix,
    const float* __restrict__ betas, const float* __restrict__ bias)
{
    extern __shared__ char smemc[];
    int z = blockIdx.z, bb = z / H_, hh = z % H_;
    int m0 = blockIdx.y*128, n0 = blockIdx.x*256;

    const bf16* Ah = Ahg + (size_t)bb*sAb + (size_t)hh*sAh;
    const bf16* Al = Alg + (size_t)bb*sAb + (size_t)hh*sAh;
    const bf16* Bh = Bhg + (size_t)bb*sBb + (size_t)hh*sBh;
    const bf16* Bl = Blg + (size_t)bb*sBb + (size_t)hh*sBh;
    size_t coff = (size_t)bb*sCb + (size_t)hh*sCh;

    int tid = threadIdx.x, wid = tid >> 5, lid = tid & 31;
    uint32_t sb = smem_u32(smemc);
    int wm = wid & 1, wn = wid >> 1;
    int mbase = wm*64, nbase = wn*32;

    float acc[4][4][4];
    #pragma unroll
    for (int i=0;i<4;i++)
        #pragma unroll
        for (int j=0;j<4;j++)
            #pragma unroll
            for (int r=0;r<4;r++) acc[i][j][r]=0.f;

    int nch = K >> 6;
    int row_l = tid >> 3, v_l = tid & 7;

    auto issue = [&](int ci, int s){
        int stg = s*G5_STG, kc0 = ci << 6;
        #pragma unroll
        for (int i=0;i<2;i++){
            int row = row_l + 64*i;
            uint32_t o = SWZ(row*128 + v_l*16);
            CP_ASYNC(sb+stg+o,       Ah + (size_t)(m0+row)*lda + kc0 + v_l*8);
            CP_ASYNC(sb+stg+16384+o, Al + (size_t)(m0+row)*lda + kc0 + v_l*8);
        }
        #pragma unroll
        for (int i=0;i<4;i++){
            int row = row_l + 64*i;
            uint32_t o = SWZ(row*128 + v_l*16);
            CP_ASYNC(sb+stg+32768+o, Bh + (size_t)(n0+row)*ldb + kc0 + v_l*8);
            CP_ASYNC(sb+stg+65536+o, Bl + (size_t)(n0+row)*ldb + kc0 + v_l*8);
        }
        CP_COMMIT();
    };

    issue(0, 0);
    if (nch > 1) issue(1, 1);

    for (int ci=0; ci<nch; ci++){
        if (ci+1 < nch) { CP_WAIT(1); } else { CP_WAIT(0); }
        __syncthreads();
        int stg = (ci&1)*G5_STG;

        #pragma unroll
        for (int ks=0; ks<4; ks++){
            int colb = ks*32 + ((lid>>4)&1)*16;
            uint32_t ah[4][4], al[4][4];
            #pragma unroll
            for (int mt=0; mt<4; mt++){
                int row = mbase + mt*16 + (lid & 15);
                uint32_t off = SWZ(row*128 + colb);
                ldm_x4(ah[mt][0],ah[mt][1],ah[mt][2],ah[mt][3], sb+stg+off);
                ldm_x4(al[mt][0],al[mt][1],al[mt][2],al[mt][3], sb+stg+16384+off);
            }
            uint32_t bh[4][2], bl[4][2];
            #pragma unroll
            for (int g=0; g<2; g++){
                int row = nbase + g*16 + (lid & 7) + ((lid>>4)&1)*8;
                int cb2 = ks*32 + ((lid>>3)&1)*16;
                uint32_t off = SWZ(row*128 + cb2);
                uint32_t r0,r1,r2,r3;
                ldm_x4(r0,r1,r2,r3, sb+stg+32768+off);
                bh[2*g][0]=r0; bh[2*g][1]=r1; bh[2*g+1][0]=r2; bh[2*g+1][1]=r3;
                ldm_x4(r0,r1,r2,r3, sb+stg+65536+off);
                bl[2*g][0]=r0; bl[2*g][1]=r1; bl[2*g+1][0]=r2; bl[2*g+1][1]=r3;
            }
            #pragma unroll
            for (int mt=0; mt<4; mt++)
                #pragma unroll
                for (int nt=0; nt<4; nt++){
                    mma16816(acc[mt][nt], ah[mt], bh[nt]);
                    mma16816(acc[mt][nt], ah[mt], bl[nt]);
                    mma16816(acc[mt][nt], al[mt], bh[nt]);
                }
        }
        __syncthreads();
        if (ci+2 < nch) issue(ci+2, ci&1);
    }

    float* buf = (float*)smemc;
    int tg = lid >> 2, t4 = lid & 3;
    #pragma unroll
    for (int mt=0; mt<4; mt++)
        #pragma unroll
        for (int nt=0; nt<4; nt++)
            #pragma unroll
            for (int r=0; r<4; r++){
                int m = mbase + mt*16 + tg + (r>=2 ? 8 : 0);
                int c = nbase + nt*8 + t4*2 + (r&1);
                buf[m*260 + c] = acc[mt][nt][r];
            }
    __syncthreads();

    float gate = 0.f;
    if (mode == EP_AMEM) gate = 1.f/(1.f + __expf(-betas[hh]));

    #pragma unroll 4
    for (int e=0; e<64; e++){
        int flat = e*512 + tid;
        int row = flat >> 8, col = flat & 255;
        float v = buf[row*260 + col];
        int m = m0 + row, c = n0 + col;
        size_t idx = coff + (size_t)m*ldc + c;
        if (mode == EP_F32) {
            C[idx] = v;
        } else if (mode == EP_SIGQK) {
            store_split(O1h, O1l, idx, v);
            float sg = v > 0.f ? v + 1.f : __expf(v);
            store_split(O2h, O2l, idx, sg);
            if (C) C[idx] = sg;
        } else if (mode == EP_BIAS) {
            C[idx] = v + bias[c];
        } else if (mode == EP_AMEM) {
            float rinv = 1.f/(rowdiv[(size_t)z*S_ + m] + 1e-6f);
            float val = gate*(v*rinv) + (1.f-gate)*mix[idx];
            store_split(O1h, O1l, idx, val);
        } else if (mode == EP_DELTA) {
            float rinv = 1.f/(rowdiv[(size_t)z*S_ + m] + 1e-6f);
            C[idx] = mix[idx] - v*rinv;
        } else {
            float mv = mix[(size_t)hh*D_*D_ + (size_t)m*D_ + c];
            C[idx] = mv + v;
        }
    }
}

// ================= fused flash attention (512 threads, 16 warps) =================
// warp grid: 4(m: 32 rows) x 4(n). S: warp tile 32x32. PV: warp tile 32x64.
#define STG_BYTES 65536
#define FA_P     131072
#define FA_STAT  196608
#define FA_SMEM  (196608 + 3072)

__global__ void __launch_bounds__(512,1) fa_kernel(
    const bf16* __restrict__ Qhg, const bf16* __restrict__ Qlg,
    const bf16* __restrict__ Khg, const bf16* __restrict__ Klg,
    const bf16* __restrict__ VThg, const bf16* __restrict__ VTlg,
    float* __restrict__ AO)
{
    extern __shared__ char smc[];
    uint32_t sb = smem_u32(smc);
    int bid = blockIdx.x;
    int z  = (bid>>1)&15;
    int mi = (bid&1) ? (bid>>5) : 15-(bid>>5);
    int bb = z / H_, hh = z % H_;
    int m0 = mi*128;

    int tid = threadIdx.x, wid = tid>>5, lid = tid&31;
    int wm = wid&3, wn = wid>>2;            // 4 x 4 warp grid
    int tg = lid>>2, t4 = lid&3;

    const bf16* Qh_ = Qhg + (size_t)bb*S_*E_ + hh*D_;
    const bf16* Ql_ = Qlg + (size_t)bb*S_*E_ + hh*D_;
    const bf16* Kh_ = Khg + (size_t)bb*S_*E_ + hh*D_;
    const bf16* Kl_ = Klg + (size_t)bb*S_*E_ + hh*D_;
    const bf16* VTh_ = VThg + (size_t)z*D_*S_;
    const bf16* VTl_ = VTlg + (size_t)z*D_*S_;

    float* m_s = (float*)(smc + FA_STAT);
    float* l_s = (float*)(smc + FA_STAT + 512);
    float* red = (float*)(smc + FA_STAT + 1024);

    if (tid < 128){ m_s[tid] = -1e30f; l_s[tid] = 0.f; }

    float acc_o[2][8][4];
    #pragma unroll
    for (int a=0;a<2;a++)
        #pragma unroll
        for (int b=0;b<8;b++)
            #pragma unroll
            for (int r=0;r<4;r++) acc_o[a][b][r]=0.f;
    __syncthreads();

    int row_l = tid>>3, v_l = tid&7;        // 64 rows/pass

    for (int j=0; j<=mi; j++){
        int jb = j*128;
        float acc_s[2][4][4];
        #pragma unroll
        for (int a=0;a<2;a++)
            #pragma unroll
            for (int b=0;b<4;b++)
                #pragma unroll
                for (int r=0;r<4;r++) acc_s[a][b][r]=0.f;

        auto issueS = [&](int c, int s){
            int stg = s*STG_BYTES, kc0 = c*64;
            #pragma unroll
            for (int i=0;i<2;i++){
                int row = row_l + 64*i;
                uint32_t o = SWZ(row*128 + v_l*16);
                CP_ASYNC(sb+stg+o,       Qh_ + (size_t)(m0+row)*E_ + kc0 + v_l*8);
                CP_ASYNC(sb+stg+16384+o, Ql_ + (size_t)(m0+row)*E_ + kc0 + v_l*8);
                CP_ASYNC(sb+stg+32768+o, Kh_ + (size_t)(jb+row)*E_ + kc0 + v_l*8);
                CP_ASYNC(sb+stg+49152+o, Kl_ + (size_t)(jb+row)*E_ + kc0 + v_l*8);
            }
            CP_COMMIT();
        };
        auto issueV = [&](int kc, int s){
            int stg = s*STG_BYTES;
            #pragma unroll
            for (int i=0;i<4;i++){
                int row = row_l + 64*i;
                uint32_t o = SWZ(row*128 + v_l*16);
                CP_ASYNC(sb+stg+o,       VTh_ + (size_t)row*S_ + jb + kc*64 + v_l*8);
                CP_ASYNC(sb+stg+32768+o, VTl_ + (size_t)row*S_ + jb + kc*64 + v_l*8);
            }
            CP_COMMIT();
        };

        // ---------- S = Q K^T ----------
        issueS(0,0); issueS(1,1);
        for (int c=0;c<4;c++){
            if (c<3) { CP_WAIT(1); } else { CP_WAIT(0); }
            __syncthreads();
            int stg = (c&1)*STG_BYTES;
            #pragma unroll
            for (int ks=0; ks<4; ks++){
                uint32_t bh[4][2], bl[4][2];
                #pragma unroll
                for (int g=0; g<2; g++){
                    int row = wn*32 + g*16 + (lid&7) + ((lid>>4)&1)*8;
                    int cb2 = ks*32 + ((lid>>3)&1)*16;
                    uint32_t off = SWZ(row*128 + cb2);
                    uint32_t r0,r1,r2,r3;
                    ldm_x4(r0,r1,r2,r3, sb+stg+32768+off);
                    bh[2*g][0]=r0; bh[2*g][1]=r1; bh[2*g+1][0]=r2; bh[2*g+1][1]=r3;
                    ldm_x4(r0,r1,r2,r3, sb+stg+49152+off);
                    bl[2*g][0]=r0; bl[2*g][1]=r1; bl[2*g+1][0]=r2; bl[2*g+1][1]=r3;
                }
                #pragma unroll
                for (int mt=0; mt<2; mt++){
                    int row = wm*32 + mt*16 + (lid&15);
                    uint32_t colb = ks*32 + ((lid>>4)&1)*16;
                    uint32_t off = SWZ(row*128 + colb);
                    uint32_t ah[4], al[4];
                    ldm_x4(ah[0],ah[1],ah[2],ah[3], sb+stg+off);
                    ldm_x4(al[0],al[1],al[2],al[3], sb+stg+16384+off);
                    #pragma unroll
                    for (int nt=0;nt<4;nt++){
                        mma16816(acc_s[mt][nt], ah, bh[nt]);
                        mma16816(acc_s[mt][nt], ah, bl[nt]);
                        mma16816(acc_s[mt][nt], al, bh[nt]);
                    }
                }
            }
            __syncthreads();
            if (c==0) issueS(2,0);
            else if (c==1) issueS(3,1);
        }

        issueV(0,0); issueV(1,1);

        // ---------- online softmax ----------
        if (j == mi){
            #pragma unroll
            for (int mt=0; mt<2; mt++)
                #pragma unroll
                for (int nt=0; nt<4; nt++)
                    #pragma unroll
                    for (int r=0;r<4;r++){
                        int srow = wm*32 + mt*16 + tg + ((r>>1)&1)*8;
                        int scol = wn*32 + nt*8 + t4*2 + (r&1);
                        if (scol > srow) acc_s[mt][nt][r] = -1e30f;
                    }
        }
        float rmax[2][2];
        #pragma unroll
        for (int mt=0; mt<2; mt++)
            #pragma unroll
            for (int hf=0; hf<2; hf++){
                float m = -1e30f;
                #pragma unroll
                for (int nt=0; nt<4; nt++){
                    m = fmaxf(m, acc_s[mt][nt][hf*2+0]);
                    m = fmaxf(m, acc_s[mt][nt][hf*2+1]);
                }
                m = fmaxf(m, __shfl_xor_sync(0xffffffffu, m, 1));
                m = fmaxf(m, __shfl_xor_sync(0xffffffffu, m, 2));
                rmax[mt][hf] = m;
            }
        if (t4 == 0){
            #pragma unroll
            for (int mt=0; mt<2; mt++)
                #pragma unroll
                for (int hf=0; hf<2; hf++)
                    red[wn*128 + wm*32 + mt*16 + tg + hf*8] = rmax[mt][hf];
        }
        __syncthreads();

        float mnew[2][2], alpha[2][2], rsum[2][2];
        #pragma unroll
        for (int mt=0; mt<2; mt++)
            #pragma unroll
            for (int hf=0; hf<2; hf++){
                int row = wm*32 + mt*16 + tg + hf*8;
                float rm = fmaxf(fmaxf(red[row], red[128+row]), fmaxf(red[256+row], red[384+row]));
                float mo = m_s[row];
                float mn = fmaxf(mo, rm);
                mnew[mt][hf] = mn;
                alpha[mt][hf] = __expf(mo - mn);
                rsum[mt][hf] = 0.f;
            }
        #pragma unroll
        for (int mt=0; mt<2; mt++)
            #pragma unroll
            for (int nt=0; nt<4; nt++)
                #pragma unroll
                for (int r=0;r<4;r++){
                    int hf = r>>1;
                    float p = __expf(acc_s[mt][nt][r] - mnew[mt][hf]);
                    acc_s[mt][nt][r] = p;
                    rsum[mt][hf] += p;
                }
        #pragma unroll
        for (int mt=0; mt<2; mt++)
            #pragma unroll
            for (int hf=0; hf<2; hf++){
                rsum[mt][hf] += __shfl_xor_sync(0xffffffffu, rsum[mt][hf], 1);
                rsum[mt][hf] += __shfl_xor_sync(0xffffffffu, rsum[mt][hf], 2);
            }
        __syncthreads();
        if (t4 == 0){
            #pragma unroll
            for (int mt=0; mt<2; mt++)
                #pragma unroll
                for (int hf=0; hf<2; hf++)
                    red[wn*128 + wm*32 + mt*16 + tg + hf*8] = rsum[mt][hf];
        }
        #pragma unroll
        for (int mt=0; mt<2; mt++)
            #pragma unroll
            for (int nt=0; nt<4; nt++)
                #pragma unroll
                for (int rp=0; rp<2; rp++){
                    int row = wm*32 + mt*16 + tg + rp*8;
                    int col = wn*32 + nt*8 + t4*2;
                    float p0 = acc_s[mt][nt][rp*2+0];
                    float p1 = acc_s[mt][nt][rp*2+1];
                    bf16 h0 = __float2bfloat16(p0);
                    bf16 h1 = __float2bfloat16(p1);
                    bf16 l0 = __float2bfloat16(p0 - __bfloat162float(h0));
                    bf16 l1 = __float2bfloat16(p1 - __bfloat162float(h1));
                    uint32_t o = (uint32_t)(col>>6)*16384u + SWZ((uint32_t)row*128 + (col&63)*2);
                    *(__nv_bfloat162*)(smc + FA_P + o)         = __nv_bfloat162(h0, h1);
                    *(__nv_bfloat162*)(smc + FA_P + 32768 + o) = __nv_bfloat162(l0, l1);
                }
        #pragma unroll
        for (int mt=0; mt<2; mt++)
            #pragma unroll
            for (int nt=0; nt<8; nt++)
                #pragma unroll
                for (int r=0;r<4;r++)
                    acc_o[mt][nt][r] *= alpha[mt][r>>1];
        __syncthreads();
        if (wn == 0 && t4 == 0){
            #pragma unroll
            for (int mt=0; mt<2; mt++)
                #pragma unroll
                for (int hf=0; hf<2; hf++){
                    int row = wm*32 + mt*16 + tg + hf*8;
                    float rs = red[row] + red[128+row] + red[256+row] + red[384+row];
                    l_s[row] = l_s[row]*alpha[mt][hf] + rs;
                    m_s[row] = mnew[mt][hf];
                }
        }

        // ---------- O += P V ----------
        for (int kc=0; kc<2; kc++){
            if (kc==0) { CP_WAIT(1); } else { CP_WAIT(0); }
            __syncthreads();
            int stg = kc*STG_BYTES;
            uint32_t pb = FA_P + kc*16384;
            #pragma unroll
            for (int ks=0; ks<4; ks++){
                uint32_t bh[8][2], bl[8][2];
                #pragma unroll
                for (int g=0; g<4; g++){
                    int row = wn*64 + g*16 + (lid&7) + ((lid>>4)&1)*8;
                    int cb2 = ks*32 + ((lid>>3)&1)*16;
                    uint32_t off = SWZ(row*128 + cb2);
                    uint32_t r0,r1,r2,r3;
                    ldm_x4(r0,r1,r2,r3, sb+stg+off);
                    bh[2*g][0]=r0; bh[2*g][1]=r1; bh[2*g+1][0]=r2; bh[2*g+1][1]=r3;
                    ldm_x4(r0,r1,r2,r3, sb+stg+32768+off);
                    bl[2*g][0]=r0; bl[2*g][1]=r1; bl[2*g+1][0]=r2; bl[2*g+1][1]=r3;
                }
                #pragma unroll
                for (int mt=0; mt<2; mt++){
                    int row = wm*32 + mt*16 + (lid&15);
                    uint32_t colb = ks*32 + ((lid>>4)&1)*16;
                    uint32_t off = SWZ(row*128 + colb);
                    uint32_t ah[4], al[4];
                    ldm_x4(ah[0],ah[1],ah[2],ah[3], sb+pb+off);
                    ldm_x4(al[0],al[1],al[2],al[3], sb+pb+32768+off);
                    #pragma unroll
                    for (int nt=0;nt<8;nt++){
                        mma16816(acc_o[mt][nt], ah, bh[nt]);
                        mma16816(acc_o[mt][nt], ah, bl[nt]);
                        mma16816(acc_o[mt][nt], al, bh[nt]);
                    }
                }
            }
            __syncthreads();
        }
    }

    // ---------- normalize + store ----------
    __syncthreads();
    float* AOp = AO + (size_t)bb*S_*E_ + hh*D_;
    #pragma unroll
    for (int mt=0; mt<2; mt++)
        #pragma unroll
        for (int hf=0; hf<2; hf++){
            int row = wm*32 + mt*16 + tg + hf*8;
            float linv = 1.f/l_s[row];
            #pragma unroll
            for (int nt=0; nt<8; nt++){
                int col = wn*64 + nt*8 + t4*2;
                float2 v;
                v.x = acc_o[mt][nt][hf*2+0]*linv;
                v.y = acc_o[mt][nt][hf*2+1]*linv;
                *(float2*)(AOp + (size_t)(m0+row)*E_ + col) = v;
            }
        }
}

// ================= small kernels =================
__global__ void split_f32(const float* __restrict__ src, bf16* __restrict__ h, bf16* __restrict__ l, int n4){
    int i = blockIdx.x*blockDim.x + threadIdx.x;
    if (i >= n4) return;
    float4 v = ((const float4*)src)[i];
    size_t o = (size_t)i*4;
    store_split(h, l, o+0, v.x); store_split(h, l, o+1, v.y);
    store_split(h, l, o+2, v.z); store_split(h, l, o+3, v.w);
}

__global__ void transW(const float* __restrict__ W, bf16* __restrict__ Th, bf16* __restrict__ Tl){
    __shared__ float t[32][33];
    int k0 = blockIdx.x*32, n0 = blockIdx.y*32;
    int tx = threadIdx.x, ty = threadIdx.y;
    #pragma unroll
    for (int i=0;i<32;i+=8) t[ty+i][tx] = W[(size_t)(k0+ty+i)*E_ + n0+tx];
    __syncthreads();
    #pragma unroll
    for (int i=0;i<32;i+=8){
        size_t o = (size_t)(n0+ty+i)*E_ + k0+tx;
        store_split(Th, Tl, o, t[tx][ty+i]);
    }
}

__global__ void transBH(const float* __restrict__ X, bf16* __restrict__ Th, bf16* __restrict__ Tl){
    __shared__ float t[32][33];
    int z = blockIdx.z, b = z / H_, h = z % H_;
    int s0 = blockIdx.x*32, d0 = blockIdx.y*32;
    int tx = threadIdx.x, ty = threadIdx.y;
    const float* src = X + (size_t)b*S_*E_ + h*D_;
    #pragma unroll
    for (int i=0;i<32;i+=8) t[ty+i][tx] = src[(size_t)(s0+ty+i)*E_ + d0+tx];
    __syncthreads();
    #pragma unroll
    for (int i=0;i<32;i+=8){
        size_t o = (size_t)z*D_*S_ + (size_t)(d0+ty+i)*S_ + s0+tx;
        store_split(Th, Tl, o, t[tx][ty+i]);
    }
}

__global__ void transMem(const float* __restrict__ M, bf16* __restrict__ Th, bf16* __restrict__ Tl){
    __shared__ float t[32][33];
    int h = blockIdx.z;
    int d0 = blockIdx.x*32, e0 = blockIdx.y*32;
    int tx = threadIdx.x, ty = threadIdx.y;
    #pragma unroll
    for (int i=0;i<32;i+=8) t[ty+i][tx] = M[(size_t)h*D_*D_ + (size_t)(d0+ty+i)*D_ + e0+tx];
    __syncthreads();
    #pragma unroll
    for (int i=0;i<32;i+=8){
        size_t o = (size_t)h*D_*D_ + (size_t)(e0+ty+i)*D_ + d0+tx;
        store_split(Th, Tl, o, t[tx][ty+i]);
    }
}

__global__ void rowdot_split(const bf16* __restrict__ Hh, const bf16* __restrict__ Hl,
                             const float* __restrict__ zvec, float* __restrict__ out){
    int w = threadIdx.x >> 5, lane = threadIdx.x & 31;
    int r = blockIdx.x*8 + w;
    int z = r / S_, s = r % S_;
    int b = z / H_, h = z % H_;
    size_t base = (size_t)(b*S_+s)*E_ + h*D_;
    const float* zp = zvec + h*D_;
    float acc = 0.f;
    #pragma unroll
    for (int d=lane; d<D_; d+=32)
        acc += (__bfloat162float(Hh[base+d]) + __bfloat162float(Hl[base+d])) * zp[d];
    #pragma unroll
    for (int o=16;o;o>>=1) acc += __shfl_xor_sync(0xffffffffu, acc, o);
    if (lane==0) out[r] = acc;
}

__global__ void znew_part(const float* __restrict__ SK, float* __restrict__ part){
    int z = blockIdx.x, c = blockIdx.y;
    int b = z / H_, h = z % H_;
    int d = threadIdx.x;
    const float* p = SK + (size_t)b*S_*E_ + h*D_ + d + (size_t)(c*256)*E_;
    float acc = 0.f;
    #pragma unroll 8
    for (int s=0; s<256; s++) acc += p[(size_t)s*E_];
    part[(z*8+c)*D_ + d] = acc;
}
__global__ void znew_fin(const float* __restrict__ part, const float* __restrict__ zvec,
                         float* __restrict__ out){
    int z = blockIdx.x, d = threadIdx.x;
    float a = zvec[(z%H_)*D_ + d];
    #pragma unroll
    for (int c=0;c<8;c++) a += part[(z*8+c)*D_ + d];
    out[z*D_ + d] = a;
}

// ================= launch =================
extern "C" void kernel_launch(void* const* d_in, const int* in_sizes, int n_in,
                              void* d_out, int out_size)
{
    const float* hs    = (const float*)d_in[0];
    const float* Wq    = (const float*)d_in[1];
    const float* Wk    = (const float*)d_in[2];
    const float* Wv    = (const float*)d_in[3];
    const float* Wo    = (const float*)d_in[4];
    const float* bo    = (const float*)d_in[5];
    const float* betas = (const float*)d_in[6];
    const float* memp  = (const float*)d_in[7];
    const float* zv    = (const float*)d_in[8];
    float* out = (float*)d_out;

    cudaFuncSetAttribute(tc_gemm, cudaFuncAttributeMaxDynamicSharedMemorySize, G5_SMEM);
    cudaFuncSetAttribute(fa_kernel, cudaFuncAttributeMaxDynamicSharedMemorySize, FA_SMEM);

#define GS(var, sym) cudaGetSymbolAddress((void**)&var, sym)
    bf16 *HSh,*HSl,*WqTh,*WqTl,*WkTh,*WkTl,*WvTh,*WvTl,*WoTh,*WoTl,*memTh,*memTl;
    bf16 *Qh,*Ql,*Kh,*Kl,*SQh,*SQl,*SKh,*SKl,*ABh,*ABl,*VTh,*VTl,*UTh,*UTl,*SKTh,*SKTl;
    float *Vf,*Uf,*SKf,*AO,*Zq,*Zk,*Zp;
    GS(HSh,g_HSh); GS(HSl,g_HSl);
    GS(WqTh,g_WqTh); GS(WqTl,g_WqTl); GS(WkTh,g_WkTh); GS(WkTl,g_WkTl);
    GS(WvTh,g_WvTh); GS(WvTl,g_WvTl); GS(WoTh,g_WoTh); GS(WoTl,g_WoTl);
    GS(memTh,g_memTh); GS(memTl,g_memTl);
    GS(Qh,g_Qh); GS(Ql,g_Ql); GS(Kh,g_Kh); GS(Kl,g_Kl);
    GS(SQh,g_SQh); GS(SQl,g_SQl); GS(SKh,g_SKh); GS(SKl,g_SKl);
    GS(ABh,g_ABh); GS(ABl,g_ABl);
    GS(VTh,g_VTh); GS(VTl,g_VTl); GS(UTh,g_UTh); GS(UTl,g_UTl);
    GS(SKTh,g_SKTh); GS(SKTl,g_SKTl);
    GS(Vf,g_Vf); GS(Uf,g_Uf); GS(SKf,g_SKf); GS(AO,g_AO);
    GS(Zq,g_Zq); GS(Zk,g_Zk); GS(Zp,g_Zpart);

    const long OUT_MEM = (long)B_*S_*E_;
    const long OUT_Z   = OUT_MEM + (long)B_*H_*D_*D_;
    dim3 t256(256), t512(512), t328(32,8);

    // input conversions
    split_f32<<<MSZ/1024, t256>>>(hs, HSh, HSl, MSZ/4);
    transW<<<dim3(32,32), t328>>>(Wq, WqTh, WqTl);
    transW<<<dim3(32,32), t328>>>(Wk, WkTh, WkTl);
    transW<<<dim3(32,32), t328>>>(Wv, WvTh, WvTl);
    transW<<<dim3(32,32), t328>>>(Wo, WoTh, WoTl);
    transMem<<<dim3(8,8,H_), t328>>>(memp, memTh, memTl);

    // projections
    tc_gemm<<<dim3(4,64,1), t512, G5_SMEM>>>(HSh,HSl,WqTh,WqTl, E_,E_,E_,E_,
        0,0,0,0,0,0, EP_SIGQK, 0, Qh,Ql, SQh,SQl, 0,0,0,0);
    tc_gemm<<<dim3(4,64,1), t512, G5_SMEM>>>(HSh,HSl,WkTh,WkTl, E_,E_,E_,E_,
        0,0,0,0,0,0, EP_SIGQK, SKf, Kh,Kl, SKh,SKl, 0,0,0,0);
    tc_gemm<<<dim3(4,64,1), t512, G5_SMEM>>>(HSh,HSl,WvTh,WvTl, E_,E_,E_,E_,
        0,0,0,0,0,0, EP_F32, Vf, 0,0,0,0, 0,0,0,0);

    transBH<<<dim3(64,8,BH_), t328>>>(Vf, VTh, VTl);

    // fused attention (512 threads)
    fa_kernel<<<256, t512, FA_SMEM>>>(Qh,Ql,Kh,Kl,VTh,VTl, AO);

    // sigma . z
    rowdot_split<<<BH_*S_/8, t256>>>(SQh, SQl, zv, Zq);
    rowdot_split<<<BH_*S_/8, t256>>>(SKh, SKl, zv, Zk);

    // A_mem + gate mix -> split AB
    tc_gemm<<<dim3(1,16,BH_), t512, G5_SMEM>>>(SQh,SQl,memTh,memTl, D_, E_,D_,E_,
        (long)S_*E_, D_, 0, (long)D_*D_, (long)S_*E_, (long)D_,
        EP_AMEM, 0, ABh,ABl, 0,0, Zq, AO, betas, 0);

    // U = V - delta
    tc_gemm<<<dim3(1,16,BH_), t512, G5_SMEM>>>(SKh,SKl,memTh,memTl, D_, E_,D_,E_,
        (long)S_*E_, D_, 0, (long)D_*D_, (long)S_*E_, (long)D_,
        EP_DELTA, Uf, 0,0,0,0, Zk, Vf, 0, 0);

    transBH<<<dim3(64,8,BH_), t328>>>(Uf, UTh, UTl);
    transBH<<<dim3(64,8,BH_), t328>>>(SKf, SKTh, SKTl);

    // mem_new = mem + SK^T @ U
    tc_gemm<<<dim3(1,2,BH_), t512, G5_SMEM>>>(SKTh,SKTl,UTh,UTl, S_, S_,S_,D_,
        (long)H_*D_*S_, (long)D_*S_, (long)H_*D_*S_, (long)D_*S_, (long)H_*D_*D_, (long)D_*D_,
        EP_MEMUPD, out+OUT_MEM, 0,0,0,0, 0, memp, 0, 0);

    // z_new
    znew_part<<<dim3(BH_,8), D_>>>(SKf, Zp);
    znew_fin<<<BH_, D_>>>(Zp, zv, out+OUT_Z);

    // out projection + bias
    tc_gemm<<<dim3(4,64,1), t512, G5_SMEM>>>(ABh,ABl,WoTh,WoTl, E_,E_,E_,E_,
        0,0,0,0,0,0, EP_BIAS, out, 0,0,0,0, 0,0,0, bo);
}

// round 10
// speedup vs baseline: 1.0277x; 1.0277x over previous
#include <cuda_runtime.h>
#include <cuda_bf16.h>
#include <cstdint>
#include <math.h>

#define B_ 4
#define S_ 2048
#define E_ 1024
#define H_ 4
#define D_ 256
#define BH_ 16
#define MSZ (B_*S_*E_)

typedef __nv_bfloat16 bf16;

// ================= device scratch =================
__device__ bf16 g_HSh[MSZ], g_HSl[MSZ];
__device__ bf16 g_WqTh[E_*E_], g_WqTl[E_*E_];
__device__ bf16 g_WkTh[E_*E_], g_WkTl[E_*E_];
__device__ bf16 g_WvTh[E_*E_], g_WvTl[E_*E_];
__device__ bf16 g_WoTh[E_*E_], g_WoTl[E_*E_];
__device__ bf16 g_memTh[H_*D_*D_], g_memTl[H_*D_*D_];
__device__ bf16 g_Qh[MSZ], g_Ql[MSZ], g_Kh[MSZ], g_Kl[MSZ];
__device__ bf16 g_SQh[MSZ], g_SQl[MSZ], g_SKh[MSZ], g_SKl[MSZ];
__device__ bf16 g_ABh[MSZ], g_ABl[MSZ];
__device__ bf16 g_VTh[MSZ], g_VTl[MSZ];
__device__ bf16 g_UTh[MSZ], g_UTl[MSZ];
__device__ bf16 g_SKTh[MSZ], g_SKTl[MSZ];
__device__ float g_Vf[MSZ], g_AO[MSZ];
__device__ float g_Zq[BH_*S_], g_Zk[BH_*S_];

// ================= helpers =================
__device__ __forceinline__ uint32_t smem_u32(const void* p){
    uint32_t a;
    asm("{ .reg .u64 t; cvta.to.shared.u64 t, %1; cvt.u32.u64 %0, t; }" : "=r"(a) : "l"(p));
    return a;
}
#define SWZ(o) ((o) ^ (((o) >> 3) & 0x70))

#define CP_ASYNC(daddr, gptr) \
    asm volatile("cp.async.cg.shared.global [%0], [%1], 16;" :: "r"(daddr), "l"(gptr) : "memory")
#define CP_COMMIT() asm volatile("cp.async.commit_group;" ::: "memory")
#define CP_WAIT(n)  asm volatile("cp.async.wait_group %0;" :: "n"(n) : "memory")

__device__ __forceinline__ void ldm_x4(uint32_t& r0, uint32_t& r1, uint32_t& r2, uint32_t& r3, uint32_t a){
    asm volatile("ldmatrix.sync.aligned.m8n8.x4.shared.b16 {%0,%1,%2,%3}, [%4];"
        : "=r"(r0), "=r"(r1), "=r"(r2), "=r"(r3) : "r"(a));
}
__device__ __forceinline__ void mma16816(float* c, const uint32_t* a, const uint32_t* b){
    asm volatile("mma.sync.aligned.m16n8k16.row.col.f32.bf16.bf16.f32 "
        "{%0,%1,%2,%3}, {%4,%5,%6,%7}, {%8,%9}, {%0,%1,%2,%3};"
        : "+f"(c[0]), "+f"(c[1]), "+f"(c[2]), "+f"(c[3])
        : "r"(a[0]), "r"(a[1]), "r"(a[2]), "r"(a[3]), "r"(b[0]), "r"(b[1]));
}

__device__ __forceinline__ void store_split(bf16* ph, bf16* pl, size_t i, float v){
    bf16 h = __float2bfloat16(v);
    ph[i] = h;
    pl[i] = __float2bfloat16(v - __bfloat162float(h));
}

enum { EP_F32=0, EP_SIGQK=1, EP_BIAS=2, EP_AMEM=3, EP_DELTA=4, EP_MEMUPD=5 };

// ================= 512-thread HMMA GEMM =================
// Block tile 128x256, K-chunk 64, 2-stage cp.async. 16 warps = 2(m) x 8(n).
// tmode: 0 none; 1 projection-style transposed out (b=m>>11, h=n0>>8);
//        2 batched-style transposed out (z=blockIdx.z, s=m, d=c).
#define G5_STG 98304
#define G5_SMEM (2*G5_STG)

__global__ void __launch_bounds__(512,1) tc_gemm(
    const bf16* __restrict__ Ahg, const bf16* __restrict__ Alg,
    const bf16* __restrict__ Bhg, const bf16* __restrict__ Blg,
    int K, int lda, int ldb, int ldc,
    long sAb, long sAh, long sBb, long sBh, long sCb, long sCh,
    int mode,
    float* __restrict__ C, bf16* __restrict__ O1h, bf16* __restrict__ O1l,
    bf16* __restrict__ O2h, bf16* __restrict__ O2l,
    const float* __restrict__ rowdiv, const float* __restrict__ mix,
    const float* __restrict__ betas, const float* __restrict__ bias,
    bf16* __restrict__ Th, bf16* __restrict__ Tl, int tmode)
{
    extern __shared__ char smemc[];
    int z = blockIdx.z, bb = z / H_, hh = z % H_;
    int m0 = blockIdx.y*128, n0 = blockIdx.x*256;

    const bf16* Ah = Ahg + (size_t)bb*sAb + (size_t)hh*sAh;
    const bf16* Al = Alg + (size_t)bb*sAb + (size_t)hh*sAh;
    const bf16* Bh = Bhg + (size_t)bb*sBb + (size_t)hh*sBh;
    const bf16* Bl = Blg + (size_t)bb*sBb + (size_t)hh*sBh;
    size_t coff = (size_t)bb*sCb + (size_t)hh*sCh;

    int tid = threadIdx.x, wid = tid >> 5, lid = tid & 31;
    uint32_t sb = smem_u32(smemc);
    int wm = wid & 1, wn = wid >> 1;
    int mbase = wm*64, nbase = wn*32;

    float acc[4][4][4];
    #pragma unroll
    for (int i=0;i<4;i++)
        #pragma unroll
        for (int j=0;j<4;j++)
            #pragma unroll
            for (int r=0;r<4;r++) acc[i][j][r]=0.f;

    int nch = K >> 6;
    int row_l = tid >> 3, v_l = tid & 7;

    auto issue = [&](int ci, int s){
        int stg = s*G5_STG, kc0 = ci << 6;
        #pragma unroll
        for (int i=0;i<2;i++){
            int row = row_l + 64*i;
            uint32_t o = SWZ(row*128 + v_l*16);
            CP_ASYNC(sb+stg+o,       Ah + (size_t)(m0+row)*lda + kc0 + v_l*8);
            CP_ASYNC(sb+stg+16384+o, Al + (size_t)(m0+row)*lda + kc0 + v_l*8);
        }
        #pragma unroll
        for (int i=0;i<4;i++){
            int row = row_l + 64*i;
            uint32_t o = SWZ(row*128 + v_l*16);
            CP_ASYNC(sb+stg+32768+o, Bh + (size_t)(n0+row)*ldb + kc0 + v_l*8);
            CP_ASYNC(sb+stg+65536+o, Bl + (size_t)(n0+row)*ldb + kc0 + v_l*8);
        }
        CP_COMMIT();
    };

    issue(0, 0);
    if (nch > 1) issue(1, 1);

    for (int ci=0; ci<nch; ci++){
        if (ci+1 < nch) { CP_WAIT(1); } else { CP_WAIT(0); }
        __syncthreads();
        int stg = (ci&1)*G5_STG;

        #pragma unroll
        for (int ks=0; ks<4; ks++){
            int colb = ks*32 + ((lid>>4)&1)*16;
            uint32_t ah[4][4], al[4][4];
            #pragma unroll
            for (int mt=0; mt<4; mt++){
                int row = mbase + mt*16 + (lid & 15);
                uint32_t off = SWZ(row*128 + colb);
                ldm_x4(ah[mt][0],ah[mt][1],ah[mt][2],ah[mt][3], sb+stg+off);
                ldm_x4(al[mt][0],al[mt][1],al[mt][2],al[mt][3], sb+stg+16384+off);
            }
            uint32_t bh[4][2], bl[4][2];
            #pragma unroll
            for (int g=0; g<2; g++){
                int row = nbase + g*16 + (lid & 7) + ((lid>>4)&1)*8;
                int cb2 = ks*32 + ((lid>>3)&1)*16;
                uint32_t off = SWZ(row*128 + cb2);
                uint32_t r0,r1,r2,r3;
                ldm_x4(r0,r1,r2,r3, sb+stg+32768+off);
                bh[2*g][0]=r0; bh[2*g][1]=r1; bh[2*g+1][0]=r2; bh[2*g+1][1]=r3;
                ldm_x4(r0,r1,r2,r3, sb+stg+65536+off);
                bl[2*g][0]=r0; bl[2*g][1]=r1; bl[2*g+1][0]=r2; bl[2*g+1][1]=r3;
            }
            #pragma unroll
            for (int mt=0; mt<4; mt++)
                #pragma unroll
                for (int nt=0; nt<4; nt++){
                    mma16816(acc[mt][nt], ah[mt], bh[nt]);
                    mma16816(acc[mt][nt], ah[mt], bl[nt]);
                    mma16816(acc[mt][nt], al[mt], bh[nt]);
                }
        }
        __syncthreads();
        if (ci+2 < nch) issue(ci+2, ci&1);
    }

    float* buf = (float*)smemc;              // 128 x 260
    int tg = lid >> 2, t4 = lid & 3;
    #pragma unroll
    for (int mt=0; mt<4; mt++)
        #pragma unroll
        for (int nt=0; nt<4; nt++)
            #pragma unroll
            for (int r=0; r<4; r++){
                int m = mbase + mt*16 + tg + (r>=2 ? 8 : 0);
                int c = nbase + nt*8 + t4*2 + (r&1);
                buf[m*260 + c] = acc[mt][nt][r];
            }
    __syncthreads();

    float gate = 0.f;
    if (mode == EP_AMEM) gate = 1.f/(1.f + __expf(-betas[hh]));

    #pragma unroll 4
    for (int e=0; e<64; e++){
        int flat = e*512 + tid;
        int row = flat >> 8, col = flat & 255;
        float v = buf[row*260 + col];
        int m = m0 + row, c = n0 + col;
        size_t idx = coff + (size_t)m*ldc + c;
        if (mode == EP_F32) {
            if (C) C[idx] = v;
        } else if (mode == EP_SIGQK) {
            store_split(O1h, O1l, idx, v);
            float sg = v > 0.f ? v + 1.f : __expf(v);
            store_split(O2h, O2l, idx, sg);
            buf[row*260 + col] = sg;          // final value for transposed pass
        } else if (mode == EP_BIAS) {
            C[idx] = v + bias[c];
        } else if (mode == EP_AMEM) {
            float rinv = 1.f/(rowdiv[(size_t)z*S_ + m] + 1e-6f);
            float val = gate*(v*rinv) + (1.f-gate)*mix[idx];
            store_split(O1h, O1l, idx, val);
        } else if (mode == EP_DELTA) {
            float rinv = 1.f/(rowdiv[(size_t)z*S_ + m] + 1e-6f);
            float u = mix[idx] - v*rinv;
            if (C) C[idx] = u;
            buf[row*260 + col] = u;           // final value for transposed pass
        } else {
            float mv = mix[(size_t)hh*D_*D_ + (size_t)m*D_ + c];
            C[idx] = mv + v;
        }
    }

    // ---- optional transposed split output: T[(bh)*D + d][s] ----
    if (tmode){
        __syncthreads();
        size_t tbase; int sofs;
        if (tmode == 1){
            int b = m0 >> 11;                  // batch (2048 rows each)
            int s0 = m0 & 2047;
            int h = n0 >> 8;                   // head (256 cols each)
            tbase = ((size_t)(b*H_ + h))*D_*S_;
            sofs = s0;
        } else {
            tbase = (size_t)z*D_*S_;
            sofs = m0;
        }
        #pragma unroll 4
        for (int e=0; e<32; e++){
            int flat = e*512 + tid;            // 16384 (d, s-pair) items
            int d = flat >> 6;
            int s = (flat & 63)*2;
            float v0 = buf[(s+0)*260 + d];
            float v1 = buf[(s+1)*260 + d];
            bf16 h0 = __float2bfloat16(v0);
            bf16 h1 = __float2bfloat16(v1);
            bf16 l0 = __float2bfloat16(v0 - __bfloat162float(h0));
            bf16 l1 = __float2bfloat16(v1 - __bfloat162float(h1));
            size_t o = tbase + (size_t)d*S_ + sofs + s;
            *(__nv_bfloat162*)(Th + o) = __nv_bfloat162(h0, h1);
            *(__nv_bfloat162*)(Tl + o) = __nv_bfloat162(l0, l1);
        }
    }
}

// ================= fused flash attention (256 threads — validated best) =================
#define STG_BYTES 65536
#define FA_P     131072
#define FA_STAT  196608
#define FA_SMEM  (196608 + 3072)

__global__ void __launch_bounds__(256,1) fa_kernel(
    const bf16* __restrict__ Qhg, const bf16* __restrict__ Qlg,
    const bf16* __restrict__ Khg, const bf16* __restrict__ Klg,
    const bf16* __restrict__ VThg, const bf16* __restrict__ VTlg,
    float* __restrict__ AO)
{
    extern __shared__ char smc[];
    uint32_t sb = smem_u32(smc);
    int bid = blockIdx.x;
    int z  = (bid>>1)&15;
    int mi = (bid&1) ? (bid>>5) : 15-(bid>>5);
    int bb = z / H_, hh = z % H_;
    int m0 = mi*128;

    int tid = threadIdx.x, wid = tid>>5, lid = tid&31;
    int wm = wid&1, wn = wid>>1;
    int tg = lid>>2, t4 = lid&3;

    const bf16* Qh_ = Qhg + (size_t)bb*S_*E_ + hh*D_;
    const bf16* Ql_ = Qlg + (size_t)bb*S_*E_ + hh*D_;
    const bf16* Kh_ = Khg + (size_t)bb*S_*E_ + hh*D_;
    const bf16* Kl_ = Klg + (size_t)bb*S_*E_ + hh*D_;
    const bf16* VTh_ = VThg + (size_t)z*D_*S_;
    const bf16* VTl_ = VTlg + (size_t)z*D_*S_;

    float* m_s = (float*)(smc + FA_STAT);
    float* l_s = (float*)(smc + FA_STAT + 512);
    float* red = (float*)(smc + FA_STAT + 1024);

    if (tid < 128){ m_s[tid] = -1e30f; l_s[tid] = 0.f; }

    float acc_o[4][8][4];
    #pragma unroll
    for (int a=0;a<4;a++)
        #pragma unroll
        for (int b=0;b<8;b++)
            #pragma unroll
            for (int r=0;r<4;r++) acc_o[a][b][r]=0.f;
    __syncthreads();

    int row_l = tid>>3, v_l = tid&7;

    for (int j=0; j<=mi; j++){
        int jb = j*128;
        float acc_s[4][4][4];
        #pragma unroll
        for (int a=0;a<4;a++)
            #pragma unroll
            for (int b=0;b<4;b++)
                #pragma unroll
                for (int r=0;r<4;r++) acc_s[a][b][r]=0.f;

        auto issueS = [&](int c, int s){
            int stg = s*STG_BYTES, kc0 = c*64;
            #pragma unroll
            for (int i=0;i<4;i++){
                int row = row_l + 32*i;
                uint32_t o = SWZ(row*128 + v_l*16);
                CP_ASYNC(sb+stg+o,       Qh_ + (size_t)(m0+row)*E_ + kc0 + v_l*8);
                CP_ASYNC(sb+stg+16384+o, Ql_ + (size_t)(m0+row)*E_ + kc0 + v_l*8);
                CP_ASYNC(sb+stg+32768+o, Kh_ + (size_t)(jb+row)*E_ + kc0 + v_l*8);
                CP_ASYNC(sb+stg+49152+o, Kl_ + (size_t)(jb+row)*E_ + kc0 + v_l*8);
            }
            CP_COMMIT();
        };
        auto issueV = [&](int kc, int s){
            int stg = s*STG_BYTES;
            #pragma unroll
            for (int i=0;i<8;i++){
                int row = row_l + 32*i;
                uint32_t o = SWZ(row*128 + v_l*16);
                CP_ASYNC(sb+stg+o,       VTh_ + (size_t)row*S_ + jb + kc*64 + v_l*8);
                CP_ASYNC(sb+stg+32768+o, VTl_ + (size_t)row*S_ + jb + kc*64 + v_l*8);
            }
            CP_COMMIT();
        };

        issueS(0,0); issueS(1,1);
        for (int c=0;c<4;c++){
            if (c<3) { CP_WAIT(1); } else { CP_WAIT(0); }
            __syncthreads();
            int stg = (c&1)*STG_BYTES;
            #pragma unroll
            for (int ks=0; ks<4; ks++){
                uint32_t bh[4][2], bl[4][2];
                #pragma unroll
                for (int g=0; g<2; g++){
                    int row = wn*32 + g*16 + (lid&7) + ((lid>>4)&1)*8;
                    int cb2 = ks*32 + ((lid>>3)&1)*16;
                    uint32_t off = SWZ(row*128 + cb2);
                    uint32_t r0,r1,r2,r3;
                    ldm_x4(r0,r1,r2,r3, sb+stg+32768+off);
                    bh[2*g][0]=r0; bh[2*g][1]=r1; bh[2*g+1][0]=r2; bh[2*g+1][1]=r3;
                    ldm_x4(r0,r1,r2,r3, sb+stg+49152+off);
                    bl[2*g][0]=r0; bl[2*g][1]=r1; bl[2*g+1][0]=r2; bl[2*g+1][1]=r3;
                }
                #pragma unroll
                for (int mt=0; mt<4; mt++){
                    int row = wm*64 + mt*16 + (lid&15);
                    uint32_t colb = ks*32 + ((lid>>4)&1)*16;
                    uint32_t off = SWZ(row*128 + colb);
                    uint32_t ah[4], al[4];
                    ldm_x4(ah[0],ah[1],ah[2],ah[3], sb+stg+off);
                    ldm_x4(al[0],al[1],al[2],al[3], sb+stg+16384+off);
                    #pragma unroll
                    for (int nt=0;nt<4;nt++){
                        mma16816(acc_s[mt][nt], ah, bh[nt]);
                        mma16816(acc_s[mt][nt], ah, bl[nt]);
                        mma16816(acc_s[mt][nt], al, bh[nt]);
                    }
                }
            }
            __syncthreads();
            if (c==0) issueS(2,0);
            else if (c==1) issueS(3,1);
        }

        issueV(0,0); issueV(1,1);

        if (j == mi){
            #pragma unroll
            for (int mt=0; mt<4; mt++)
                #pragma unroll
                for (int nt=0; nt<4; nt++)
                    #pragma unroll
                    for (int r=0;r<4;r++){
                        int srow = wm*64 + mt*16 + tg + ((r>>1)&1)*8;
                        int scol = wn*32 + nt*8 + t4*2 + (r&1);
                        if (scol > srow) acc_s[mt][nt][r] = -1e30f;
                    }
        }
        float rmax[4][2];
        #pragma unroll
        for (int mt=0; mt<4; mt++)
            #pragma unroll
            for (int hf=0; hf<2; hf++){
                float m = -1e30f;
                #pragma unroll
                for (int nt=0; nt<4; nt++){
                    m = fmaxf(m, acc_s[mt][nt][hf*2+0]);
                    m = fmaxf(m, acc_s[mt][nt][hf*2+1]);
                }
                m = fmaxf(m, __shfl_xor_sync(0xffffffffu, m, 1));
                m = fmaxf(m, __shfl_xor_sync(0xffffffffu, m, 2));
                rmax[mt][hf] = m;
            }
        if (t4 == 0){
            #pragma unroll
            for (int mt=0; mt<4; mt++)
                #pragma unroll
                for (int hf=0; hf<2; hf++)
                    red[wn*128 + wm*64 + mt*16 + tg + hf*8] = rmax[mt][hf];
        }
        __syncthreads();

        float mnew[4][2], alpha[4][2], rsum[4][2];
        #pragma unroll
        for (int mt=0; mt<4; mt++)
            #pragma unroll
            for (int hf=0; hf<2; hf++){
                int row = wm*64 + mt*16 + tg + hf*8;
                float rm = fmaxf(fmaxf(red[row], red[128+row]), fmaxf(red[256+row], red[384+row]));
                float mo = m_s[row];
                float mn = fmaxf(mo, rm);
                mnew[mt][hf] = mn;
                alpha[mt][hf] = __expf(mo - mn);
                rsum[mt][hf] = 0.f;
            }
        #pragma unroll
        for (int mt=0; mt<4; mt++)
            #pragma unroll
            for (int nt=0; nt<4; nt++)
                #pragma unroll
                for (int r=0;r<4;r++){
                    int hf = r>>1;
                    float p = __expf(acc_s[mt][nt][r] - mnew[mt][hf]);
                    acc_s[mt][nt][r] = p;
                    rsum[mt][hf] += p;
                }
        #pragma unroll
        for (int mt=0; mt<4; mt++)
            #pragma unroll
            for (int hf=0; hf<2; hf++){
                rsum[mt][hf] += __shfl_xor_sync(0xffffffffu, rsum[mt][hf], 1);
                rsum[mt][hf] += __shfl_xor_sync(0xffffffffu, rsum[mt][hf], 2);
            }
        __syncthreads();
        if (t4 == 0){
            #pragma unroll
            for (int mt=0; mt<4; mt++)
                #pragma unroll
                for (int hf=0; hf<2; hf++)
                    red[wn*128 + wm*64 + mt*16 + tg + hf*8] = rsum[mt][hf];
        }
        #pragma unroll
        for (int mt=0; mt<4; mt++)
            #pragma unroll
            for (int nt=0; nt<4; nt++)
                #pragma unroll
                for (int rp=0; rp<2; rp++){
                    int row = wm*64 + mt*16 + tg + rp*8;
                    int col = wn*32 + nt*8 + t4*2;
                    float p0 = acc_s[mt][nt][rp*2+0];
                    float p1 = acc_s[mt][nt][rp*2+1];
                    bf16 h0 = __float2bfloat16(p0);
                    bf16 h1 = __float2bfloat16(p1);
                    bf16 l0 = __float2bfloat16(p0 - __bfloat162float(h0));
                    bf16 l1 = __float2bfloat16(p1 - __bfloat162float(h1));
                    uint32_t o = (uint32_t)(col>>6)*16384u + SWZ((uint32_t)row*128 + (col&63)*2);
                    *(__nv_bfloat162*)(smc + FA_P + o)         = __nv_bfloat162(h0, h1);
                    *(__nv_bfloat162*)(smc + FA_P + 32768 + o) = __nv_bfloat162(l0, l1);
                }
        #pragma unroll
        for (int mt=0; mt<4; mt++)
            #pragma unroll
            for (int nt=0; nt<8; nt++)
                #pragma unroll
                for (int r=0;r<4;r++)
                    acc_o[mt][nt][r] *= alpha[mt][r>>1];
        __syncthreads();
        if (wn == 0 && t4 == 0){
            #pragma unroll
            for (int mt=0; mt<4; mt++)
                #pragma unroll
                for (int hf=0; hf<2; hf++){
                    int row = wm*64 + mt*16 + tg + hf*8;
                    float rs = red[row] + red[128+row] + red[256+row] + red[384+row];
                    l_s[row] = l_s[row]*alpha[mt][hf] + rs;
                    m_s[row] = mnew[mt][hf];
                }
        }

        for (int kc=0; kc<2; kc++){
            if (kc==0) { CP_WAIT(1); } else { CP_WAIT(0); }
            __syncthreads();
            int stg = kc*STG_BYTES;
            uint32_t pb = FA_P + kc*16384;
            #pragma unroll
            for (int ks=0; ks<4; ks++){
                uint32_t bh[8][2], bl[8][2];
                #pragma unroll
                for (int g=0; g<4; g++){
                    int row = wn*64 + g*16 + (lid&7) + ((lid>>4)&1)*8;
                    int cb2 = ks*32 + ((lid>>3)&1)*16;
                    uint32_t off = SWZ(row*128 + cb2);
                    uint32_t r0,r1,r2,r3;
                    ldm_x4(r0,r1,r2,r3, sb+stg+off);
                    bh[2*g][0]=r0; bh[2*g][1]=r1; bh[2*g+1][0]=r2; bh[2*g+1][1]=r3;
                    ldm_x4(r0,r1,r2,r3, sb+stg+32768+off);
                    bl[2*g][0]=r0; bl[2*g][1]=r1; bl[2*g+1][0]=r2; bl[2*g+1][1]=r3;
                }
                #pragma unroll
                for (int mt=0; mt<4; mt++){
                    int row = wm*64 + mt*16 + (lid&15);
                    uint32_t colb = ks*32 + ((lid>>4)&1)*16;
                    uint32_t off = SWZ(row*128 + colb);
                    uint32_t ah[4], al[4];
                    ldm_x4(ah[0],ah[1],ah[2],ah[3], sb+pb+off);
                    ldm_x4(al[0],al[1],al[2],al[3], sb+pb+32768+off);
                    #pragma unroll
                    for (int nt=0;nt<8;nt++){
                        mma16816(acc_o[mt][nt], ah, bh[nt]);
                        mma16816(acc_o[mt][nt], ah, bl[nt]);
                        mma16816(acc_o[mt][nt], al, bh[nt]);
                    }
                }
            }
            __syncthreads();
        }
    }

    __syncthreads();
    float* AOp = AO + (size_t)bb*S_*E_ + hh*D_;
    #pragma unroll
    for (int mt=0; mt<4; mt++)
        #pragma unroll
        for (int hf=0; hf<2; hf++){
            int row = wm*64 + mt*16 + tg + hf*8;
            float linv = 1.f/l_s[row];
            #pragma unroll
            for (int nt=0; nt<8; nt++){
                int col = wn*64 + nt*8 + t4*2;
                float2 v;
                v.x = acc_o[mt][nt][hf*2+0]*linv;
                v.y = acc_o[mt][nt][hf*2+1]*linv;
                *(float2*)(AOp + (size_t)(m0+row)*E_ + col) = v;
            }
        }
}

// ================= small kernels =================
__global__ void split_f32(const float* __restrict__ src, bf16* __restrict__ h, bf16* __restrict__ l, int n4){
    int i = blockIdx.x*blockDim.x + threadIdx.x;
    if (i >= n4) return;
    float4 v = ((const float4*)src)[i];
    size_t o = (size_t)i*4;
    store_split(h, l, o+0, v.x); store_split(h, l, o+1, v.y);
    store_split(h, l, o+2, v.z); store_split(h, l, o+3, v.w);
}

__global__ void transW(const float* __restrict__ W, bf16* __restrict__ Th, bf16* __restrict__ Tl){
    __shared__ float t[32][33];
    int k0 = blockIdx.x*32, n0 = blockIdx.y*32;
    int tx = threadIdx.x, ty = threadIdx.y;
    #pragma unroll
    for (int i=0;i<32;i+=8) t[ty+i][tx] = W[(size_t)(k0+ty+i)*E_ + n0+tx];
    __syncthreads();
    #pragma unroll
    for (int i=0;i<32;i+=8){
        size_t o = (size_t)(n0+ty+i)*E_ + k0+tx;
        store_split(Th, Tl, o, t[tx][ty+i]);
    }
}

__global__ void transMem(const float* __restrict__ M, bf16* __restrict__ Th, bf16* __restrict__ Tl){
    __shared__ float t[32][33];
    int h = blockIdx.z;
    int d0 = blockIdx.x*32, e0 = blockIdx.y*32;
    int tx = threadIdx.x, ty = threadIdx.y;
    #pragma unroll
    for (int i=0;i<32;i+=8) t[ty+i][tx] = M[(size_t)h*D_*D_ + (size_t)(d0+ty+i)*D_ + e0+tx];
    __syncthreads();
    #pragma unroll
    for (int i=0;i<32;i+=8){
        size_t o = (size_t)h*D_*D_ + (size_t)(e0+ty+i)*D_ + d0+tx;
        store_split(Th, Tl, o, t[tx][ty+i]);
    }
}

__global__ void rowdot_split(const bf16* __restrict__ Hh, const bf16* __restrict__ Hl,
                             const float* __restrict__ zvec, float* __restrict__ out){
    int w = threadIdx.x >> 5, lane = threadIdx.x & 31;
    int r = blockIdx.x*8 + w;
    int z = r / S_, s = r % S_;
    int b = z / H_, h = z % H_;
    size_t base = (size_t)(b*S_+s)*E_ + h*D_;
    const float* zp = zvec + h*D_;
    float acc = 0.f;
    #pragma unroll
    for (int d=lane; d<D_; d+=32)
        acc += (__bfloat162float(Hh[base+d]) + __bfloat162float(Hl[base+d])) * zp[d];
    #pragma unroll
    for (int o=16;o;o>>=1) acc += __shfl_xor_sync(0xffffffffu, acc, o);
    if (lane==0) out[r] = acc;
}

// z_new from transposed sigma_k: out[z*D+d] = zvec[h*D+d] + sum_s SKT[(z*D+d)*S + s]
__global__ void znew_t(const bf16* __restrict__ SKTh, const bf16* __restrict__ SKTl,
                       const float* __restrict__ zvec, float* __restrict__ out){
    int w = threadIdx.x >> 5, lane = threadIdx.x & 31;
    int r = blockIdx.x*8 + w;          // [0, BH_*D_)
    int z = r / D_, d = r % D_;
    const bf16* ph = SKTh + (size_t)r*S_;
    const bf16* pl = SKTl + (size_t)r*S_;
    float acc = 0.f;
    #pragma unroll 4
    for (int s=lane; s<S_; s+=32)
        acc += __bfloat162float(ph[s]) + __bfloat162float(pl[s]);
    #pragma unroll
    for (int o=16;o;o>>=1) acc += __shfl_xor_sync(0xffffffffu, acc, o);
    if (lane==0) out[r] = zvec[(z%H_)*D_ + d] + acc;
}

// ================= launch =================
extern "C" void kernel_launch(void* const* d_in, const int* in_sizes, int n_in,
                              void* d_out, int out_size)
{
    const float* hs    = (const float*)d_in[0];
    const float* Wq    = (const float*)d_in[1];
    const float* Wk    = (const float*)d_in[2];
    const float* Wv    = (const float*)d_in[3];
    const float* Wo    = (const float*)d_in[4];
    const float* bo    = (const float*)d_in[5];
    const float* betas = (const float*)d_in[6];
    const float* memp  = (const float*)d_in[7];
    const float* zv    = (const float*)d_in[8];
    float* out = (float*)d_out;

    cudaFuncSetAttribute(tc_gemm, cudaFuncAttributeMaxDynamicSharedMemorySize, G5_SMEM);
    cudaFuncSetAttribute(fa_kernel, cudaFuncAttributeMaxDynamicSharedMemorySize, FA_SMEM);

#define GS(var, sym) cudaGetSymbolAddress((void**)&var, sym)
    bf16 *HSh,*HSl,*WqTh,*WqTl,*WkTh,*WkTl,*WvTh,*WvTl,*WoTh,*WoTl,*memTh,*memTl;
    bf16 *Qh,*Ql,*Kh,*Kl,*SQh,*SQl,*SKh,*SKl,*ABh,*ABl,*VTh,*VTl,*UTh,*UTl,*SKTh,*SKTl;
    float *Vf,*AO,*Zq,*Zk;
    GS(HSh,g_HSh); GS(HSl,g_HSl);
    GS(WqTh,g_WqTh); GS(WqTl,g_WqTl); GS(WkTh,g_WkTh); GS(WkTl,g_WkTl);
    GS(WvTh,g_WvTh); GS(WvTl,g_WvTl); GS(WoTh,g_WoTh); GS(WoTl,g_WoTl);
    GS(memTh,g_memTh); GS(memTl,g_memTl);
    GS(Qh,g_Qh); GS(Ql,g_Ql); GS(Kh,g_Kh); GS(Kl,g_Kl);
    GS(SQh,g_SQh); GS(SQl,g_SQl); GS(SKh,g_SKh); GS(SKl,g_SKl);
    GS(ABh,g_ABh); GS(ABl,g_ABl);
    GS(VTh,g_VTh); GS(VTl,g_VTl); GS(UTh,g_UTh); GS(UTl,g_UTl);
    GS(SKTh,g_SKTh); GS(SKTl,g_SKTl);
    GS(Vf,g_Vf); GS(AO,g_AO);
    GS(Zq,g_Zq); GS(Zk,g_Zk);

    const long OUT_MEM = (long)B_*S_*E_;
    const long OUT_Z   = OUT_MEM + (long)B_*H_*D_*D_;
    dim3 t256(256), t512(512), t328(32,8);

    // input conversions
    split_f32<<<MSZ/1024, t256>>>(hs, HSh, HSl, MSZ/4);
    transW<<<dim3(32,32), t328>>>(Wq, WqTh, WqTl);
    transW<<<dim3(32,32), t328>>>(Wk, WkTh, WkTl);
    transW<<<dim3(32,32), t328>>>(Wv, WvTh, WvTl);
    transW<<<dim3(32,32), t328>>>(Wo, WoTh, WoTl);
    transMem<<<dim3(8,8,H_), t328>>>(memp, memTh, memTl);

    // projections (transposed outputs fused into epilogues)
    tc_gemm<<<dim3(4,64,1), t512, G5_SMEM>>>(HSh,HSl,WqTh,WqTl, E_,E_,E_,E_,
        0,0,0,0,0,0, EP_SIGQK, 0, Qh,Ql, SQh,SQl, 0,0,0,0, 0,0,0);
    tc_gemm<<<dim3(4,64,1), t512, G5_SMEM>>>(HSh,HSl,WkTh,WkTl, E_,E_,E_,E_,
        0,0,0,0,0,0, EP_SIGQK, 0, Kh,Kl, SKh,SKl, 0,0,0,0, SKTh,SKTl,1);
    tc_gemm<<<dim3(4,64,1), t512, G5_SMEM>>>(HSh,HSl,WvTh,WvTl, E_,E_,E_,E_,
        0,0,0,0,0,0, EP_F32, Vf, 0,0,0,0, 0,0,0,0, VTh,VTl,1);

    // fused attention (256 threads)
    fa_kernel<<<256, t256, FA_SMEM>>>(Qh,Ql,Kh,Kl,VTh,VTl, AO);

    // sigma . z
    rowdot_split<<<BH_*S_/8, t256>>>(SQh, SQl, zv, Zq);
    rowdot_split<<<BH_*S_/8, t256>>>(SKh, SKl, zv, Zk);

    // A_mem + gate mix -> split AB
    tc_gemm<<<dim3(1,16,BH_), t512, G5_SMEM>>>(SQh,SQl,memTh,memTl, D_, E_,D_,E_,
        (long)S_*E_, D_, 0, (long)D_*D_, (long)S_*E_, (long)D_,
        EP_AMEM, 0, ABh,ABl, 0,0, Zq, AO, betas, 0, 0,0,0);

    // U = V - delta (transposed UT written directly)
    tc_gemm<<<dim3(1,16,BH_), t512, G5_SMEM>>>(SKh,SKl,memTh,memTl, D_, E_,D_,E_,
        (long)S_*E_, D_, 0, (long)D_*D_, (long)S_*E_, (long)D_,
        EP_DELTA, 0, 0,0,0,0, Zk, Vf, 0, 0, UTh,UTl,2);

    // mem_new = mem + SK^T @ U
    tc_gemm<<<dim3(1,2,BH_), t512, G5_SMEM>>>(SKTh,SKTl,UTh,UTl, S_, S_,S_,D_,
        (long)H_*D_*S_, (long)D_*S_, (long)H_*D_*S_, (long)D_*S_, (long)H_*D_*D_, (long)D_*D_,
        EP_MEMUPD, out+OUT_MEM, 0,0,0,0, 0, memp, 0, 0, 0,0,0);

    // z_new from SKT
    znew_t<<<BH_*D_/8, t256>>>(SKTh, SKTl, zv, out+OUT_Z);

    // out projection + bias
    tc_gemm<<<dim3(4,64,1), t512, G5_SMEM>>>(ABh,ABl,WoTh,WoTl, E_,E_,E_,E_,
        0,0,0,0,0,0, EP_BIAS, out, 0,0,0,0, 0,0,0, bo, 0,0,0);
}

// round 11
// speedup vs baseline: 1.1775x; 1.1458x over previous
#include <cuda_runtime.h>
#include <cuda_bf16.h>
#include <cstdint>
#include <math.h>

#define B_ 4
#define S_ 2048
#define E_ 1024
#define H_ 4
#define D_ 256
#define BH_ 16
#define MSZ (B_*S_*E_)

typedef __nv_bfloat16 bf16;

// ================= device scratch =================
__device__ bf16 g_HSh[MSZ], g_HSl[MSZ];
__device__ bf16 g_WqTh[E_*E_], g_WqTl[E_*E_];
__device__ bf16 g_WkTh[E_*E_], g_WkTl[E_*E_];
__device__ bf16 g_WvTh[E_*E_], g_WvTl[E_*E_];
__device__ bf16 g_WoTh[E_*E_], g_WoTl[E_*E_];
__device__ bf16 g_memTh[H_*D_*D_], g_memTl[H_*D_*D_];
__device__ bf16 g_Qh[MSZ], g_Ql[MSZ], g_Kh[MSZ], g_Kl[MSZ];
__device__ bf16 g_SQh[MSZ], g_SQl[MSZ], g_SKh[MSZ], g_SKl[MSZ];
__device__ bf16 g_ABh[MSZ], g_ABl[MSZ];
__device__ bf16 g_VTh[MSZ], g_VTl[MSZ];
__device__ bf16 g_UTh[MSZ], g_UTl[MSZ];
__device__ bf16 g_SKTh[MSZ], g_SKTl[MSZ];
__device__ float g_Vf[MSZ], g_AO[MSZ];
__device__ float g_Zq[BH_*S_], g_Zk[BH_*S_];

// ================= helpers =================
__device__ __forceinline__ uint32_t smem_u32(const void* p){
    uint32_t a;
    asm("{ .reg .u64 t; cvta.to.shared.u64 t, %1; cvt.u32.u64 %0, t; }" : "=r"(a) : "l"(p));
    return a;
}
#define SWZ(o) ((o) ^ (((o) >> 3) & 0x70))

#define CP_ASYNC(daddr, gptr) \
    asm volatile("cp.async.cg.shared.global [%0], [%1], 16;" :: "r"(daddr), "l"(gptr) : "memory")
#define CP_COMMIT() asm volatile("cp.async.commit_group;" ::: "memory")
#define CP_WAIT(n)  asm volatile("cp.async.wait_group %0;" :: "n"(n) : "memory")

__device__ __forceinline__ void ldm_x4(uint32_t& r0, uint32_t& r1, uint32_t& r2, uint32_t& r3, uint32_t a){
    asm volatile("ldmatrix.sync.aligned.m8n8.x4.shared.b16 {%0,%1,%2,%3}, [%4];"
        : "=r"(r0), "=r"(r1), "=r"(r2), "=r"(r3) : "r"(a));
}
__device__ __forceinline__ void mma16816(float* c, const uint32_t* a, const uint32_t* b){
    asm volatile("mma.sync.aligned.m16n8k16.row.col.f32.bf16.bf16.f32 "
        "{%0,%1,%2,%3}, {%4,%5,%6,%7}, {%8,%9}, {%0,%1,%2,%3};"
        : "+f"(c[0]), "+f"(c[1]), "+f"(c[2]), "+f"(c[3])
        : "r"(a[0]), "r"(a[1]), "r"(a[2]), "r"(a[3]), "r"(b[0]), "r"(b[1]));
}

__device__ __forceinline__ void store_split(bf16* ph, bf16* pl, size_t i, float v){
    bf16 h = __float2bfloat16(v);
    ph[i] = h;
    pl[i] = __float2bfloat16(v - __bfloat162float(h));
}

enum { EP_F32=0, EP_SIGQK=1, EP_BIAS=2, EP_AMEM=3, EP_DELTA=4, EP_MEMUPD=5 };

// ================= 512-thread HMMA GEMM body =================
#define G5_STG 98304
#define G5_SMEM (2*G5_STG)

__device__ void tc_gemm_body(
    const bf16* __restrict__ Ahg, const bf16* __restrict__ Alg,
    const bf16* __restrict__ Bhg, const bf16* __restrict__ Blg,
    int K, int lda, int ldb, int ldc,
    long sAb, long sAh, long sBb, long sBh, long sCb, long sCh,
    int mode,
    float* __restrict__ C, bf16* __restrict__ O1h, bf16* __restrict__ O1l,
    bf16* __restrict__ O2h, bf16* __restrict__ O2l,
    const float* __restrict__ rowdiv, const float* __restrict__ mix,
    const float* __restrict__ betas, const float* __restrict__ bias,
    bf16* __restrict__ Th, bf16* __restrict__ Tl, int tmode,
    int bx, int by, int bz, char* smemc)
{
    int z = bz, bb = z / H_, hh = z % H_;
    int m0 = by*128, n0 = bx*256;

    const bf16* Ah = Ahg + (size_t)bb*sAb + (size_t)hh*sAh;
    const bf16* Al = Alg + (size_t)bb*sAb + (size_t)hh*sAh;
    const bf16* Bh = Bhg + (size_t)bb*sBb + (size_t)hh*sBh;
    const bf16* Bl = Blg + (size_t)bb*sBb + (size_t)hh*sBh;
    size_t coff = (size_t)bb*sCb + (size_t)hh*sCh;

    int tid = threadIdx.x, wid = tid >> 5, lid = tid & 31;
    uint32_t sb = smem_u32(smemc);
    int wm = wid & 1, wn = wid >> 1;
    int mbase = wm*64, nbase = wn*32;

    float acc[4][4][4];
    #pragma unroll
    for (int i=0;i<4;i++)
        #pragma unroll
        for (int j=0;j<4;j++)
            #pragma unroll
            for (int r=0;r<4;r++) acc[i][j][r]=0.f;

    int nch = K >> 6;
    int row_l = tid >> 3, v_l = tid & 7;

    auto issue = [&](int ci, int s){
        int stg = s*G5_STG, kc0 = ci << 6;
        #pragma unroll
        for (int i=0;i<2;i++){
            int row = row_l + 64*i;
            uint32_t o = SWZ(row*128 + v_l*16);
            CP_ASYNC(sb+stg+o,       Ah + (size_t)(m0+row)*lda + kc0 + v_l*8);
            CP_ASYNC(sb+stg+16384+o, Al + (size_t)(m0+row)*lda + kc0 + v_l*8);
        }
        #pragma unroll
        for (int i=0;i<4;i++){
            int row = row_l + 64*i;
            uint32_t o = SWZ(row*128 + v_l*16);
            CP_ASYNC(sb+stg+32768+o, Bh + (size_t)(n0+row)*ldb + kc0 + v_l*8);
            CP_ASYNC(sb+stg+65536+o, Bl + (size_t)(n0+row)*ldb + kc0 + v_l*8);
        }
        CP_COMMIT();
    };

    issue(0, 0);
    if (nch > 1) issue(1, 1);

    for (int ci=0; ci<nch; ci++){
        if (ci+1 < nch) { CP_WAIT(1); } else { CP_WAIT(0); }
        __syncthreads();
        int stg = (ci&1)*G5_STG;

        #pragma unroll
        for (int ks=0; ks<4; ks++){
            int colb = ks*32 + ((lid>>4)&1)*16;
            uint32_t ah[4][4], al[4][4];
            #pragma unroll
            for (int mt=0; mt<4; mt++){
                int row = mbase + mt*16 + (lid & 15);
                uint32_t off = SWZ(row*128 + colb);
                ldm_x4(ah[mt][0],ah[mt][1],ah[mt][2],ah[mt][3], sb+stg+off);
                ldm_x4(al[mt][0],al[mt][1],al[mt][2],al[mt][3], sb+stg+16384+off);
            }
            uint32_t bh[4][2], bl[4][2];
            #pragma unroll
            for (int g=0; g<2; g++){
                int row = nbase + g*16 + (lid & 7) + ((lid>>4)&1)*8;
                int cb2 = ks*32 + ((lid>>3)&1)*16;
                uint32_t off = SWZ(row*128 + cb2);
                uint32_t r0,r1,r2,r3;
                ldm_x4(r0,r1,r2,r3, sb+stg+32768+off);
                bh[2*g][0]=r0; bh[2*g][1]=r1; bh[2*g+1][0]=r2; bh[2*g+1][1]=r3;
                ldm_x4(r0,r1,r2,r3, sb+stg+65536+off);
                bl[2*g][0]=r0; bl[2*g][1]=r1; bl[2*g+1][0]=r2; bl[2*g+1][1]=r3;
            }
            #pragma unroll
            for (int mt=0; mt<4; mt++)
                #pragma unroll
                for (int nt=0; nt<4; nt++){
                    mma16816(acc[mt][nt], ah[mt], bh[nt]);
                    mma16816(acc[mt][nt], ah[mt], bl[nt]);
                    mma16816(acc[mt][nt], al[mt], bh[nt]);
                }
        }
        __syncthreads();
        if (ci+2 < nch) issue(ci+2, ci&1);
    }

    float* buf = (float*)smemc;              // 128 x 260
    int tg = lid >> 2, t4 = lid & 3;
    #pragma unroll
    for (int mt=0; mt<4; mt++)
        #pragma unroll
        for (int nt=0; nt<4; nt++)
            #pragma unroll
            for (int r=0; r<4; r++){
                int m = mbase + mt*16 + tg + (r>=2 ? 8 : 0);
                int c = nbase + nt*8 + t4*2 + (r&1);
                buf[m*260 + c] = acc[mt][nt][r];
            }
    __syncthreads();

    float gate = 0.f;
    if (mode == EP_AMEM) gate = 1.f/(1.f + __expf(-betas[hh]));

    #pragma unroll 4
    for (int e=0; e<64; e++){
        int flat = e*512 + tid;
        int row = flat >> 8, col = flat & 255;
        float v = buf[row*260 + col];
        int m = m0 + row, c = n0 + col;
        size_t idx = coff + (size_t)m*ldc + c;
        if (mode == EP_F32) {
            if (C) C[idx] = v;
        } else if (mode == EP_SIGQK) {
            store_split(O1h, O1l, idx, v);
            float sg = v > 0.f ? v + 1.f : __expf(v);
            store_split(O2h, O2l, idx, sg);
            buf[row*260 + col] = sg;
        } else if (mode == EP_BIAS) {
            C[idx] = v + bias[c];
        } else if (mode == EP_AMEM) {
            float rinv = 1.f/(rowdiv[(size_t)z*S_ + m] + 1e-6f);
            float val = gate*(v*rinv) + (1.f-gate)*mix[idx];
            store_split(O1h, O1l, idx, val);
        } else if (mode == EP_DELTA) {
            float rinv = 1.f/(rowdiv[(size_t)z*S_ + m] + 1e-6f);
            float u = mix[idx] - v*rinv;
            if (C) C[idx] = u;
            buf[row*260 + col] = u;
        } else {
            float mv = mix[(size_t)hh*D_*D_ + (size_t)m*D_ + c];
            C[idx] = mv + v;
        }
    }

    if (tmode){
        __syncthreads();
        size_t tbase; int sofs;
        if (tmode == 1){
            int b = m0 >> 11;
            int s0 = m0 & 2047;
            int h = n0 >> 8;
            tbase = ((size_t)(b*H_ + h))*D_*S_;
            sofs = s0;
        } else {
            tbase = (size_t)z*D_*S_;
            sofs = m0;
        }
        #pragma unroll 4
        for (int e=0; e<32; e++){
            int flat = e*512 + tid;
            int d = flat >> 6;
            int s = (flat & 63)*2;
            float v0 = buf[(s+0)*260 + d];
            float v1 = buf[(s+1)*260 + d];
            bf16 h0 = __float2bfloat16(v0);
            bf16 h1 = __float2bfloat16(v1);
            bf16 l0 = __float2bfloat16(v0 - __bfloat162float(h0));
            bf16 l1 = __float2bfloat16(v1 - __bfloat162float(h1));
            size_t o = tbase + (size_t)d*S_ + sofs + s;
            *(__nv_bfloat162*)(Th + o) = __nv_bfloat162(h0, h1);
            *(__nv_bfloat162*)(Tl + o) = __nv_bfloat162(l0, l1);
        }
    }
}

__global__ void __launch_bounds__(512,1) tc_gemm(
    const bf16* __restrict__ Ahg, const bf16* __restrict__ Alg,
    const bf16* __restrict__ Bhg, const bf16* __restrict__ Blg,
    int K, int lda, int ldb, int ldc,
    long sAb, long sAh, long sBb, long sBh, long sCb, long sCh,
    int mode,
    float* __restrict__ C, bf16* __restrict__ O1h, bf16* __restrict__ O1l,
    bf16* __restrict__ O2h, bf16* __restrict__ O2l,
    const float* __restrict__ rowdiv, const float* __restrict__ mix,
    const float* __restrict__ betas, const float* __restrict__ bias,
    bf16* __restrict__ Th, bf16* __restrict__ Tl, int tmode)
{
    extern __shared__ char smemc[];
    tc_gemm_body(Ahg,Alg,Bhg,Blg,K,lda,ldb,ldc,sAb,sAh,sBb,sBh,sCb,sCh,mode,
                 C,O1h,O1l,O2h,O2l,rowdiv,mix,betas,bias,Th,Tl,tmode,
                 blockIdx.x, blockIdx.y, blockIdx.z, smemc);
}

// ================= fused flash attention body (512 threads, round-8 validated) =================
#define STG_BYTES 65536
#define FA_P     131072
#define FA_STAT  196608
#define FA_SMEM  (196608 + 3072)

__device__ void fa_body(
    const bf16* __restrict__ Qhg, const bf16* __restrict__ Qlg,
    const bf16* __restrict__ Khg, const bf16* __restrict__ Klg,
    const bf16* __restrict__ VThg, const bf16* __restrict__ VTlg,
    float* __restrict__ AO, int bid, char* smc)
{
    uint32_t sb = smem_u32(smc);
    int z  = (bid>>1)&15;
    int mi = (bid&1) ? (bid>>5) : 15-(bid>>5);
    int bb = z / H_, hh = z % H_;
    int m0 = mi*128;

    int tid = threadIdx.x, wid = tid>>5, lid = tid&31;
    int wm = wid&3, wn = wid>>2;            // 4 x 4 warp grid
    int tg = lid>>2, t4 = lid&3;

    const bf16* Qh_ = Qhg + (size_t)bb*S_*E_ + hh*D_;
    const bf16* Ql_ = Qlg + (size_t)bb*S_*E_ + hh*D_;
    const bf16* Kh_ = Khg + (size_t)bb*S_*E_ + hh*D_;
    const bf16* Kl_ = Klg + (size_t)bb*S_*E_ + hh*D_;
    const bf16* VTh_ = VThg + (size_t)z*D_*S_;
    const bf16* VTl_ = VTlg + (size_t)z*D_*S_;

    float* m_s = (float*)(smc + FA_STAT);
    float* l_s = (float*)(smc + FA_STAT + 512);
    float* red = (float*)(smc + FA_STAT + 1024);

    if (tid < 128){ m_s[tid] = -1e30f; l_s[tid] = 0.f; }

    float acc_o[2][8][4];
    #pragma unroll
    for (int a=0;a<2;a++)
        #pragma unroll
        for (int b=0;b<8;b++)
            #pragma unroll
            for (int r=0;r<4;r++) acc_o[a][b][r]=0.f;
    __syncthreads();

    int row_l = tid>>3, v_l = tid&7;        // 64 rows/pass

    for (int j=0; j<=mi; j++){
        int jb = j*128;
        float acc_s[2][4][4];
        #pragma unroll
        for (int a=0;a<2;a++)
            #pragma unroll
            for (int b=0;b<4;b++)
                #pragma unroll
                for (int r=0;r<4;r++) acc_s[a][b][r]=0.f;

        auto issueS = [&](int c, int s){
            int stg = s*STG_BYTES, kc0 = c*64;
            #pragma unroll
            for (int i=0;i<2;i++){
                int row = row_l + 64*i;
                uint32_t o = SWZ(row*128 + v_l*16);
                CP_ASYNC(sb+stg+o,       Qh_ + (size_t)(m0+row)*E_ + kc0 + v_l*8);
                CP_ASYNC(sb+stg+16384+o, Ql_ + (size_t)(m0+row)*E_ + kc0 + v_l*8);
                CP_ASYNC(sb+stg+32768+o, Kh_ + (size_t)(jb+row)*E_ + kc0 + v_l*8);
                CP_ASYNC(sb+stg+49152+o, Kl_ + (size_t)(jb+row)*E_ + kc0 + v_l*8);
            }
            CP_COMMIT();
        };
        auto issueV = [&](int kc, int s){
            int stg = s*STG_BYTES;
            #pragma unroll
            for (int i=0;i<4;i++){
                int row = row_l + 64*i;
                uint32_t o = SWZ(row*128 + v_l*16);
                CP_ASYNC(sb+stg+o,       VTh_ + (size_t)row*S_ + jb + kc*64 + v_l*8);
                CP_ASYNC(sb+stg+32768+o, VTl_ + (size_t)row*S_ + jb + kc*64 + v_l*8);
            }
            CP_COMMIT();
        };

        issueS(0,0); issueS(1,1);
        for (int c=0;c<4;c++){
            if (c<3) { CP_WAIT(1); } else { CP_WAIT(0); }
            __syncthreads();
            int stg = (c&1)*STG_BYTES;
            #pragma unroll
            for (int ks=0; ks<4; ks++){
                uint32_t bh[4][2], bl[4][2];
                #pragma unroll
                for (int g=0; g<2; g++){
                    int row = wn*32 + g*16 + (lid&7) + ((lid>>4)&1)*8;
                    int cb2 = ks*32 + ((lid>>3)&1)*16;
                    uint32_t off = SWZ(row*128 + cb2);
                    uint32_t r0,r1,r2,r3;
                    ldm_x4(r0,r1,r2,r3, sb+stg+32768+off);
                    bh[2*g][0]=r0; bh[2*g][1]=r1; bh[2*g+1][0]=r2; bh[2*g+1][1]=r3;
                    ldm_x4(r0,r1,r2,r3, sb+stg+49152+off);
                    bl[2*g][0]=r0; bl[2*g][1]=r1; bl[2*g+1][0]=r2; bl[2*g+1][1]=r3;
                }
                #pragma unroll
                for (int mt=0; mt<2; mt++){
                    int row = wm*32 + mt*16 + (lid&15);
                    uint32_t colb = ks*32 + ((lid>>4)&1)*16;
                    uint32_t off = SWZ(row*128 + colb);
                    uint32_t ah[4], al[4];
                    ldm_x4(ah[0],ah[1],ah[2],ah[3], sb+stg+off);
                    ldm_x4(al[0],al[1],al[2],al[3], sb+stg+16384+off);
                    #pragma unroll
                    for (int nt=0;nt<4;nt++){
                        mma16816(acc_s[mt][nt], ah, bh[nt]);
                        mma16816(acc_s[mt][nt], ah, bl[nt]);
                        mma16816(acc_s[mt][nt], al, bh[nt]);
                    }
                }
            }
            __syncthreads();
            if (c==0) issueS(2,0);
            else if (c==1) issueS(3,1);
        }

        issueV(0,0); issueV(1,1);

        if (j == mi){
            #pragma unroll
            for (int mt=0; mt<2; mt++)
                #pragma unroll
                for (int nt=0; nt<4; nt++)
                    #pragma unroll
                    for (int r=0;r<4;r++){
                        int srow = wm*32 + mt*16 + tg + ((r>>1)&1)*8;
                        int scol = wn*32 + nt*8 + t4*2 + (r&1);
                        if (scol > srow) acc_s[mt][nt][r] = -1e30f;
                    }
        }
        float rmax[2][2];
        #pragma unroll
        for (int mt=0; mt<2; mt++)
            #pragma unroll
            for (int hf=0; hf<2; hf++){
                float m = -1e30f;
                #pragma unroll
                for (int nt=0; nt<4; nt++){
                    m = fmaxf(m, acc_s[mt][nt][hf*2+0]);
                    m = fmaxf(m, acc_s[mt][nt][hf*2+1]);
                }
                m = fmaxf(m, __shfl_xor_sync(0xffffffffu, m, 1));
                m = fmaxf(m, __shfl_xor_sync(0xffffffffu, m, 2));
                rmax[mt][hf] = m;
            }
        if (t4 == 0){
            #pragma unroll
            for (int mt=0; mt<2; mt++)
                #pragma unroll
                for (int hf=0; hf<2; hf++)
                    red[wn*128 + wm*32 + mt*16 + tg + hf*8] = rmax[mt][hf];
        }
        __syncthreads();

        float mnew[2][2], alpha[2][2], rsum[2][2];
        #pragma unroll
        for (int mt=0; mt<2; mt++)
            #pragma unroll
            for (int hf=0; hf<2; hf++){
                int row = wm*32 + mt*16 + tg + hf*8;
                float rm = fmaxf(fmaxf(red[row], red[128+row]), fmaxf(red[256+row], red[384+row]));
                float mo = m_s[row];
                float mn = fmaxf(mo, rm);
                mnew[mt][hf] = mn;
                alpha[mt][hf] = __expf(mo - mn);
                rsum[mt][hf] = 0.f;
            }
        #pragma unroll
        for (int mt=0; mt<2; mt++)
            #pragma unroll
            for (int nt=0; nt<4; nt++)
                #pragma unroll
                for (int r=0;r<4;r++){
                    int hf = r>>1;
                    float p = __expf(acc_s[mt][nt][r] - mnew[mt][hf]);
                    acc_s[mt][nt][r] = p;
                    rsum[mt][hf] += p;
                }
        #pragma unroll
        for (int mt=0; mt<2; mt++)
            #pragma unroll
            for (int hf=0; hf<2; hf++){
                rsum[mt][hf] += __shfl_xor_sync(0xffffffffu, rsum[mt][hf], 1);
                rsum[mt][hf] += __shfl_xor_sync(0xffffffffu, rsum[mt][hf], 2);
            }
        __syncthreads();
        if (t4 == 0){
            #pragma unroll
            for (int mt=0; mt<2; mt++)
                #pragma unroll
                for (int hf=0; hf<2; hf++)
                    red[wn*128 + wm*32 + mt*16 + tg + hf*8] = rsum[mt][hf];
        }
        #pragma unroll
        for (int mt=0; mt<2; mt++)
            #pragma unroll
            for (int nt=0; nt<4; nt++)
                #pragma unroll
                for (int rp=0; rp<2; rp++){
                    int row = wm*32 + mt*16 + tg + rp*8;
                    int col = wn*32 + nt*8 + t4*2;
                    float p0 = acc_s[mt][nt][rp*2+0];
                    float p1 = acc_s[mt][nt][rp*2+1];
                    bf16 h0 = __float2bfloat16(p0);
                    bf16 h1 = __float2bfloat16(p1);
                    bf16 l0 = __float2bfloat16(p0 - __bfloat162float(h0));
                    bf16 l1 = __float2bfloat16(p1 - __bfloat162float(h1));
                    uint32_t o = (uint32_t)(col>>6)*16384u + SWZ((uint32_t)row*128 + (col&63)*2);
                    *(__nv_bfloat162*)(smc + FA_P + o)         = __nv_bfloat162(h0, h1);
                    *(__nv_bfloat162*)(smc + FA_P + 32768 + o) = __nv_bfloat162(l0, l1);
                }
        #pragma unroll
        for (int mt=0; mt<2; mt++)
            #pragma unroll
            for (int nt=0; nt<8; nt++)
                #pragma unroll
                for (int r=0;r<4;r++)
                    acc_o[mt][nt][r] *= alpha[mt][r>>1];
        __syncthreads();
        if (wn == 0 && t4 == 0){
            #pragma unroll
            for (int mt=0; mt<2; mt++)
                #pragma unroll
                for (int hf=0; hf<2; hf++){
                    int row = wm*32 + mt*16 + tg + hf*8;
                    float rs = red[row] + red[128+row] + red[256+row] + red[384+row];
                    l_s[row] = l_s[row]*alpha[mt][hf] + rs;
                    m_s[row] = mnew[mt][hf];
                }
        }

        for (int kc=0; kc<2; kc++){
            if (kc==0) { CP_WAIT(1); } else { CP_WAIT(0); }
            __syncthreads();
            int stg = kc*STG_BYTES;
            uint32_t pb = FA_P + kc*16384;
            #pragma unroll
            for (int ks=0; ks<4; ks++){
                uint32_t bh[8][2], bl[8][2];
                #pragma unroll
                for (int g=0; g<4; g++){
                    int row = wn*64 + g*16 + (lid&7) + ((lid>>4)&1)*8;
                    int cb2 = ks*32 + ((lid>>3)&1)*16;
                    uint32_t off = SWZ(row*128 + cb2);
                    uint32_t r0,r1,r2,r3;
                    ldm_x4(r0,r1,r2,r3, sb+stg+off);
                    bh[2*g][0]=r0; bh[2*g][1]=r1; bh[2*g+1][0]=r2; bh[2*g+1][1]=r3;
                    ldm_x4(r0,r1,r2,r3, sb+stg+32768+off);
                    bl[2*g][0]=r0; bl[2*g][1]=r1; bl[2*g+1][0]=r2; bl[2*g+1][1]=r3;
                }
                #pragma unroll
                for (int mt=0; mt<2; mt++){
                    int row = wm*32 + mt*16 + (lid&15);
                    uint32_t colb = ks*32 + ((lid>>4)&1)*16;
                    uint32_t off = SWZ(row*128 + colb);
                    uint32_t ah[4], al[4];
                    ldm_x4(ah[0],ah[1],ah[2],ah[3], sb+pb+off);
                    ldm_x4(al[0],al[1],al[2],al[3], sb+pb+32768+off);
                    #pragma unroll
                    for (int nt=0;nt<8;nt++){
                        mma16816(acc_o[mt][nt], ah, bh[nt]);
                        mma16816(acc_o[mt][nt], ah, bl[nt]);
                        mma16816(acc_o[mt][nt], al, bh[nt]);
                    }
                }
            }
            __syncthreads();
        }
    }

    __syncthreads();
    float* AOp = AO + (size_t)bb*S_*E_ + hh*D_;
    #pragma unroll
    for (int mt=0; mt<2; mt++)
        #pragma unroll
        for (int hf=0; hf<2; hf++){
            int row = wm*32 + mt*16 + tg + hf*8;
            float linv = 1.f/l_s[row];
            #pragma unroll
            for (int nt=0; nt<8; nt++){
                int col = wn*64 + nt*8 + t4*2;
                float2 v;
                v.x = acc_o[mt][nt][hf*2+0]*linv;
                v.y = acc_o[mt][nt][hf*2+1]*linv;
                *(float2*)(AOp + (size_t)(m0+row)*E_ + col) = v;
            }
        }
}

// ================= merged launch A: fa (0-255) | DELTA (256-511) | znew (512-1023) =================
__global__ void __launch_bounds__(512,1) fused_attn_delta(
    const bf16* __restrict__ Qh, const bf16* __restrict__ Ql,
    const bf16* __restrict__ Kh, const bf16* __restrict__ Kl,
    const bf16* __restrict__ VTh, const bf16* __restrict__ VTl,
    float* __restrict__ AO,
    const bf16* __restrict__ SKh, const bf16* __restrict__ SKl,
    const bf16* __restrict__ memTh, const bf16* __restrict__ memTl,
    const float* __restrict__ Zk, const float* __restrict__ Vf,
    bf16* __restrict__ UTh, bf16* __restrict__ UTl,
    const bf16* __restrict__ SKTh, const bf16* __restrict__ SKTl,
    const float* __restrict__ zvec, float* __restrict__ zout)
{
    extern __shared__ char smc[];
    int bid = blockIdx.x;
    if (bid < 256){
        fa_body(Qh,Ql,Kh,Kl,VTh,VTl, AO, bid, smc);
    } else if (bid < 512){
        int n = bid - 256;
        tc_gemm_body(SKh,SKl,memTh,memTl, D_, E_,D_,E_,
            (long)S_*E_, D_, 0, (long)D_*D_, (long)S_*E_, (long)D_,
            EP_DELTA, 0, 0,0,0,0, Zk, Vf, 0, 0, UTh,UTl,2,
            0, n & 15, n >> 4, smc);
    } else {
        if (threadIdx.x < 256){
            int w = threadIdx.x >> 5, lane = threadIdx.x & 31;
            int r = (bid - 512)*8 + w;         // [0, BH_*D_)
            int z = r / D_, d = r % D_;
            const bf16* ph = SKTh + (size_t)r*S_;
            const bf16* pl = SKTl + (size_t)r*S_;
            float acc = 0.f;
            #pragma unroll 4
            for (int s=lane; s<S_; s+=32)
                acc += __bfloat162float(ph[s]) + __bfloat162float(pl[s]);
            #pragma unroll
            for (int o=16;o;o>>=1) acc += __shfl_xor_sync(0xffffffffu, acc, o);
            if (lane==0) zout[r] = zvec[(z%H_)*D_ + d] + acc;
        }
    }
}

// ================= merged launch B: AMEM (0-255) | memupd (256-287) =================
__global__ void __launch_bounds__(512,1) fused_amem_memupd(
    const bf16* __restrict__ SQh, const bf16* __restrict__ SQl,
    const bf16* __restrict__ memTh, const bf16* __restrict__ memTl,
    const float* __restrict__ Zq, const float* __restrict__ AO,
    const float* __restrict__ betas,
    bf16* __restrict__ ABh, bf16* __restrict__ ABl,
    const bf16* __restrict__ SKTh, const bf16* __restrict__ SKTl,
    const bf16* __restrict__ UTh, const bf16* __restrict__ UTl,
    const float* __restrict__ memp, float* __restrict__ memout)
{
    extern __shared__ char smc[];
    int bid = blockIdx.x;
    if (bid < 256){
        int n = bid;
        tc_gemm_body(SQh,SQl,memTh,memTl, D_, E_,D_,E_,
            (long)S_*E_, D_, 0, (long)D_*D_, (long)S_*E_, (long)D_,
            EP_AMEM, 0, ABh,ABl, 0,0, Zq, AO, betas, 0, 0,0,0,
            0, n & 15, n >> 4, smc);
    } else {
        int n = bid - 256;
        tc_gemm_body(SKTh,SKTl,UTh,UTl, S_, S_,S_,D_,
            (long)H_*D_*S_, (long)D_*S_, (long)H_*D_*S_, (long)D_*S_, (long)H_*D_*D_, (long)D_*D_,
            EP_MEMUPD, memout, 0,0,0,0, 0, memp, 0, 0, 0,0,0,
            0, n & 1, n >> 1, smc);
    }
}

// ================= small kernels =================
__global__ void split_f32(const float* __restrict__ src, bf16* __restrict__ h, bf16* __restrict__ l, int n4){
    int i = blockIdx.x*blockDim.x + threadIdx.x;
    if (i >= n4) return;
    float4 v = ((const float4*)src)[i];
    size_t o = (size_t)i*4;
    store_split(h, l, o+0, v.x); store_split(h, l, o+1, v.y);
    store_split(h, l, o+2, v.z); store_split(h, l, o+3, v.w);
}

__global__ void transW(const float* __restrict__ W, bf16* __restrict__ Th, bf16* __restrict__ Tl){
    __shared__ float t[32][33];
    int k0 = blockIdx.x*32, n0 = blockIdx.y*32;
    int tx = threadIdx.x, ty = threadIdx.y;
    #pragma unroll
    for (int i=0;i<32;i+=8) t[ty+i][tx] = W[(size_t)(k0+ty+i)*E_ + n0+tx];
    __syncthreads();
    #pragma unroll
    for (int i=0;i<32;i+=8){
        size_t o = (size_t)(n0+ty+i)*E_ + k0+tx;
        store_split(Th, Tl, o, t[tx][ty+i]);
    }
}

__global__ void transMem(const float* __restrict__ M, bf16* __restrict__ Th, bf16* __restrict__ Tl){
    __shared__ float t[32][33];
    int h = blockIdx.z;
    int d0 = blockIdx.x*32, e0 = blockIdx.y*32;
    int tx = threadIdx.x, ty = threadIdx.y;
    #pragma unroll
    for (int i=0;i<32;i+=8) t[ty+i][tx] = M[(size_t)h*D_*D_ + (size_t)(d0+ty+i)*D_ + e0+tx];
    __syncthreads();
    #pragma unroll
    for (int i=0;i<32;i+=8){
        size_t o = (size_t)h*D_*D_ + (size_t)(e0+ty+i)*D_ + d0+tx;
        store_split(Th, Tl, o, t[tx][ty+i]);
    }
}

__global__ void rowdot_split(const bf16* __restrict__ Hh, const bf16* __restrict__ Hl,
                             const float* __restrict__ zvec, float* __restrict__ out){
    int w = threadIdx.x >> 5, lane = threadIdx.x & 31;
    int r = blockIdx.x*8 + w;
    int z = r / S_, s = r % S_;
    int b = z / H_, h = z % H_;
    size_t base = (size_t)(b*S_+s)*E_ + h*D_;
    const float* zp = zvec + h*D_;
    float acc = 0.f;
    #pragma unroll
    for (int d=lane; d<D_; d+=32)
        acc += (__bfloat162float(Hh[base+d]) + __bfloat162float(Hl[base+d])) * zp[d];
    #pragma unroll
    for (int o=16;o;o>>=1) acc += __shfl_xor_sync(0xffffffffu, acc, o);
    if (lane==0) out[r] = acc;
}

// ================= launch =================
extern "C" void kernel_launch(void* const* d_in, const int* in_sizes, int n_in,
                              void* d_out, int out_size)
{
    const float* hs    = (const float*)d_in[0];
    const float* Wq    = (const float*)d_in[1];
    const float* Wk    = (const float*)d_in[2];
    const float* Wv    = (const float*)d_in[3];
    const float* Wo    = (const float*)d_in[4];
    const float* bo    = (const float*)d_in[5];
    const float* betas = (const float*)d_in[6];
    const float* memp  = (const float*)d_in[7];
    const float* zv    = (const float*)d_in[8];
    float* out = (float*)d_out;

    cudaFuncSetAttribute(tc_gemm, cudaFuncAttributeMaxDynamicSharedMemorySize, G5_SMEM);
    cudaFuncSetAttribute(fused_attn_delta, cudaFuncAttributeMaxDynamicSharedMemorySize, FA_SMEM);
    cudaFuncSetAttribute(fused_amem_memupd, cudaFuncAttributeMaxDynamicSharedMemorySize, G5_SMEM);

#define GS(var, sym) cudaGetSymbolAddress((void**)&var, sym)
    bf16 *HSh,*HSl,*WqTh,*WqTl,*WkTh,*WkTl,*WvTh,*WvTl,*WoTh,*WoTl,*memTh,*memTl;
    bf16 *Qh,*Ql,*Kh,*Kl,*SQh,*SQl,*SKh,*SKl,*ABh,*ABl,*VTh,*VTl,*UTh,*UTl,*SKTh,*SKTl;
    float *Vf,*AO,*Zq,*Zk;
    GS(HSh,g_HSh); GS(HSl,g_HSl);
    GS(WqTh,g_WqTh); GS(WqTl,g_WqTl); GS(WkTh,g_WkTh); GS(WkTl,g_WkTl);
    GS(WvTh,g_WvTh); GS(WvTl,g_WvTl); GS(WoTh,g_WoTh); GS(WoTl,g_WoTl);
    GS(memTh,g_memTh); GS(memTl,g_memTl);
    GS(Qh,g_Qh); GS(Ql,g_Ql); GS(Kh,g_Kh); GS(Kl,g_Kl);
    GS(SQh,g_SQh); GS(SQl,g_SQl); GS(SKh,g_SKh); GS(SKl,g_SKl);
    GS(ABh,g_ABh); GS(ABl,g_ABl);
    GS(VTh,g_VTh); GS(VTl,g_VTl); GS(UTh,g_UTh); GS(UTl,g_UTl);
    GS(SKTh,g_SKTh); GS(SKTl,g_SKTl);
    GS(Vf,g_Vf); GS(AO,g_AO);
    GS(Zq,g_Zq); GS(Zk,g_Zk);

    const long OUT_MEM = (long)B_*S_*E_;
    const long OUT_Z   = OUT_MEM + (long)B_*H_*D_*D_;
    dim3 t256(256), t512(512), t328(32,8);

    // input conversions
    split_f32<<<MSZ/1024, t256>>>(hs, HSh, HSl, MSZ/4);
    transW<<<dim3(32,32), t328>>>(Wq, WqTh, WqTl);
    transW<<<dim3(32,32), t328>>>(Wk, WkTh, WkTl);
    transW<<<dim3(32,32), t328>>>(Wv, WvTh, WvTl);
    transW<<<dim3(32,32), t328>>>(Wo, WoTh, WoTl);
    transMem<<<dim3(8,8,H_), t328>>>(memp, memTh, memTl);

    // projections (transposed outputs fused into epilogues)
    tc_gemm<<<dim3(4,64,1), t512, G5_SMEM>>>(HSh,HSl,WqTh,WqTl, E_,E_,E_,E_,
        0,0,0,0,0,0, EP_SIGQK, 0, Qh,Ql, SQh,SQl, 0,0,0,0, 0,0,0);
    tc_gemm<<<dim3(4,64,1), t512, G5_SMEM>>>(HSh,HSl,WkTh,WkTl, E_,E_,E_,E_,
        0,0,0,0,0,0, EP_SIGQK, 0, Kh,Kl, SKh,SKl, 0,0,0,0, SKTh,SKTl,1);
    tc_gemm<<<dim3(4,64,1), t512, G5_SMEM>>>(HSh,HSl,WvTh,WvTl, E_,E_,E_,E_,
        0,0,0,0,0,0, EP_F32, Vf, 0,0,0,0, 0,0,0,0, VTh,VTl,1);

    // sigma . z (needed before DELTA / AMEM)
    rowdot_split<<<BH_*S_/8, t256>>>(SQh, SQl, zv, Zq);
    rowdot_split<<<BH_*S_/8, t256>>>(SKh, SKl, zv, Zk);

    // merged: flash attention ∥ U = V - delta ∥ z_new
    fused_attn_delta<<<1024, t512, FA_SMEM>>>(
        Qh,Ql,Kh,Kl,VTh,VTl, AO,
        SKh,SKl, memTh,memTl, Zk, Vf, UTh,UTl,
        SKTh,SKTl, zv, out+OUT_Z);

    // merged: A_mem+gate ∥ mem_new
    fused_amem_memupd<<<288, t512, G5_SMEM>>>(
        SQh,SQl, memTh,memTl, Zq, AO, betas, ABh,ABl,
        SKTh,SKTl, UTh,UTl, memp, out+OUT_MEM);

    // out projection + bias
    tc_gemm<<<dim3(4,64,1), t512, G5_SMEM>>>(ABh,ABl,WoTh,WoTl, E_,E_,E_,E_,
        0,0,0,0,0,0, EP_BIAS, out, 0,0,0,0, 0,0,0, bo, 0,0,0);
}

// round 12
// speedup vs baseline: 1.2021x; 1.0209x over previous
#include <cuda_runtime.h>
#include <cuda_bf16.h>
#include <cstdint>
#include <math.h>

#define B_ 4
#define S_ 2048
#define E_ 1024
#define H_ 4
#define D_ 256
#define BH_ 16
#define MSZ (B_*S_*E_)

typedef __nv_bfloat16 bf16;

// ================= device scratch =================
__device__ bf16 g_HSh[MSZ], g_HSl[MSZ];
__device__ bf16 g_WqTh[E_*E_], g_WqTl[E_*E_];
__device__ bf16 g_WkTh[E_*E_], g_WkTl[E_*E_];
__device__ bf16 g_WvTh[E_*E_], g_WvTl[E_*E_];
__device__ bf16 g_WoTh[E_*E_], g_WoTl[E_*E_];
__device__ bf16 g_memTh[H_*D_*D_], g_memTl[H_*D_*D_];
__device__ bf16 g_Qh[MSZ], g_Ql[MSZ], g_Kh[MSZ], g_Kl[MSZ];
__device__ bf16 g_SQh[MSZ], g_SQl[MSZ], g_SKh[MSZ], g_SKl[MSZ];
__device__ bf16 g_ABh[MSZ], g_ABl[MSZ];
__device__ bf16 g_VTh[MSZ], g_VTl[MSZ];
__device__ bf16 g_UTh[MSZ], g_UTl[MSZ];
__device__ bf16 g_SKTh[MSZ], g_SKTl[MSZ];
__device__ float g_Vf[MSZ], g_AO[MSZ];
__device__ float g_Zq[BH_*S_], g_Zk[BH_*S_];

// ================= helpers =================
__device__ __forceinline__ uint32_t smem_u32(const void* p){
    uint32_t a;
    asm("{ .reg .u64 t; cvta.to.shared.u64 t, %1; cvt.u32.u64 %0, t; }" : "=r"(a) : "l"(p));
    return a;
}
#define SWZ(o) ((o) ^ (((o) >> 3) & 0x70))

#define CP_ASYNC(daddr, gptr) \
    asm volatile("cp.async.cg.shared.global [%0], [%1], 16;" :: "r"(daddr), "l"(gptr) : "memory")
#define CP_COMMIT() asm volatile("cp.async.commit_group;" ::: "memory")
#define CP_WAIT(n)  asm volatile("cp.async.wait_group %0;" :: "n"(n) : "memory")

__device__ __forceinline__ void ldm_x4(uint32_t& r0, uint32_t& r1, uint32_t& r2, uint32_t& r3, uint32_t a){
    asm volatile("ldmatrix.sync.aligned.m8n8.x4.shared.b16 {%0,%1,%2,%3}, [%4];"
        : "=r"(r0), "=r"(r1), "=r"(r2), "=r"(r3) : "r"(a));
}
__device__ __forceinline__ void mma16816(float* c, const uint32_t* a, const uint32_t* b){
    asm volatile("mma.sync.aligned.m16n8k16.row.col.f32.bf16.bf16.f32 "
        "{%0,%1,%2,%3}, {%4,%5,%6,%7}, {%8,%9}, {%0,%1,%2,%3};"
        : "+f"(c[0]), "+f"(c[1]), "+f"(c[2]), "+f"(c[3])
        : "r"(a[0]), "r"(a[1]), "r"(a[2]), "r"(a[3]), "r"(b[0]), "r"(b[1]));
}

__device__ __forceinline__ void store_split(bf16* ph, bf16* pl, size_t i, float v){
    bf16 h = __float2bfloat16(v);
    ph[i] = h;
    pl[i] = __float2bfloat16(v - __bfloat162float(h));
}

enum { EP_F32=0, EP_SIGQK=1, EP_BIAS=2, EP_AMEM=3, EP_DELTA=4, EP_MEMUPD=5 };

// ================= 512-thread HMMA GEMM body =================
#define G5_STG 98304
#define G5_SMEM (2*G5_STG)

__device__ void tc_gemm_body(
    const bf16* __restrict__ Ahg, const bf16* __restrict__ Alg,
    const bf16* __restrict__ Bhg, const bf16* __restrict__ Blg,
    int K, int lda, int ldb, int ldc,
    long sAb, long sAh, long sBb, long sBh, long sCb, long sCh,
    int mode,
    float* __restrict__ C, bf16* __restrict__ O1h, bf16* __restrict__ O1l,
    bf16* __restrict__ O2h, bf16* __restrict__ O2l,
    const float* __restrict__ rowdiv, const float* __restrict__ mix,
    const float* __restrict__ betas, const float* __restrict__ bias,
    bf16* __restrict__ Th, bf16* __restrict__ Tl, int tmode,
    const float* __restrict__ zdotv, float* __restrict__ Zout,
    int bx, int by, int bz, char* smemc)
{
    int z = bz, bb = z / H_, hh = z % H_;
    int m0 = by*128, n0 = bx*256;

    const bf16* Ah = Ahg + (size_t)bb*sAb + (size_t)hh*sAh;
    const bf16* Al = Alg + (size_t)bb*sAb + (size_t)hh*sAh;
    const bf16* Bh = Bhg + (size_t)bb*sBb + (size_t)hh*sBh;
    const bf16* Bl = Blg + (size_t)bb*sBb + (size_t)hh*sBh;
    size_t coff = (size_t)bb*sCb + (size_t)hh*sCh;

    int tid = threadIdx.x, wid = tid >> 5, lid = tid & 31;
    uint32_t sb = smem_u32(smemc);
    int wm = wid & 1, wn = wid >> 1;
    int mbase = wm*64, nbase = wn*32;

    float acc[4][4][4];
    #pragma unroll
    for (int i=0;i<4;i++)
        #pragma unroll
        for (int j=0;j<4;j++)
            #pragma unroll
            for (int r=0;r<4;r++) acc[i][j][r]=0.f;

    int nch = K >> 6;
    int row_l = tid >> 3, v_l = tid & 7;

    auto issue = [&](int ci, int s){
        int stg = s*G5_STG, kc0 = ci << 6;
        #pragma unroll
        for (int i=0;i<2;i++){
            int row = row_l + 64*i;
            uint32_t o = SWZ(row*128 + v_l*16);
            CP_ASYNC(sb+stg+o,       Ah + (size_t)(m0+row)*lda + kc0 + v_l*8);
            CP_ASYNC(sb+stg+16384+o, Al + (size_t)(m0+row)*lda + kc0 + v_l*8);
        }
        #pragma unroll
        for (int i=0;i<4;i++){
            int row = row_l + 64*i;
            uint32_t o = SWZ(row*128 + v_l*16);
            CP_ASYNC(sb+stg+32768+o, Bh + (size_t)(n0+row)*ldb + kc0 + v_l*8);
            CP_ASYNC(sb+stg+65536+o, Bl + (size_t)(n0+row)*ldb + kc0 + v_l*8);
        }
        CP_COMMIT();
    };

    issue(0, 0);
    if (nch > 1) issue(1, 1);

    for (int ci=0; ci<nch; ci++){
        if (ci+1 < nch) { CP_WAIT(1); } else { CP_WAIT(0); }
        __syncthreads();
        int stg = (ci&1)*G5_STG;

        #pragma unroll
        for (int ks=0; ks<4; ks++){
            int colb = ks*32 + ((lid>>4)&1)*16;
            uint32_t ah[4][4], al[4][4];
            #pragma unroll
            for (int mt=0; mt<4; mt++){
                int row = mbase + mt*16 + (lid & 15);
                uint32_t off = SWZ(row*128 + colb);
                ldm_x4(ah[mt][0],ah[mt][1],ah[mt][2],ah[mt][3], sb+stg+off);
                ldm_x4(al[mt][0],al[mt][1],al[mt][2],al[mt][3], sb+stg+16384+off);
            }
            uint32_t bh[4][2], bl[4][2];
            #pragma unroll
            for (int g=0; g<2; g++){
                int row = nbase + g*16 + (lid & 7) + ((lid>>4)&1)*8;
                int cb2 = ks*32 + ((lid>>3)&1)*16;
                uint32_t off = SWZ(row*128 + cb2);
                uint32_t r0,r1,r2,r3;
                ldm_x4(r0,r1,r2,r3, sb+stg+32768+off);
                bh[2*g][0]=r0; bh[2*g][1]=r1; bh[2*g+1][0]=r2; bh[2*g+1][1]=r3;
                ldm_x4(r0,r1,r2,r3, sb+stg+65536+off);
                bl[2*g][0]=r0; bl[2*g][1]=r1; bl[2*g+1][0]=r2; bl[2*g+1][1]=r3;
            }
            #pragma unroll
            for (int mt=0; mt<4; mt++)
                #pragma unroll
                for (int nt=0; nt<4; nt++){
                    mma16816(acc[mt][nt], ah[mt], bh[nt]);
                    mma16816(acc[mt][nt], ah[mt], bl[nt]);
                    mma16816(acc[mt][nt], al[mt], bh[nt]);
                }
        }
        __syncthreads();
        if (ci+2 < nch) issue(ci+2, ci&1);
    }

    float* buf = (float*)smemc;              // 128 x 260
    int tg = lid >> 2, t4 = lid & 3;
    #pragma unroll
    for (int mt=0; mt<4; mt++)
        #pragma unroll
        for (int nt=0; nt<4; nt++)
            #pragma unroll
            for (int r=0; r<4; r++){
                int m = mbase + mt*16 + tg + (r>=2 ? 8 : 0);
                int c = nbase + nt*8 + t4*2 + (r&1);
                buf[m*260 + c] = acc[mt][nt][r];
            }
    __syncthreads();

    float gate = 0.f;
    if (mode == EP_AMEM) gate = 1.f/(1.f + __expf(-betas[hh]));

    #pragma unroll 4
    for (int e=0; e<64; e++){
        int flat = e*512 + tid;
        int row = flat >> 8, col = flat & 255;
        float v = buf[row*260 + col];
        int m = m0 + row, c = n0 + col;
        size_t idx = coff + (size_t)m*ldc + c;
        if (mode == EP_F32) {
            if (C) C[idx] = v;
        } else if (mode == EP_SIGQK) {
            store_split(O1h, O1l, idx, v);
            float sg = v > 0.f ? v + 1.f : __expf(v);
            store_split(O2h, O2l, idx, sg);
            buf[row*260 + col] = sg;
        } else if (mode == EP_BIAS) {
            C[idx] = v + bias[c];
        } else if (mode == EP_AMEM) {
            float rinv = 1.f/(rowdiv[(size_t)z*S_ + m] + 1e-6f);
            float val = gate*(v*rinv) + (1.f-gate)*mix[idx];
            store_split(O1h, O1l, idx, val);
        } else if (mode == EP_DELTA) {
            float rinv = 1.f/(rowdiv[(size_t)z*S_ + m] + 1e-6f);
            float u = mix[idx] - v*rinv;
            if (C) C[idx] = u;
            buf[row*260 + col] = u;
        } else {
            float mv = mix[(size_t)hh*D_*D_ + (size_t)m*D_ + c];
            C[idx] = mv + v;
        }
    }

    // ---- fused rowdot for sigma projections: Zout[z*S+s] = dot(sigma_row, zvec_head) ----
    if (mode == EP_SIGQK && Zout){
        __syncthreads();
        int bp = m0 >> 11, hp = n0 >> 8;
        int s0 = m0 & 2047;
        float* Zp = Zout + ((size_t)(bp*H_ + hp))*S_ + s0;
        const float* zvp = zdotv + hp*D_;
        int row = tid >> 2, q = tid & 3;
        float acc2 = 0.f;
        #pragma unroll 16
        for (int c = q*64; c < q*64 + 64; c++)
            acc2 += buf[row*260 + c] * zvp[c];
        acc2 += __shfl_xor_sync(0xffffffffu, acc2, 1);
        acc2 += __shfl_xor_sync(0xffffffffu, acc2, 2);
        if (q == 0) Zp[row] = acc2;
    }

    if (tmode){
        __syncthreads();
        size_t tbase; int sofs;
        if (tmode == 1){
            int b = m0 >> 11;
            int s0 = m0 & 2047;
            int h = n0 >> 8;
            tbase = ((size_t)(b*H_ + h))*D_*S_;
            sofs = s0;
        } else {
            tbase = (size_t)z*D_*S_;
            sofs = m0;
        }
        #pragma unroll 4
        for (int e=0; e<32; e++){
            int flat = e*512 + tid;
            int d = flat >> 6;
            int s = (flat & 63)*2;
            float v0 = buf[(s+0)*260 + d];
            float v1 = buf[(s+1)*260 + d];
            bf16 h0 = __float2bfloat16(v0);
            bf16 h1 = __float2bfloat16(v1);
            bf16 l0 = __float2bfloat16(v0 - __bfloat162float(h0));
            bf16 l1 = __float2bfloat16(v1 - __bfloat162float(h1));
            size_t o = tbase + (size_t)d*S_ + sofs + s;
            *(__nv_bfloat162*)(Th + o) = __nv_bfloat162(h0, h1);
            *(__nv_bfloat162*)(Tl + o) = __nv_bfloat162(l0, l1);
        }
    }
}

__global__ void __launch_bounds__(512,1) tc_gemm(
    const bf16* __restrict__ Ahg, const bf16* __restrict__ Alg,
    const bf16* __restrict__ Bhg, const bf16* __restrict__ Blg,
    int K, int lda, int ldb, int ldc,
    long sAb, long sAh, long sBb, long sBh, long sCb, long sCh,
    int mode,
    float* __restrict__ C, bf16* __restrict__ O1h, bf16* __restrict__ O1l,
    bf16* __restrict__ O2h, bf16* __restrict__ O2l,
    const float* __restrict__ rowdiv, const float* __restrict__ mix,
    const float* __restrict__ betas, const float* __restrict__ bias,
    bf16* __restrict__ Th, bf16* __restrict__ Tl, int tmode)
{
    extern __shared__ char smemc[];
    tc_gemm_body(Ahg,Alg,Bhg,Blg,K,lda,ldb,ldc,sAb,sAh,sBb,sBh,sCb,sCh,mode,
                 C,O1h,O1l,O2h,O2l,rowdiv,mix,betas,bias,Th,Tl,tmode,0,0,
                 blockIdx.x, blockIdx.y, blockIdx.z, smemc);
}

// ================= merged projections: Q (0-255) | K (256-511) | V (512-767) =================
__global__ void __launch_bounds__(512,1) fused_proj(
    const bf16* __restrict__ HSh, const bf16* __restrict__ HSl,
    const bf16* __restrict__ WqTh, const bf16* __restrict__ WqTl,
    const bf16* __restrict__ WkTh, const bf16* __restrict__ WkTl,
    const bf16* __restrict__ WvTh, const bf16* __restrict__ WvTl,
    bf16* __restrict__ Qh, bf16* __restrict__ Ql,
    bf16* __restrict__ SQh, bf16* __restrict__ SQl,
    bf16* __restrict__ Kh, bf16* __restrict__ Kl,
    bf16* __restrict__ SKh, bf16* __restrict__ SKl,
    bf16* __restrict__ SKTh, bf16* __restrict__ SKTl,
    float* __restrict__ Vf, bf16* __restrict__ VTh, bf16* __restrict__ VTl,
    const float* __restrict__ zv, float* __restrict__ Zq, float* __restrict__ Zk)
{
    extern __shared__ char smc[];
    int bid = blockIdx.x;
    int which = bid >> 8, n = bid & 255;
    int bx = n & 3, by = n >> 2;
    if (which == 0){
        tc_gemm_body(HSh,HSl,WqTh,WqTl, E_,E_,E_,E_, 0,0,0,0,0,0, EP_SIGQK,
            0, Qh,Ql, SQh,SQl, 0,0,0,0, 0,0,0, zv, Zq, bx,by,0, smc);
    } else if (which == 1){
        tc_gemm_body(HSh,HSl,WkTh,WkTl, E_,E_,E_,E_, 0,0,0,0,0,0, EP_SIGQK,
            0, Kh,Kl, SKh,SKl, 0,0,0,0, SKTh,SKTl,1, zv, Zk, bx,by,0, smc);
    } else {
        tc_gemm_body(HSh,HSl,WvTh,WvTl, E_,E_,E_,E_, 0,0,0,0,0,0, EP_F32,
            Vf, 0,0,0,0, 0,0,0,0, VTh,VTl,1, 0,0, bx,by,0, smc);
    }
}

// ================= fused flash attention body (512 threads, validated in merged context) =================
#define STG_BYTES 65536
#define FA_P     131072
#define FA_STAT  196608
#define FA_SMEM  (196608 + 3072)

__device__ void fa_body(
    const bf16* __restrict__ Qhg, const bf16* __restrict__ Qlg,
    const bf16* __restrict__ Khg, const bf16* __restrict__ Klg,
    const bf16* __restrict__ VThg, const bf16* __restrict__ VTlg,
    float* __restrict__ AO, int bid, char* smc)
{
    uint32_t sb = smem_u32(smc);
    int z  = (bid>>1)&15;
    int mi = (bid&1) ? (bid>>5) : 15-(bid>>5);
    int bb = z / H_, hh = z % H_;
    int m0 = mi*128;

    int tid = threadIdx.x, wid = tid>>5, lid = tid&31;
    int wm = wid&3, wn = wid>>2;
    int tg = lid>>2, t4 = lid&3;

    const bf16* Qh_ = Qhg + (size_t)bb*S_*E_ + hh*D_;
    const bf16* Ql_ = Qlg + (size_t)bb*S_*E_ + hh*D_;
    const bf16* Kh_ = Khg + (size_t)bb*S_*E_ + hh*D_;
    const bf16* Kl_ = Klg + (size_t)bb*S_*E_ + hh*D_;
    const bf16* VTh_ = VThg + (size_t)z*D_*S_;
    const bf16* VTl_ = VTlg + (size_t)z*D_*S_;

    float* m_s = (float*)(smc + FA_STAT);
    float* l_s = (float*)(smc + FA_STAT + 512);
    float* red = (float*)(smc + FA_STAT + 1024);

    if (tid < 128){ m_s[tid] = -1e30f; l_s[tid] = 0.f; }

    float acc_o[2][8][4];
    #pragma unroll
    for (int a=0;a<2;a++)
        #pragma unroll
        for (int b=0;b<8;b++)
            #pragma unroll
            for (int r=0;r<4;r++) acc_o[a][b][r]=0.f;
    __syncthreads();

    int row_l = tid>>3, v_l = tid&7;

    for (int j=0; j<=mi; j++){
        int jb = j*128;
        float acc_s[2][4][4];
        #pragma unroll
        for (int a=0;a<2;a++)
            #pragma unroll
            for (int b=0;b<4;b++)
                #pragma unroll
                for (int r=0;r<4;r++) acc_s[a][b][r]=0.f;

        auto issueS = [&](int c, int s){
            int stg = s*STG_BYTES, kc0 = c*64;
            #pragma unroll
            for (int i=0;i<2;i++){
                int row = row_l + 64*i;
                uint32_t o = SWZ(row*128 + v_l*16);
                CP_ASYNC(sb+stg+o,       Qh_ + (size_t)(m0+row)*E_ + kc0 + v_l*8);
                CP_ASYNC(sb+stg+16384+o, Ql_ + (size_t)(m0+row)*E_ + kc0 + v_l*8);
                CP_ASYNC(sb+stg+32768+o, Kh_ + (size_t)(jb+row)*E_ + kc0 + v_l*8);
                CP_ASYNC(sb+stg+49152+o, Kl_ + (size_t)(jb+row)*E_ + kc0 + v_l*8);
            }
            CP_COMMIT();
        };
        auto issueV = [&](int kc, int s){
            int stg = s*STG_BYTES;
            #pragma unroll
            for (int i=0;i<4;i++){
                int row = row_l + 64*i;
                uint32_t o = SWZ(row*128 + v_l*16);
                CP_ASYNC(sb+stg+o,       VTh_ + (size_t)row*S_ + jb + kc*64 + v_l*8);
                CP_ASYNC(sb+stg+32768+o, VTl_ + (size_t)row*S_ + jb + kc*64 + v_l*8);
            }
            CP_COMMIT();
        };

        issueS(0,0); issueS(1,1);
        for (int c=0;c<4;c++){
            if (c<3) { CP_WAIT(1); } else { CP_WAIT(0); }
            __syncthreads();
            int stg = (c&1)*STG_BYTES;
            #pragma unroll
            for (int ks=0; ks<4; ks++){
                uint32_t bh[4][2], bl[4][2];
                #pragma unroll
                for (int g=0; g<2; g++){
                    int row = wn*32 + g*16 + (lid&7) + ((lid>>4)&1)*8;
                    int cb2 = ks*32 + ((lid>>3)&1)*16;
                    uint32_t off = SWZ(row*128 + cb2);
                    uint32_t r0,r1,r2,r3;
                    ldm_x4(r0,r1,r2,r3, sb+stg+32768+off);
                    bh[2*g][0]=r0; bh[2*g][1]=r1; bh[2*g+1][0]=r2; bh[2*g+1][1]=r3;
                    ldm_x4(r0,r1,r2,r3, sb+stg+49152+off);
                    bl[2*g][0]=r0; bl[2*g][1]=r1; bl[2*g+1][0]=r2; bl[2*g+1][1]=r3;
                }
                #pragma unroll
                for (int mt=0; mt<2; mt++){
                    int row = wm*32 + mt*16 + (lid&15);
                    uint32_t colb = ks*32 + ((lid>>4)&1)*16;
                    uint32_t off = SWZ(row*128 + colb);
                    uint32_t ah[4], al[4];
                    ldm_x4(ah[0],ah[1],ah[2],ah[3], sb+stg+off);
                    ldm_x4(al[0],al[1],al[2],al[3], sb+stg+16384+off);
                    #pragma unroll
                    for (int nt=0;nt<4;nt++){
                        mma16816(acc_s[mt][nt], ah, bh[nt]);
                        mma16816(acc_s[mt][nt], ah, bl[nt]);
                        mma16816(acc_s[mt][nt], al, bh[nt]);
                    }
                }
            }
            __syncthreads();
            if (c==0) issueS(2,0);
            else if (c==1) issueS(3,1);
        }

        issueV(0,0); issueV(1,1);

        if (j == mi){
            #pragma unroll
            for (int mt=0; mt<2; mt++)
                #pragma unroll
                for (int nt=0; nt<4; nt++)
                    #pragma unroll
                    for (int r=0;r<4;r++){
                        int srow = wm*32 + mt*16 + tg + ((r>>1)&1)*8;
                        int scol = wn*32 + nt*8 + t4*2 + (r&1);
                        if (scol > srow) acc_s[mt][nt][r] = -1e30f;
                    }
        }
        float rmax[2][2];
        #pragma unroll
        for (int mt=0; mt<2; mt++)
            #pragma unroll
            for (int hf=0; hf<2; hf++){
                float m = -1e30f;
                #pragma unroll
                for (int nt=0; nt<4; nt++){
                    m = fmaxf(m, acc_s[mt][nt][hf*2+0]);
                    m = fmaxf(m, acc_s[mt][nt][hf*2+1]);
                }
                m = fmaxf(m, __shfl_xor_sync(0xffffffffu, m, 1));
                m = fmaxf(m, __shfl_xor_sync(0xffffffffu, m, 2));
                rmax[mt][hf] = m;
            }
        if (t4 == 0){
            #pragma unroll
            for (int mt=0; mt<2; mt++)
                #pragma unroll
                for (int hf=0; hf<2; hf++)
                    red[wn*128 + wm*32 + mt*16 + tg + hf*8] = rmax[mt][hf];
        }
        __syncthreads();

        float mnew[2][2], alpha[2][2], rsum[2][2];
        #pragma unroll
        for (int mt=0; mt<2; mt++)
            #pragma unroll
            for (int hf=0; hf<2; hf++){
                int row = wm*32 + mt*16 + tg + hf*8;
                float rm = fmaxf(fmaxf(red[row], red[128+row]), fmaxf(red[256+row], red[384+row]));
                float mo = m_s[row];
                float mn = fmaxf(mo, rm);
                mnew[mt][hf] = mn;
                alpha[mt][hf] = __expf(mo - mn);
                rsum[mt][hf] = 0.f;
            }
        #pragma unroll
        for (int mt=0; mt<2; mt++)
            #pragma unroll
            for (int nt=0; nt<4; nt++)
                #pragma unroll
                for (int r=0;r<4;r++){
                    int hf = r>>1;
                    float p = __expf(acc_s[mt][nt][r] - mnew[mt][hf]);
                    acc_s[mt][nt][r] = p;
                    rsum[mt][hf] += p;
                }
        #pragma unroll
        for (int mt=0; mt<2; mt++)
            #pragma unroll
            for (int hf=0; hf<2; hf++){
                rsum[mt][hf] += __shfl_xor_sync(0xffffffffu, rsum[mt][hf], 1);
                rsum[mt][hf] += __shfl_xor_sync(0xffffffffu, rsum[mt][hf], 2);
            }
        __syncthreads();
        if (t4 == 0){
            #pragma unroll
            for (int mt=0; mt<2; mt++)
                #pragma unroll
                for (int hf=0; hf<2; hf++)
                    red[wn*128 + wm*32 + mt*16 + tg + hf*8] = rsum[mt][hf];
        }
        #pragma unroll
        for (int mt=0; mt<2; mt++)
            #pragma unroll
            for (int nt=0; nt<4; nt++)
                #pragma unroll
                for (int rp=0; rp<2; rp++){
                    int row = wm*32 + mt*16 + tg + rp*8;
                    int col = wn*32 + nt*8 + t4*2;
                    float p0 = acc_s[mt][nt][rp*2+0];
                    float p1 = acc_s[mt][nt][rp*2+1];
                    bf16 h0 = __float2bfloat16(p0);
                    bf16 h1 = __float2bfloat16(p1);
                    bf16 l0 = __float2bfloat16(p0 - __bfloat162float(h0));
                    bf16 l1 = __float2bfloat16(p1 - __bfloat162float(h1));
                    uint32_t o = (uint32_t)(col>>6)*16384u + SWZ((uint32_t)row*128 + (col&63)*2);
                    *(__nv_bfloat162*)(smc + FA_P + o)         = __nv_bfloat162(h0, h1);
                    *(__nv_bfloat162*)(smc + FA_P + 32768 + o) = __nv_bfloat162(l0, l1);
                }
        #pragma unroll
        for (int mt=0; mt<2; mt++)
            #pragma unroll
            for (int nt=0; nt<8; nt++)
                #pragma unroll
                for (int r=0;r<4;r++)
                    acc_o[mt][nt][r] *= alpha[mt][r>>1];
        __syncthreads();
        if (wn == 0 && t4 == 0){
            #pragma unroll
            for (int mt=0; mt<2; mt++)
                #pragma unroll
                for (int hf=0; hf<2; hf++){
                    int row = wm*32 + mt*16 + tg + hf*8;
                    float rs = red[row] + red[128+row] + red[256+row] + red[384+row];
                    l_s[row] = l_s[row]*alpha[mt][hf] + rs;
                    m_s[row] = mnew[mt][hf];
                }
        }

        for (int kc=0; kc<2; kc++){
            if (kc==0) { CP_WAIT(1); } else { CP_WAIT(0); }
            __syncthreads();
            int stg = kc*STG_BYTES;
            uint32_t pb = FA_P + kc*16384;
            #pragma unroll
            for (int ks=0; ks<4; ks++){
                uint32_t bh[8][2], bl[8][2];
                #pragma unroll
                for (int g=0; g<4; g++){
                    int row = wn*64 + g*16 + (lid&7) + ((lid>>4)&1)*8;
                    int cb2 = ks*32 + ((lid>>3)&1)*16;
                    uint32_t off = SWZ(row*128 + cb2);
                    uint32_t r0,r1,r2,r3;
                    ldm_x4(r0,r1,r2,r3, sb+stg+off);
                    bh[2*g][0]=r0; bh[2*g][1]=r1; bh[2*g+1][0]=r2; bh[2*g+1][1]=r3;
                    ldm_x4(r0,r1,r2,r3, sb+stg+32768+off);
                    bl[2*g][0]=r0; bl[2*g][1]=r1; bl[2*g+1][0]=r2; bl[2*g+1][1]=r3;
                }
                #pragma unroll
                for (int mt=0; mt<2; mt++){
                    int row = wm*32 + mt*16 + (lid&15);
                    uint32_t colb = ks*32 + ((lid>>4)&1)*16;
                    uint32_t off = SWZ(row*128 + colb);
                    uint32_t ah[4], al[4];
                    ldm_x4(ah[0],ah[1],ah[2],ah[3], sb+pb+off);
                    ldm_x4(al[0],al[1],al[2],al[3], sb+pb+32768+off);
                    #pragma unroll
                    for (int nt=0;nt<8;nt++){
                        mma16816(acc_o[mt][nt], ah, bh[nt]);
                        mma16816(acc_o[mt][nt], ah, bl[nt]);
                        mma16816(acc_o[mt][nt], al, bh[nt]);
                    }
                }
            }
            __syncthreads();
        }
    }

    __syncthreads();
    float* AOp = AO + (size_t)bb*S_*E_ + hh*D_;
    #pragma unroll
    for (int mt=0; mt<2; mt++)
        #pragma unroll
        for (int hf=0; hf<2; hf++){
            int row = wm*32 + mt*16 + tg + hf*8;
            float linv = 1.f/l_s[row];
            #pragma unroll
            for (int nt=0; nt<8; nt++){
                int col = wn*64 + nt*8 + t4*2;
                float2 v;
                v.x = acc_o[mt][nt][hf*2+0]*linv;
                v.y = acc_o[mt][nt][hf*2+1]*linv;
                *(float2*)(AOp + (size_t)(m0+row)*E_ + col) = v;
            }
        }
}

// ================= merged launch A: fa (0-255) | DELTA (256-511) | znew (512-1023) =================
__global__ void __launch_bounds__(512,1) fused_attn_delta(
    const bf16* __restrict__ Qh, const bf16* __restrict__ Ql,
    const bf16* __restrict__ Kh, const bf16* __restrict__ Kl,
    const bf16* __restrict__ VTh, const bf16* __restrict__ VTl,
    float* __restrict__ AO,
    const bf16* __restrict__ SKh, const bf16* __restrict__ SKl,
    const bf16* __restrict__ memTh, const bf16* __restrict__ memTl,
    const float* __restrict__ Zk, const float* __restrict__ Vf,
    bf16* __restrict__ UTh, bf16* __restrict__ UTl,
    const bf16* __restrict__ SKTh, const bf16* __restrict__ SKTl,
    const float* __restrict__ zvec, float* __restrict__ zout)
{
    extern __shared__ char smc[];
    int bid = blockIdx.x;
    if (bid < 256){
        fa_body(Qh,Ql,Kh,Kl,VTh,VTl, AO, bid, smc);
    } else if (bid < 512){
        int n = bid - 256;
        tc_gemm_body(SKh,SKl,memTh,memTl, D_, E_,D_,E_,
            (long)S_*E_, D_, 0, (long)D_*D_, (long)S_*E_, (long)D_,
            EP_DELTA, 0, 0,0,0,0, Zk, Vf, 0, 0, UTh,UTl,2, 0,0,
            0, n & 15, n >> 4, smc);
    } else {
        if (threadIdx.x < 256){
            int w = threadIdx.x >> 5, lane = threadIdx.x & 31;
            int r = (bid - 512)*8 + w;
            int z = r / D_, d = r % D_;
            const bf16* ph = SKTh + (size_t)r*S_;
            const bf16* pl = SKTl + (size_t)r*S_;
            float acc = 0.f;
            #pragma unroll 4
            for (int s=lane; s<S_; s+=32)
                acc += __bfloat162float(ph[s]) + __bfloat162float(pl[s]);
            #pragma unroll
            for (int o=16;o;o>>=1) acc += __shfl_xor_sync(0xffffffffu, acc, o);
            if (lane==0) zout[r] = zvec[(z%H_)*D_ + d] + acc;
        }
    }
}

// ================= merged launch B: AMEM (0-255) | memupd (256-287) =================
__global__ void __launch_bounds__(512,1) fused_amem_memupd(
    const bf16* __restrict__ SQh, const bf16* __restrict__ SQl,
    const bf16* __restrict__ memTh, const bf16* __restrict__ memTl,
    const float* __restrict__ Zq, const float* __restrict__ AO,
    const float* __restrict__ betas,
    bf16* __restrict__ ABh, bf16* __restrict__ ABl,
    const bf16* __restrict__ SKTh, const bf16* __restrict__ SKTl,
    const bf16* __restrict__ UTh, const bf16* __restrict__ UTl,
    const float* __restrict__ memp, float* __restrict__ memout)
{
    extern __shared__ char smc[];
    int bid = blockIdx.x;
    if (bid < 256){
        int n = bid;
        tc_gemm_body(SQh,SQl,memTh,memTl, D_, E_,D_,E_,
            (long)S_*E_, D_, 0, (long)D_*D_, (long)S_*E_, (long)D_,
            EP_AMEM, 0, ABh,ABl, 0,0, Zq, AO, betas, 0, 0,0,0, 0,0,
            0, n & 15, n >> 4, smc);
    } else {
        int n = bid - 256;
        tc_gemm_body(SKTh,SKTl,UTh,UTl, S_, S_,S_,D_,
            (long)H_*D_*S_, (long)D_*S_, (long)H_*D_*S_, (long)D_*S_, (long)H_*D_*D_, (long)D_*D_,
            EP_MEMUPD, memout, 0,0,0,0, 0, memp, 0, 0, 0,0,0, 0,0,
            0, n & 1, n >> 1, smc);
    }
}

// ================= merged prep: split (0-8191) | transW x4 (8192-12287) | transMem (12288-12543) =================
__global__ void __launch_bounds__(256) prep_kernel(
    const float* __restrict__ hs,
    const float* __restrict__ Wq, const float* __restrict__ Wk,
    const float* __restrict__ Wv, const float* __restrict__ Wo,
    const float* __restrict__ memp,
    bf16* __restrict__ HSh, bf16* __restrict__ HSl,
    bf16* __restrict__ WqTh, bf16* __restrict__ WqTl,
    bf16* __restrict__ WkTh, bf16* __restrict__ WkTl,
    bf16* __restrict__ WvTh, bf16* __restrict__ WvTl,
    bf16* __restrict__ WoTh, bf16* __restrict__ WoTl,
    bf16* __restrict__ memTh, bf16* __restrict__ memTl)
{
    __shared__ float t[32][33];
    int bid = blockIdx.x, tid = threadIdx.x;
    if (bid < 8192){
        int i = bid*256 + tid;
        float4 v = ((const float4*)hs)[i];
        size_t o = (size_t)i*4;
        store_split(HSh, HSl, o+0, v.x); store_split(HSh, HSl, o+1, v.y);
        store_split(HSh, HSl, o+2, v.z); store_split(HSh, HSl, o+3, v.w);
    } else if (bid < 12288){
        int n = bid - 8192;
        int w = n >> 10, inner = n & 1023;
        const float* W = (w==0) ? Wq : (w==1) ? Wk : (w==2) ? Wv : Wo;
        bf16* Th = (w==0) ? WqTh : (w==1) ? WkTh : (w==2) ? WvTh : WoTh;
        bf16* Tl = (w==0) ? WqTl : (w==1) ? WkTl : (w==2) ? WvTl : WoTl;
        int k0 = (inner & 31)*32, n0 = (inner >> 5)*32;
        int tx = tid & 31, ty = tid >> 5;
        #pragma unroll
        for (int i=0;i<32;i+=8) t[ty+i][tx] = W[(size_t)(k0+ty+i)*E_ + n0+tx];
        __syncthreads();
        #pragma unroll
        for (int i=0;i<32;i+=8){
            size_t o = (size_t)(n0+ty+i)*E_ + k0+tx;
            store_split(Th, Tl, o, t[tx][ty+i]);
        }
    } else {
        int n = bid - 12288;
        int h = n >> 6;
        int d0 = ((n >> 3) & 7)*32, e0 = (n & 7)*32;
        int tx = tid & 31, ty = tid >> 5;
        #pragma unroll
        for (int i=0;i<32;i+=8) t[ty+i][tx] = memp[(size_t)h*D_*D_ + (size_t)(d0+ty+i)*D_ + e0+tx];
        __syncthreads();
        #pragma unroll
        for (int i=0;i<32;i+=8){
            size_t o = (size_t)h*D_*D_ + (size_t)(e0+ty+i)*D_ + d0+tx;
            store_split(memTh, memTl, o, t[tx][ty+i]);
        }
    }
}

// ================= launch =================
extern "C" void kernel_launch(void* const* d_in, const int* in_sizes, int n_in,
                              void* d_out, int out_size)
{
    const float* hs    = (const float*)d_in[0];
    const float* Wq    = (const float*)d_in[1];
    const float* Wk    = (const float*)d_in[2];
    const float* Wv    = (const float*)d_in[3];
    const float* Wo    = (const float*)d_in[4];
    const float* bo    = (const float*)d_in[5];
    const float* betas = (const float*)d_in[6];
    const float* memp  = (const float*)d_in[7];
    const float* zv    = (const float*)d_in[8];
    float* out = (float*)d_out;

    cudaFuncSetAttribute(tc_gemm, cudaFuncAttributeMaxDynamicSharedMemorySize, G5_SMEM);
    cudaFuncSetAttribute(fused_proj, cudaFuncAttributeMaxDynamicSharedMemorySize, G5_SMEM);
    cudaFuncSetAttribute(fused_attn_delta, cudaFuncAttributeMaxDynamicSharedMemorySize, FA_SMEM);
    cudaFuncSetAttribute(fused_amem_memupd, cudaFuncAttributeMaxDynamicSharedMemorySize, G5_SMEM);

#define GS(var, sym) cudaGetSymbolAddress((void**)&var, sym)
    bf16 *HSh,*HSl,*WqTh,*WqTl,*WkTh,*WkTl,*WvTh,*WvTl,*WoTh,*WoTl,*memTh,*memTl;
    bf16 *Qh,*Ql,*Kh,*Kl,*SQh,*SQl,*SKh,*SKl,*ABh,*ABl,*VTh,*VTl,*UTh,*UTl,*SKTh,*SKTl;
    float *Vf,*AO,*Zq,*Zk;
    GS(HSh,g_HSh); GS(HSl,g_HSl);
    GS(WqTh,g_WqTh); GS(WqTl,g_WqTl); GS(WkTh,g_WkTh); GS(WkTl,g_WkTl);
    GS(WvTh,g_WvTh); GS(WvTl,g_WvTl); GS(WoTh,g_WoTh); GS(WoTl,g_WoTl);
    GS(memTh,g_memTh); GS(memTl,g_memTl);
    GS(Qh,g_Qh); GS(Ql,g_Ql); GS(Kh,g_Kh); GS(Kl,g_Kl);
    GS(SQh,g_SQh); GS(SQl,g_SQl); GS(SKh,g_SKh); GS(SKl,g_SKl);
    GS(ABh,g_ABh); GS(ABl,g_ABl);
    GS(VTh,g_VTh); GS(VTl,g_VTl); GS(UTh,g_UTh); GS(UTl,g_UTl);
    GS(SKTh,g_SKTh); GS(SKTl,g_SKTl);
    GS(Vf,g_Vf); GS(AO,g_AO);
    GS(Zq,g_Zq); GS(Zk,g_Zk);

    const long OUT_MEM = (long)B_*S_*E_;
    const long OUT_Z   = OUT_MEM + (long)B_*H_*D_*D_;
    dim3 t256(256), t512(512);

    // merged prep: split hidden states + transpose/split all weights + mem
    prep_kernel<<<12544, t256>>>(hs, Wq, Wk, Wv, Wo, memp,
        HSh, HSl, WqTh, WqTl, WkTh, WkTl, WvTh, WvTl, WoTh, WoTl, memTh, memTl);

    // merged projections Q|K|V with fused sigma rowdots and transposed outputs
    fused_proj<<<768, t512, G5_SMEM>>>(HSh,HSl, WqTh,WqTl, WkTh,WkTl, WvTh,WvTl,
        Qh,Ql, SQh,SQl, Kh,Kl, SKh,SKl, SKTh,SKTl, Vf, VTh,VTl, zv, Zq, Zk);

    // merged: flash attention ∥ U = V - delta ∥ z_new
    fused_attn_delta<<<1024, t512, FA_SMEM>>>(
        Qh,Ql,Kh,Kl,VTh,VTl, AO,
        SKh,SKl, memTh,memTl, Zk, Vf, UTh,UTl,
        SKTh,SKTl, zv, out+OUT_Z);

    // merged: A_mem+gate ∥ mem_new
    fused_amem_memupd<<<288, t512, G5_SMEM>>>(
        SQh,SQl, memTh,memTl, Zq, AO, betas, ABh,ABl,
        SKTh,SKTl, UTh,UTl, memp, out+OUT_MEM);

    // out projection + bias
    tc_gemm<<<dim3(4,64,1), t512, G5_SMEM>>>(ABh,ABl,WoTh,WoTl, E_,E_,E_,E_,
        0,0,0,0,0,0, EP_BIAS, out, 0,0,0,0, 0,0,0, bo, 0,0,0);
}

// round 15
// speedup vs baseline: 1.2681x; 1.0549x over previous
#include <cuda_runtime.h>
#include <cuda_bf16.h>
#include <cstdint>
#include <math.h>

#define B_ 4
#define S_ 2048
#define E_ 1024
#define H_ 4
#define D_ 256
#define BH_ 16
#define MSZ (B_*S_*E_)

typedef __nv_bfloat16 bf16;

// ================= device scratch =================
__device__ bf16 g_HSh[MSZ], g_HSl[MSZ];
__device__ bf16 g_WqTh[E_*E_], g_WqTl[E_*E_];
__device__ bf16 g_WkTh[E_*E_], g_WkTl[E_*E_];
__device__ bf16 g_WvTh[E_*E_], g_WvTl[E_*E_];
__device__ bf16 g_WoTh[E_*E_], g_WoTl[E_*E_];
__device__ bf16 g_memTh[H_*D_*D_], g_memTl[H_*D_*D_];
__device__ bf16 g_Qh[MSZ], g_Ql[MSZ], g_Kh[MSZ], g_Kl[MSZ];
__device__ bf16 g_SQh[MSZ], g_SQl[MSZ], g_SKh[MSZ], g_SKl[MSZ];
__device__ bf16 g_ABh[MSZ], g_ABl[MSZ];
__device__ bf16 g_VTh[MSZ], g_VTl[MSZ];
__device__ bf16 g_UTh[MSZ], g_UTl[MSZ];
__device__ bf16 g_SKTh[MSZ], g_SKTl[MSZ];
__device__ float g_Vf[MSZ], g_AO[MSZ];
__device__ float g_Zq[BH_*S_], g_Zk[BH_*S_];
__device__ int g_faFlag[BH_*16];
__device__ int g_dCnt[BH_];

// ================= helpers =================
__device__ __forceinline__ uint32_t smem_u32(const void* p){
    uint32_t a;
    asm("{ .reg .u64 t; cvta.to.shared.u64 t, %1; cvt.u32.u64 %0, t; }" : "=r"(a) : "l"(p));
    return a;
}
#define SWZ(o) ((o) ^ (((o) >> 3) & 0x70))
#define BUFP 261

#define CP_ASYNC(daddr, gptr) \
    asm volatile("cp.async.cg.shared.global [%0], [%1], 16;" :: "r"(daddr), "l"(gptr) : "memory")
#define CP_COMMIT() asm volatile("cp.async.commit_group;" ::: "memory")
#define CP_WAIT(n)  asm volatile("cp.async.wait_group %0;" :: "n"(n) : "memory")

__device__ __forceinline__ void ldm_x4(uint32_t& r0, uint32_t& r1, uint32_t& r2, uint32_t& r3, uint32_t a){
    asm volatile("ldmatrix.sync.aligned.m8n8.x4.shared.b16 {%0,%1,%2,%3}, [%4];"
        : "=r"(r0), "=r"(r1), "=r"(r2), "=r"(r3) : "r"(a));
}
__device__ __forceinline__ void mma16816(float* c, const uint32_t* a, const uint32_t* b){
    asm volatile("mma.sync.aligned.m16n8k16.row.col.f32.bf16.bf16.f32 "
        "{%0,%1,%2,%3}, {%4,%5,%6,%7}, {%8,%9}, {%0,%1,%2,%3};"
        : "+f"(c[0]), "+f"(c[1]), "+f"(c[2]), "+f"(c[3])
        : "r"(a[0]), "r"(a[1]), "r"(a[2]), "r"(a[3]), "r"(b[0]), "r"(b[1]));
}

__device__ __forceinline__ void store_split(bf16* ph, bf16* pl, size_t i, float v){
    bf16 h = __float2bfloat16(v);
    ph[i] = h;
    pl[i] = __float2bfloat16(v - __bfloat162float(h));
}

enum { EP_F32=0, EP_SIGQK=1, EP_BIAS=2, EP_AMEM=3, EP_DELTA=4, EP_MEMUPD=5 };

// ================= 512-thread HMMA GEMM body =================
#define G5_STG 98304
#define G5_SMEM (2*G5_STG)

__device__ void tc_gemm_body(
    const bf16* __restrict__ Ahg, const bf16* __restrict__ Alg,
    const bf16* __restrict__ Bhg, const bf16* __restrict__ Blg,
    int K, int lda, int ldb, int ldc,
    long sAb, long sAh, long sBb, long sBh, long sCb, long sCh,
    int mode,
    float* __restrict__ C, bf16* __restrict__ O1h, bf16* __restrict__ O1l,
    bf16* __restrict__ O2h, bf16* __restrict__ O2l,
    const float* __restrict__ rowdiv, const float* __restrict__ mix,
    const float* __restrict__ betas, const float* __restrict__ bias,
    bf16* __restrict__ Th, bf16* __restrict__ Tl, int tmode,
    const float* __restrict__ zdotv, float* __restrict__ Zout,
    int* wflag, int wcnt, int wpos, int* doneflag,
    int bx, int by, int bz, char* smemc)
{
    int z = bz, bb = z / H_, hh = z % H_;
    int m0 = by*128, n0 = bx*256;
    int tid = threadIdx.x, wid = tid >> 5, lid = tid & 31;

    // wait-at-start (memupd: B operand produced by peer CTAs)
    if (wflag && wpos == 1){
        if (tid == 0){ while (atomicAdd(wflag, 0) < wcnt) {} }
        __syncthreads();
        __threadfence();
    }

    const bf16* Ah = Ahg + (size_t)bb*sAb + (size_t)hh*sAh;
    const bf16* Al = Alg + (size_t)bb*sAb + (size_t)hh*sAh;
    const bf16* Bh = Bhg + (size_t)bb*sBb + (size_t)hh*sBh;
    const bf16* Bl = Blg + (size_t)bb*sBb + (size_t)hh*sBh;
    size_t coff = (size_t)bb*sCb + (size_t)hh*sCh;

    uint32_t sb = smem_u32(smemc);
    int wm = wid & 1, wn = wid >> 1;
    int mbase = wm*64, nbase = wn*32;

    float acc[4][4][4];
    #pragma unroll
    for (int i=0;i<4;i++)
        #pragma unroll
        for (int j=0;j<4;j++)
            #pragma unroll
            for (int r=0;r<4;r++) acc[i][j][r]=0.f;

    int nch = K >> 6;
    int row_l = tid >> 3, v_l = tid & 7;

    auto issue = [&](int ci, int s){
        int stg = s*G5_STG, kc0 = ci << 6;
        #pragma unroll
        for (int i=0;i<2;i++){
            int row = row_l + 64*i;
            uint32_t o = SWZ(row*128 + v_l*16);
            CP_ASYNC(sb+stg+o,       Ah + (size_t)(m0+row)*lda + kc0 + v_l*8);
            CP_ASYNC(sb+stg+16384+o, Al + (size_t)(m0+row)*lda + kc0 + v_l*8);
        }
        #pragma unroll
        for (int i=0;i<4;i++){
            int row = row_l + 64*i;
            uint32_t o = SWZ(row*128 + v_l*16);
            CP_ASYNC(sb+stg+32768+o, Bh + (size_t)(n0+row)*ldb + kc0 + v_l*8);
            CP_ASYNC(sb+stg+65536+o, Bl + (size_t)(n0+row)*ldb + kc0 + v_l*8);
        }
        CP_COMMIT();
    };

    issue(0, 0);
    if (nch > 1) issue(1, 1);

    for (int ci=0; ci<nch; ci++){
        if (ci+1 < nch) { CP_WAIT(1); } else { CP_WAIT(0); }
        __syncthreads();
        int stg = (ci&1)*G5_STG;

        #pragma unroll
        for (int ks=0; ks<4; ks++){
            int colb = ks*32 + ((lid>>4)&1)*16;
            uint32_t ah[4][4], al[4][4];
            #pragma unroll
            for (int mt=0; mt<4; mt++){
                int row = mbase + mt*16 + (lid & 15);
                uint32_t off = SWZ(row*128 + colb);
                ldm_x4(ah[mt][0],ah[mt][1],ah[mt][2],ah[mt][3], sb+stg+off);
                ldm_x4(al[mt][0],al[mt][1],al[mt][2],al[mt][3], sb+stg+16384+off);
            }
            uint32_t bh[4][2], bl[4][2];
            #pragma unroll
            for (int g=0; g<2; g++){
                int row = nbase + g*16 + (lid & 7) + ((lid>>4)&1)*8;
                int cb2 = ks*32 + ((lid>>3)&1)*16;
                uint32_t off = SWZ(row*128 + cb2);
                uint32_t r0,r1,r2,r3;
                ldm_x4(r0,r1,r2,r3, sb+stg+32768+off);
                bh[2*g][0]=r0; bh[2*g][1]=r1; bh[2*g+1][0]=r2; bh[2*g+1][1]=r3;
                ldm_x4(r0,r1,r2,r3, sb+stg+65536+off);
                bl[2*g][0]=r0; bl[2*g][1]=r1; bl[2*g+1][0]=r2; bl[2*g+1][1]=r3;
            }
            #pragma unroll
            for (int mt=0; mt<4; mt++)
                #pragma unroll
                for (int nt=0; nt<4; nt++){
                    mma16816(acc[mt][nt], ah[mt], bh[nt]);
                    mma16816(acc[mt][nt], ah[mt], bl[nt]);
                    mma16816(acc[mt][nt], al[mt], bh[nt]);
                }
        }
        __syncthreads();
        if (ci+2 < nch) issue(ci+2, ci&1);
    }

    float* buf = (float*)smemc;              // 128 x BUFP
    int tg = lid >> 2, t4 = lid & 3;
    #pragma unroll
    for (int mt=0; mt<4; mt++)
        #pragma unroll
        for (int nt=0; nt<4; nt++)
            #pragma unroll
            for (int r=0; r<4; r++){
                int m = mbase + mt*16 + tg + (r>=2 ? 8 : 0);
                int c = nbase + nt*8 + t4*2 + (r&1);
                buf[m*BUFP + c] = acc[mt][nt][r];
            }
    __syncthreads();

    // wait-pre-epilogue (amem: mix=AO produced by fa peer CTAs)
    if (wflag && wpos == 2){
        if (tid == 0){ while (atomicAdd(wflag, 0) < wcnt) {} }
        __syncthreads();
        __threadfence();
    }

    float gate = 0.f;
    if (mode == EP_AMEM) gate = 1.f/(1.f + __expf(-betas[hh]));

    #pragma unroll 4
    for (int e=0; e<64; e++){
        int flat = e*512 + tid;
        int row = flat >> 8, col = flat & 255;
        float v = buf[row*BUFP + col];
        int m = m0 + row, c = n0 + col;
        size_t idx = coff + (size_t)m*ldc + c;
        if (mode == EP_F32) {
            if (C) C[idx] = v;
        } else if (mode == EP_SIGQK) {
            store_split(O1h, O1l, idx, v);
            float sg = v > 0.f ? v + 1.f : __expf(v);
            store_split(O2h, O2l, idx, sg);
            buf[row*BUFP + col] = sg;
        } else if (mode == EP_BIAS) {
            C[idx] = v + bias[c];
        } else if (mode == EP_AMEM) {
            float rinv = 1.f/(rowdiv[(size_t)z*S_ + m] + 1e-6f);
            float val = gate*(v*rinv) + (1.f-gate)*mix[idx];
            store_split(O1h, O1l, idx, val);
        } else if (mode == EP_DELTA) {
            float rinv = 1.f/(rowdiv[(size_t)z*S_ + m] + 1e-6f);
            float u = mix[idx] - v*rinv;
            if (C) C[idx] = u;
            buf[row*BUFP + col] = u;
        } else {
            float mv = mix[(size_t)hh*D_*D_ + (size_t)m*D_ + c];
            C[idx] = mv + v;
        }
    }

    // ---- fused rowdot for sigma projections ----
    if (mode == EP_SIGQK && Zout){
        __syncthreads();
        int bp = m0 >> 11, hp = n0 >> 8;
        int s0 = m0 & 2047;
        float* Zp = Zout + ((size_t)(bp*H_ + hp))*S_ + s0;
        const float* zvp = zdotv + hp*D_;
        int row = tid >> 2, q = tid & 3;
        float acc2 = 0.f;
        #pragma unroll 16
        for (int c = q*64; c < q*64 + 64; c++)
            acc2 += buf[row*BUFP + c] * zvp[c];
        acc2 += __shfl_xor_sync(0xffffffffu, acc2, 1);
        acc2 += __shfl_xor_sync(0xffffffffu, acc2, 2);
        if (q == 0) Zp[row] = acc2;
    }

    if (tmode){
        __syncthreads();
        size_t tbase; int sofs;
        if (tmode == 1){
            int b = m0 >> 11;
            int s0 = m0 & 2047;
            int h = n0 >> 8;
            tbase = ((size_t)(b*H_ + h))*D_*S_;
            sofs = s0;
        } else {
            tbase = (size_t)z*D_*S_;
            sofs = m0;
        }
        #pragma unroll 4
        for (int e=0; e<32; e++){
            int flat = e*512 + tid;
            int d = flat >> 6;
            int s = (flat & 63)*2;
            float v0 = buf[(s+0)*BUFP + d];
            float v1 = buf[(s+1)*BUFP + d];
            bf16 h0 = __float2bfloat16(v0);
            bf16 h1 = __float2bfloat16(v1);
            bf16 l0 = __float2bfloat16(v0 - __bfloat162float(h0));
            bf16 l1 = __float2bfloat16(v1 - __bfloat162float(h1));
            size_t o = tbase + (size_t)d*S_ + sofs + s;
            *(__nv_bfloat162*)(Th + o) = __nv_bfloat162(h0, h1);
            *(__nv_bfloat162*)(Tl + o) = __nv_bfloat162(l0, l1);
        }
    }

    if (doneflag){
        __threadfence();
        __syncthreads();
        if (tid == 0) atomicAdd(doneflag, 1);
    }
}

__global__ void __launch_bounds__(512,1) tc_gemm(
    const bf16* __restrict__ Ahg, const bf16* __restrict__ Alg,
    const bf16* __restrict__ Bhg, const bf16* __restrict__ Blg,
    int K, int lda, int ldb, int ldc,
    long sAb, long sAh, long sBb, long sBh, long sCb, long sCh,
    int mode,
    float* __restrict__ C, bf16* __restrict__ O1h, bf16* __restrict__ O1l,
    bf16* __restrict__ O2h, bf16* __restrict__ O2l,
    const float* __restrict__ rowdiv, const float* __restrict__ mix,
    const float* __restrict__ betas, const float* __restrict__ bias,
    bf16* __restrict__ Th, bf16* __restrict__ Tl, int tmode)
{
    extern __shared__ char smemc[];
    tc_gemm_body(Ahg,Alg,Bhg,Blg,K,lda,ldb,ldc,sAb,sAh,sBb,sBh,sCb,sCh,mode,
                 C,O1h,O1l,O2h,O2l,rowdiv,mix,betas,bias,Th,Tl,tmode,0,0,
                 0,0,0,0,
                 blockIdx.x, blockIdx.y, blockIdx.z, smemc);
}

// ================= merged projections: Q (0-255) | K (256-511) | V (512-767) =================
__global__ void __launch_bounds__(512,1) fused_proj(
    const bf16* __restrict__ HSh, const bf16* __restrict__ HSl,
    const bf16* __restrict__ WqTh, const bf16* __restrict__ WqTl,
    const bf16* __restrict__ WkTh, const bf16* __restrict__ WkTl,
    const bf16* __restrict__ WvTh, const bf16* __restrict__ WvTl,
    bf16* __restrict__ Qh, bf16* __restrict__ Ql,
    bf16* __restrict__ SQh, bf16* __restrict__ SQl,
    bf16* __restrict__ Kh, bf16* __restrict__ Kl,
    bf16* __restrict__ SKh, bf16* __restrict__ SKl,
    bf16* __restrict__ SKTh, bf16* __restrict__ SKTl,
    float* __restrict__ Vf, bf16* __restrict__ VTh, bf16* __restrict__ VTl,
    const float* __restrict__ zv, float* __restrict__ Zq, float* __restrict__ Zk)
{
    extern __shared__ char smc[];
    int bid = blockIdx.x;
    int which = bid >> 8, n = bid & 255;
    int bx = n & 3, by = n >> 2;
    if (which == 0){
        tc_gemm_body(HSh,HSl,WqTh,WqTl, E_,E_,E_,E_, 0,0,0,0,0,0, EP_SIGQK,
            0, Qh,Ql, SQh,SQl, 0,0,0,0, 0,0,0, zv, Zq, 0,0,0,0, bx,by,0, smc);
    } else if (which == 1){
        tc_gemm_body(HSh,HSl,WkTh,WkTl, E_,E_,E_,E_, 0,0,0,0,0,0, EP_SIGQK,
            0, Kh,Kl, SKh,SKl, 0,0,0,0, SKTh,SKTl,1, zv, Zk, 0,0,0,0, bx,by,0, smc);
    } else {
        tc_gemm_body(HSh,HSl,WvTh,WvTl, E_,E_,E_,E_, 0,0,0,0,0,0, EP_F32,
            Vf, 0,0,0,0, 0,0,0,0, VTh,VTl,1, 0,0, 0,0,0,0, bx,by,0, smc);
    }
}

// ================= fused flash attention body (512 threads) =================
#define STG_BYTES 65536
#define FA_P     131072
#define FA_STAT  196608
#define FA_SMEM  (196608 + 3072)

__device__ void fa_body(
    const bf16* __restrict__ Qhg, const bf16* __restrict__ Qlg,
    const bf16* __restrict__ Khg, const bf16* __restrict__ Klg,
    const bf16* __restrict__ VThg, const bf16* __restrict__ VTlg,
    float* __restrict__ AO, int* faFlag, int bid, char* smc)
{
    uint32_t sb = smem_u32(smc);
    int z  = (bid>>1)&15;
    int mi = (bid&1) ? (bid>>5) : 15-(bid>>5);
    int bb = z / H_, hh = z % H_;
    int m0 = mi*128;

    int tid = threadIdx.x, wid = tid>>5, lid = tid&31;
    int wm = wid&3, wn = wid>>2;
    int tg = lid>>2, t4 = lid&3;

    const bf16* Qh_ = Qhg + (size_t)bb*S_*E_ + hh*D_;
    const bf16* Ql_ = Qlg + (size_t)bb*S_*E_ + hh*D_;
    const bf16* Kh_ = Khg + (size_t)bb*S_*E_ + hh*D_;
    const bf16* Kl_ = Klg + (size_t)bb*S_*E_ + hh*D_;
    const bf16* VTh_ = VThg + (size_t)z*D_*S_;
    const bf16* VTl_ = VTlg + (size_t)z*D_*S_;

    float* m_s = (float*)(smc + FA_STAT);
    float* l_s = (float*)(smc + FA_STAT + 512);
    float* red = (float*)(smc + FA_STAT + 1024);

    if (tid < 128){ m_s[tid] = -1e30f; l_s[tid] = 0.f; }

    float acc_o[2][8][4];
    #pragma unroll
    for (int a=0;a<2;a++)
        #pragma unroll
        for (int b=0;b<8;b++)
            #pragma unroll
            for (int r=0;r<4;r++) acc_o[a][b][r]=0.f;
    __syncthreads();

    int row_l = tid>>3, v_l = tid&7;

    for (int j=0; j<=mi; j++){
        int jb = j*128;
        float acc_s[2][4][4];
        #pragma unroll
        for (int a=0;a<2;a++)
            #pragma unroll
            for (int b=0;b<4;b++)
                #pragma unroll
                for (int r=0;r<4;r++) acc_s[a][b][r]=0.f;

        auto issueS = [&](int c, int s){
            int stg = s*STG_BYTES, kc0 = c*64;
            #pragma unroll
            for (int i=0;i<2;i++){
                int row = row_l + 64*i;
                uint32_t o = SWZ(row*128 + v_l*16);
                CP_ASYNC(sb+stg+o,       Qh_ + (size_t)(m0+row)*E_ + kc0 + v_l*8);
                CP_ASYNC(sb+stg+16384+o, Ql_ + (size_t)(m0+row)*E_ + kc0 + v_l*8);
                CP_ASYNC(sb+stg+32768+o, Kh_ + (size_t)(jb+row)*E_ + kc0 + v_l*8);
                CP_ASYNC(sb+stg+49152+o, Kl_ + (size_t)(jb+row)*E_ + kc0 + v_l*8);
            }
            CP_COMMIT();
        };
        auto issueV = [&](int kc, int s){
            int stg = s*STG_BYTES;
            #pragma unroll
            for (int i=0;i<4;i++){
                int row = row_l + 64*i;
                uint32_t o = SWZ(row*128 + v_l*16);
                CP_ASYNC(sb+stg+o,       VTh_ + (size_t)row*S_ + jb + kc*64 + v_l*8);
                CP_ASYNC(sb+stg+32768+o, VTl_ + (size_t)row*S_ + jb + kc*64 + v_l*8);
            }
            CP_COMMIT();
        };

        issueS(0,0); issueS(1,1);
        for (int c=0;c<4;c++){
            if (c<3) { CP_WAIT(1); } else { CP_WAIT(0); }
            __syncthreads();
            int stg = (c&1)*STG_BYTES;
            #pragma unroll
            for (int ks=0; ks<4; ks++){
                uint32_t bh[4][2], bl[4][2];
                #pragma unroll
                for (int g=0; g<2; g++){
                    int row = wn*32 + g*16 + (lid&7) + ((lid>>4)&1)*8;
                    int cb2 = ks*32 + ((lid>>3)&1)*16;
                    uint32_t off = SWZ(row*128 + cb2);
                    uint32_t r0,r1,r2,r3;
                    ldm_x4(r0,r1,r2,r3, sb+stg+32768+off);
                    bh[2*g][0]=r0; bh[2*g][1]=r1; bh[2*g+1][0]=r2; bh[2*g+1][1]=r3;
                    ldm_x4(r0,r1,r2,r3, sb+stg+49152+off);
                    bl[2*g][0]=r0; bl[2*g][1]=r1; bl[2*g+1][0]=r2; bl[2*g+1][1]=r3;
                }
                #pragma unroll
                for (int mt=0; mt<2; mt++){
                    int row = wm*32 + mt*16 + (lid&15);
                    uint32_t colb = ks*32 + ((lid>>4)&1)*16;
                    uint32_t off = SWZ(row*128 + colb);
                    uint32_t ah[4], al[4];
                    ldm_x4(ah[0],ah[1],ah[2],ah[3], sb+stg+off);
                    ldm_x4(al[0],al[1],al[2],al[3], sb+stg+16384+off);
                    #pragma unroll
                    for (int nt=0;nt<4;nt++){
                        mma16816(acc_s[mt][nt], ah, bh[nt]);
                        mma16816(acc_s[mt][nt], ah, bl[nt]);
                        mma16816(acc_s[mt][nt], al, bh[nt]);
                    }
                }
            }
            __syncthreads();
            if (c==0) issueS(2,0);
            else if (c==1) issueS(3,1);
        }

        issueV(0,0); issueV(1,1);

        if (j == mi){
            #pragma unroll
            for (int mt=0; mt<2; mt++)
                #pragma unroll
                for (int nt=0; nt<4; nt++)
                    #pragma unroll
                    for (int r=0;r<4;r++){
                        int srow = wm*32 + mt*16 + tg + ((r>>1)&1)*8;
                        int scol = wn*32 + nt*8 + t4*2 + (r&1);
                        if (scol > srow) acc_s[mt][nt][r] = -1e30f;
                    }
        }
        float rmax[2][2];
        #pragma unroll
        for (int mt=0; mt<2; mt++)
            #pragma unroll
            for (int hf=0; hf<2; hf++){
                float m = -1e30f;
                #pragma unroll
                for (int nt=0; nt<4; nt++){
                    m = fmaxf(m, acc_s[mt][nt][hf*2+0]);
                    m = fmaxf(m, acc_s[mt][nt][hf*2+1]);
                }
                m = fmaxf(m, __shfl_xor_sync(0xffffffffu, m, 1));
                m = fmaxf(m, __shfl_xor_sync(0xffffffffu, m, 2));
                rmax[mt][hf] = m;
            }
        if (t4 == 0){
            #pragma unroll
            for (int mt=0; mt<2; mt++)
                #pragma unroll
                for (int hf=0; hf<2; hf++)
                    red[wn*128 + wm*32 + mt*16 + tg + hf*8] = rmax[mt][hf];
        }
        __syncthreads();

        float mnew[2][2], alpha[2][2], rsum[2][2];
        #pragma unroll
        for (int mt=0; mt<2; mt++)
            #pragma unroll
            for (int hf=0; hf<2; hf++){
                int row = wm*32 + mt*16 + tg + hf*8;
                float rm = fmaxf(fmaxf(red[row], red[128+row]), fmaxf(red[256+row], red[384+row]));
                float mo = m_s[row];
                float mn = fmaxf(mo, rm);
                mnew[mt][hf] = mn;
                alpha[mt][hf] = __expf(mo - mn);
                rsum[mt][hf] = 0.f;
            }
        #pragma unroll
        for (int mt=0; mt<2; mt++)
            #pragma unroll
            for (int nt=0; nt<4; nt++)
                #pragma unroll
                for (int r=0;r<4;r++){
                    int hf = r>>1;
                    float p = __expf(acc_s[mt][nt][r] - mnew[mt][hf]);
                    acc_s[mt][nt][r] = p;
                    rsum[mt][hf] += p;
                }
        #pragma unroll
        for (int mt=0; mt<2; mt++)
            #pragma unroll
            for (int hf=0; hf<2; hf++){
                rsum[mt][hf] += __shfl_xor_sync(0xffffffffu, rsum[mt][hf], 1);
                rsum[mt][hf] += __shfl_xor_sync(0xffffffffu, rsum[mt][hf], 2);
            }
        __syncthreads();
        if (t4 == 0){
            #pragma unroll
            for (int mt=0; mt<2; mt++)
                #pragma unroll
                for (int hf=0; hf<2; hf++)
                    red[wn*128 + wm*32 + mt*16 + tg + hf*8] = rsum[mt][hf];
        }
        #pragma unroll
        for (int mt=0; mt<2; mt++)
            #pragma unroll
            for (int nt=0; nt<4; nt++)
                #pragma unroll
                for (int rp=0; rp<2; rp++){
                    int row = wm*32 + mt*16 + tg + rp*8;
                    int col = wn*32 + nt*8 + t4*2;
                    float p0 = acc_s[mt][nt][rp*2+0];
                    float p1 = acc_s[mt][nt][rp*2+1];
                    bf16 h0 = __float2bfloat16(p0);
                    bf16 h1 = __float2bfloat16(p1);
                    bf16 l0 = __float2bfloat16(p0 - __bfloat162float(h0));
                    bf16 l1 = __float2bfloat16(p1 - __bfloat162float(h1));
                    uint32_t o = (uint32_t)(col>>6)*16384u + SWZ((uint32_t)row*128 + (col&63)*2);
                    *(__nv_bfloat162*)(smc + FA_P + o)         = __nv_bfloat162(h0, h1);
                    *(__nv_bfloat162*)(smc + FA_P + 32768 + o) = __nv_bfloat162(l0, l1);
                }
        #pragma unroll
        for (int mt=0; mt<2; mt++)
            #pragma unroll
            for (int nt=0; nt<8; nt++)
                #pragma unroll
                for (int r=0;r<4;r++)
                    acc_o[mt][nt][r] *= alpha[mt][r>>1];
        __syncthreads();
        if (wn == 0 && t4 == 0){
            #pragma unroll
            for (int mt=0; mt<2; mt++)
                #pragma unroll
                for (int hf=0; hf<2; hf++){
                    int row = wm*32 + mt*16 + tg + hf*8;
                    float rs = red[row] + red[128+row] + red[256+row] + red[384+row];
                    l_s[row] = l_s[row]*alpha[mt][hf] + rs;
                    m_s[row] = mnew[mt][hf];
                }
        }

        for (int kc=0; kc<2; kc++){
            if (kc==0) { CP_WAIT(1); } else { CP_WAIT(0); }
            __syncthreads();
            int stg = kc*STG_BYTES;
            uint32_t pb = FA_P + kc*16384;
            #pragma unroll
            for (int ks=0; ks<4; ks++){
                uint32_t bh[8][2], bl[8][2];
                #pragma unroll
                for (int g=0; g<4; g++){
                    int row = wn*64 + g*16 + (lid&7) + ((lid>>4)&1)*8;
                    int cb2 = ks*32 + ((lid>>3)&1)*16;
                    uint32_t off = SWZ(row*128 + cb2);
                    uint32_t r0,r1,r2,r3;
                    ldm_x4(r0,r1,r2,r3, sb+stg+off);
                    bh[2*g][0]=r0; bh[2*g][1]=r1; bh[2*g+1][0]=r2; bh[2*g+1][1]=r3;
                    ldm_x4(r0,r1,r2,r3, sb+stg+32768+off);
                    bl[2*g][0]=r0; bl[2*g][1]=r1; bl[2*g+1][0]=r2; bl[2*g+1][1]=r3;
                }
                #pragma unroll
                for (int mt=0; mt<2; mt++){
                    int row = wm*32 + mt*16 + (lid&15);
                    uint32_t colb = ks*32 + ((lid>>4)&1)*16;
                    uint32_t off = SWZ(row*128 + colb);
                    uint32_t ah[4], al[4];
                    ldm_x4(ah[0],ah[1],ah[2],ah[3], sb+pb+off);
                    ldm_x4(al[0],al[1],al[2],al[3], sb+pb+32768+off);
                    #pragma unroll
                    for (int nt=0;nt<8;nt++){
                        mma16816(acc_o[mt][nt], ah, bh[nt]);
                        mma16816(acc_o[mt][nt], ah, bl[nt]);
                        mma16816(acc_o[mt][nt], al, bh[nt]);
                    }
                }
            }
            __syncthreads();
        }
    }

    __syncthreads();
    float* AOp = AO + (size_t)bb*S_*E_ + hh*D_;
    #pragma unroll
    for (int mt=0; mt<2; mt++)
        #pragma unroll
        for (int hf=0; hf<2; hf++){
            int row = wm*32 + mt*16 + tg + hf*8;
            float linv = 1.f/l_s[row];
            #pragma unroll
            for (int nt=0; nt<8; nt++){
                int col = wn*64 + nt*8 + t4*2;
                float2 v;
                v.x = acc_o[mt][nt][hf*2+0]*linv;
                v.y = acc_o[mt][nt][hf*2+1]*linv;
                *(float2*)(AOp + (size_t)(m0+row)*E_ + col) = v;
            }
        }

    // publish AO-ready flag for this (z, mi)
    __threadfence();
    __syncthreads();
    if (tid == 0) atomicAdd(&faFlag[z*16 + mi], 1);
}

// ====== mega launch: fa 0-255 | delta 256-511 | znew 512-1023 | memupd 1024-1055 | amem 1056-1311 ======
__global__ void __launch_bounds__(512,1) fused_mega(
    const bf16* __restrict__ Qh, const bf16* __restrict__ Ql,
    const bf16* __restrict__ Kh, const bf16* __restrict__ Kl,
    const bf16* __restrict__ VTh, const bf16* __restrict__ VTl,
    float* __restrict__ AO,
    const bf16* __restrict__ SKh, const bf16* __restrict__ SKl,
    const bf16* __restrict__ SQh, const bf16* __restrict__ SQl,
    const bf16* __restrict__ memTh, const bf16* __restrict__ memTl,
    const float* __restrict__ Zk, const float* __restrict__ Zq,
    const float* __restrict__ Vf,
    bf16* __restrict__ UTh, bf16* __restrict__ UTl,
    const bf16* __restrict__ SKTh, const bf16* __restrict__ SKTl,
    const float* __restrict__ zvec, float* __restrict__ zout,
    const float* __restrict__ betas,
    bf16* __restrict__ ABh, bf16* __restrict__ ABl,
    const float* __restrict__ memp, float* __restrict__ memout,
    int* faFlag, int* dCnt)
{
    extern __shared__ char smc[];
    int bid = blockIdx.x;
    if (bid < 256){
        fa_body(Qh,Ql,Kh,Kl,VTh,VTl, AO, faFlag, bid, smc);
    } else if (bid < 512){
        int n = bid - 256;
        int z = n >> 4;
        tc_gemm_body(SKh,SKl,memTh,memTl, D_, E_,D_,E_,
            (long)S_*E_, D_, 0, (long)D_*D_, (long)S_*E_, (long)D_,
            EP_DELTA, 0, 0,0,0,0, Zk, Vf, 0, 0, UTh,UTl,2, 0,0,
            0,0,0, &dCnt[z],
            0, n & 15, z, smc);
    } else if (bid < 1024){
        if (threadIdx.x < 256){
            int w = threadIdx.x >> 5, lane = threadIdx.x & 31;
            int r = (bid - 512)*8 + w;
            int z = r / D_, d = r % D_;
            const bf16* ph = SKTh + (size_t)r*S_;
            const bf16* pl = SKTl + (size_t)r*S_;
            float acc = 0.f;
            #pragma unroll 4
            for (int s=lane; s<S_; s+=32)
                acc += __bfloat162float(ph[s]) + __bfloat162float(pl[s]);
            #pragma unroll
            for (int o=16;o;o>>=1) acc += __shfl_xor_sync(0xffffffffu, acc, o);
            if (lane==0) zout[r] = zvec[(z%H_)*D_ + d] + acc;
        }
    } else if (bid < 1056){
        int n = bid - 1024;
        int z = n >> 1;
        tc_gemm_body(SKTh,SKTl,UTh,UTl, S_, S_,S_,D_,
            (long)H_*D_*S_, (long)D_*S_, (long)H_*D_*S_, (long)D_*S_, (long)H_*D_*D_, (long)D_*D_,
            EP_MEMUPD, memout, 0,0,0,0, 0, memp, 0, 0, 0,0,0, 0,0,
            &dCnt[z], 16, 1, 0,
            0, n & 1, z, smc);
    } else {
        int n = bid - 1056;
        int z = n >> 4, my = n & 15;
        tc_gemm_body(SQh,SQl,memTh,memTl, D_, E_,D_,E_,
            (long)S_*E_, D_, 0, (long)D_*D_, (long)S_*E_, (long)D_,
            EP_AMEM, 0, ABh,ABl, 0,0, Zq, AO, betas, 0, 0,0,0, 0,0,
            &faFlag[z*16 + my], 1, 2, 0,
            0, my, z, smc);
    }
}

// ================= merged prep: split | transW x4 | transMem | flag-zero =================
__global__ void __launch_bounds__(256) prep_kernel(
    const float* __restrict__ hs,
    const float* __restrict__ Wq, const float* __restrict__ Wk,
    const float* __restrict__ Wv, const float* __restrict__ Wo,
    const float* __restrict__ memp,
    bf16* __restrict__ HSh, bf16* __restrict__ HSl,
    bf16* __restrict__ WqTh, bf16* __restrict__ WqTl,
    bf16* __restrict__ WkTh, bf16* __restrict__ WkTl,
    bf16* __restrict__ WvTh, bf16* __restrict__ WvTl,
    bf16* __restrict__ WoTh, bf16* __restrict__ WoTl,
    bf16* __restrict__ memTh, bf16* __restrict__ memTl,
    int* faFlag, int* dCnt)
{
    __shared__ float t[32][33];
    int bid = blockIdx.x, tid = threadIdx.x;
    if (bid < 8192){
        int i = bid*256 + tid;
        float4 v = ((const float4*)hs)[i];
        size_t o = (size_t)i*4;
        store_split(HSh, HSl, o+0, v.x); store_split(HSh, HSl, o+1, v.y);
        store_split(HSh, HSl, o+2, v.z); store_split(HSh, HSl, o+3, v.w);
    } else if (bid < 12288){
        int n = bid - 8192;
        int w = n >> 10, inner = n & 1023;
        const float* W = (w==0) ? Wq : (w==1) ? Wk : (w==2) ? Wv : Wo;
        bf16* Th = (w==0) ? WqTh : (w==1) ? WkTh : (w==2) ? WvTh : WoTh;
        bf16* Tl = (w==0) ? WqTl : (w==1) ? WkTl : (w==2) ? WvTl : WoTl;
        int k0 = (inner & 31)*32, n0 = (inner >> 5)*32;
        int tx = tid & 31, ty = tid >> 5;
        #pragma unroll
        for (int i=0;i<32;i+=8) t[ty+i][tx] = W[(size_t)(k0+ty+i)*E_ + n0+tx];
        __syncthreads();
        #pragma unroll
        for (int i=0;i<32;i+=8){
            size_t o = (size_t)(n0+ty+i)*E_ + k0+tx;
            store_split(Th, Tl, o, t[tx][ty+i]);
        }
    } else if (bid < 12544){
        int n = bid - 12288;
        int h = n >> 6;
        int d0 = ((n >> 3) & 7)*32, e0 = (n & 7)*32;
        int tx = tid & 31, ty = tid >> 5;
        #pragma unroll
        for (int i=0;i<32;i+=8) t[ty+i][tx] = memp[(size_t)h*D_*D_ + (size_t)(d0+ty+i)*D_ + e0+tx];
        __syncthreads();
        #pragma unroll
        for (int i=0;i<32;i+=8){
            size_t o = (size_t)h*D_*D_ + (size_t)(e0+ty+i)*D_ + d0+tx;
            store_split(memTh, memTl, o, t[tx][ty+i]);
        }
    } else {
        if (tid < 256) faFlag[tid] = 0;
        if (tid < BH_) dCnt[tid] = 0;
    }
}

// ================= launch =================
extern "C" void kernel_launch(void* const* d_in, const int* in_sizes, int n_in,
                              void* d_out, int out_size)
{
    const float* hs    = (const float*)d_in[0];
    const float* Wq    = (const float*)d_in[1];
    const float* Wk    = (const float*)d_in[2];
    const float* Wv    = (const float*)d_in[3];
    const float* Wo    = (const float*)d_in[4];
    const float* bo    = (const float*)d_in[5];
    const float* betas = (const float*)d_in[6];
    const float* memp  = (const float*)d_in[7];
    const float* zv    = (const float*)d_in[8];
    float* out = (float*)d_out;

    cudaFuncSetAttribute(tc_gemm, cudaFuncAttributeMaxDynamicSharedMemorySize, G5_SMEM);
    cudaFuncSetAttribute(fused_proj, cudaFuncAttributeMaxDynamicSharedMemorySize, G5_SMEM);
    cudaFuncSetAttribute(fused_mega, cudaFuncAttributeMaxDynamicSharedMemorySize, FA_SMEM);

#define GS(var, sym) cudaGetSymbolAddress((void**)&var, sym)
    bf16 *HSh,*HSl,*WqTh,*WqTl,*WkTh,*WkTl,*WvTh,*WvTl,*WoTh,*WoTl,*memTh,*memTl;
    bf16 *Qh,*Ql,*Kh,*Kl,*SQh,*SQl,*SKh,*SKl,*ABh,*ABl,*VTh,*VTl,*UTh,*UTl,*SKTh,*SKTl;
    float *Vf,*AO,*Zq,*Zk;
    int *faFlag,*dCnt;
    GS(HSh,g_HSh); GS(HSl,g_HSl);
    GS(WqTh,g_WqTh); GS(WqTl,g_WqTl); GS(WkTh,g_WkTh); GS(WkTl,g_WkTl);
    GS(WvTh,g_WvTh); GS(WvTl,g_WvTl); GS(WoTh,g_WoTh); GS(WoTl,g_WoTl);
    GS(memTh,g_memTh); GS(memTl,g_memTl);
    GS(Qh,g_Qh); GS(Ql,g_Ql); GS(Kh,g_Kh); GS(Kl,g_Kl);
    GS(SQh,g_SQh); GS(SQl,g_SQl); GS(SKh,g_SKh); GS(SKl,g_SKl);
    GS(ABh,g_ABh); GS(ABl,g_ABl);
    GS(VTh,g_VTh); GS(VTl,g_VTl); GS(UTh,g_UTh); GS(UTl,g_UTl);
    GS(SKTh,g_SKTh); GS(SKTl,g_SKTl);
    GS(Vf,g_Vf); GS(AO,g_AO);
    GS(Zq,g_Zq); GS(Zk,g_Zk);
    GS(faFlag,g_faFlag); GS(dCnt,g_dCnt);

    const long OUT_MEM = (long)B_*S_*E_;
    const long OUT_Z   = OUT_MEM + (long)B_*H_*D_*D_;
    dim3 t256(256), t512(512);

    // prep: split HS + transpose/split weights + mem + zero flags
    prep_kernel<<<12545, t256>>>(hs, Wq, Wk, Wv, Wo, memp,
        HSh, HSl, WqTh, WqTl, WkTh, WkTl, WvTh, WvTl, WoTh, WoTl, memTh, memTl,
        faFlag, dCnt);

    // merged projections Q|K|V with fused sigma rowdots and transposed outputs
    fused_proj<<<768, t512, G5_SMEM>>>(HSh,HSl, WqTh,WqTl, WkTh,WkTl, WvTh,WvTl,
        Qh,Ql, SQh,SQl, Kh,Kl, SKh,SKl, SKTh,SKTl, Vf, VTh,VTl, zv, Zq, Zk);

    // mega: fa ∥ delta ∥ znew ∥ memupd(waits delta) ∥ amem(waits fa)
    fused_mega<<<1312, t512, FA_SMEM>>>(
        Qh,Ql,Kh,Kl,VTh,VTl, AO,
        SKh,SKl, SQh,SQl, memTh,memTl, Zk, Zq, Vf,
        UTh,UTl, SKTh,SKTl, zv, out+OUT_Z,
        betas, ABh,ABl, memp, out+OUT_MEM,
        faFlag, dCnt);

    // out projection + bias
    tc_gemm<<<dim3(4,64,1), t512, G5_SMEM>>>(ABh,ABl,WoTh,WoTl, E_,E_,E_,E_,
        0,0,0,0,0,0, EP_BIAS, out, 0,0,0,0, 0,0,0, bo, 0,0,0);
}

// round 16
// speedup vs baseline: 1.3150x; 1.0369x over previous
#include <cuda_runtime.h>
#include <cuda_bf16.h>
#include <cstdint>
#include <math.h>

#define B_ 4
#define S_ 2048
#define E_ 1024
#define H_ 4
#define D_ 256
#define BH_ 16
#define MSZ (B_*S_*E_)

typedef __nv_bfloat16 bf16;

// ================= device scratch =================
__device__ bf16 g_HSh[MSZ], g_HSl[MSZ];
__device__ bf16 g_WqTh[E_*E_], g_WqTl[E_*E_];
__device__ bf16 g_WkTh[E_*E_], g_WkTl[E_*E_];
__device__ bf16 g_WvTh[E_*E_], g_WvTl[E_*E_];
__device__ bf16 g_WoTh[E_*E_], g_WoTl[E_*E_];
__device__ bf16 g_memTh[H_*D_*D_], g_memTl[H_*D_*D_];
__device__ bf16 g_Qh[MSZ], g_Ql[MSZ], g_Kh[MSZ], g_Kl[MSZ];
__device__ bf16 g_SQh[MSZ], g_SQl[MSZ], g_SKh[MSZ], g_SKl[MSZ];
__device__ bf16 g_ABh[MSZ], g_ABl[MSZ];
__device__ bf16 g_VTh[MSZ], g_VTl[MSZ];
__device__ bf16 g_UTh[MSZ], g_UTl[MSZ];
__device__ bf16 g_SKTh[MSZ], g_SKTl[MSZ];
__device__ float g_Vf[MSZ], g_AO[MSZ];
__device__ float g_Zq[BH_*S_], g_Zk[BH_*S_];
__device__ int g_faFlag[BH_*16];
__device__ int g_dCnt[BH_];
__device__ int g_aCnt[64];

// ================= helpers =================
__device__ __forceinline__ uint32_t smem_u32(const void* p){
    uint32_t a;
    asm("{ .reg .u64 t; cvta.to.shared.u64 t, %1; cvt.u32.u64 %0, t; }" : "=r"(a) : "l"(p));
    return a;
}
#define SWZ(o) ((o) ^ (((o) >> 3) & 0x70))
#define BUFP 261

#define CP_ASYNC(daddr, gptr) \
    asm volatile("cp.async.cg.shared.global [%0], [%1], 16;" :: "r"(daddr), "l"(gptr) : "memory")
#define CP_COMMIT() asm volatile("cp.async.commit_group;" ::: "memory")
#define CP_WAIT(n)  asm volatile("cp.async.wait_group %0;" :: "n"(n) : "memory")

__device__ __forceinline__ void ldm_x4(uint32_t& r0, uint32_t& r1, uint32_t& r2, uint32_t& r3, uint32_t a){
    asm volatile("ldmatrix.sync.aligned.m8n8.x4.shared.b16 {%0,%1,%2,%3}, [%4];"
        : "=r"(r0), "=r"(r1), "=r"(r2), "=r"(r3) : "r"(a));
}
__device__ __forceinline__ void mma16816(float* c, const uint32_t* a, const uint32_t* b){
    asm volatile("mma.sync.aligned.m16n8k16.row.col.f32.bf16.bf16.f32 "
        "{%0,%1,%2,%3}, {%4,%5,%6,%7}, {%8,%9}, {%0,%1,%2,%3};"
        : "+f"(c[0]), "+f"(c[1]), "+f"(c[2]), "+f"(c[3])
        : "r"(a[0]), "r"(a[1]), "r"(a[2]), "r"(a[3]), "r"(b[0]), "r"(b[1]));
}

__device__ __forceinline__ void store_split(bf16* ph, bf16* pl, size_t i, float v){
    bf16 h = __float2bfloat16(v);
    ph[i] = h;
    pl[i] = __float2bfloat16(v - __bfloat162float(h));
}

enum { EP_F32=0, EP_SIGQK=1, EP_BIAS=2, EP_AMEM=3, EP_DELTA=4, EP_MEMUPD=5 };

// ================= 512-thread HMMA GEMM body =================
#define G5_STG 98304
#define G5_SMEM (2*G5_STG)

__device__ void tc_gemm_body(
    const bf16* __restrict__ Ahg, const bf16* __restrict__ Alg,
    const bf16* __restrict__ Bhg, const bf16* __restrict__ Blg,
    int K, int lda, int ldb, int ldc,
    long sAb, long sAh, long sBb, long sBh, long sCb, long sCh,
    int mode,
    float* __restrict__ C, bf16* __restrict__ O1h, bf16* __restrict__ O1l,
    bf16* __restrict__ O2h, bf16* __restrict__ O2l,
    const float* __restrict__ rowdiv, const float* __restrict__ mix,
    const float* __restrict__ betas, const float* __restrict__ bias,
    bf16* __restrict__ Th, bf16* __restrict__ Tl, int tmode,
    const float* __restrict__ zdotv, float* __restrict__ Zout,
    int* wflag, int wcnt, int wpos, int* doneflag,
    int bx, int by, int bz, char* smemc)
{
    int z = bz, bb = z / H_, hh = z % H_;
    int m0 = by*128, n0 = bx*256;
    int tid = threadIdx.x, wid = tid >> 5, lid = tid & 31;

    // wait-at-start (A/B operand produced by peer CTAs in same launch)
    if (wflag && wpos == 1){
        if (tid == 0){ while (atomicAdd(wflag, 0) < wcnt) {} }
        __syncthreads();
        __threadfence();
    }

    const bf16* Ah = Ahg + (size_t)bb*sAb + (size_t)hh*sAh;
    const bf16* Al = Alg + (size_t)bb*sAb + (size_t)hh*sAh;
    const bf16* Bh = Bhg + (size_t)bb*sBb + (size_t)hh*sBh;
    const bf16* Bl = Blg + (size_t)bb*sBb + (size_t)hh*sBh;
    size_t coff = (size_t)bb*sCb + (size_t)hh*sCh;

    uint32_t sb = smem_u32(smemc);
    int wm = wid & 1, wn = wid >> 1;
    int mbase = wm*64, nbase = wn*32;

    float acc[4][4][4];
    #pragma unroll
    for (int i=0;i<4;i++)
        #pragma unroll
        for (int j=0;j<4;j++)
            #pragma unroll
            for (int r=0;r<4;r++) acc[i][j][r]=0.f;

    int nch = K >> 6;
    int row_l = tid >> 3, v_l = tid & 7;

    auto issue = [&](int ci, int s){
        int stg = s*G5_STG, kc0 = ci << 6;
        #pragma unroll
        for (int i=0;i<2;i++){
            int row = row_l + 64*i;
            uint32_t o = SWZ(row*128 + v_l*16);
            CP_ASYNC(sb+stg+o,       Ah + (size_t)(m0+row)*lda + kc0 + v_l*8);
            CP_ASYNC(sb+stg+16384+o, Al + (size_t)(m0+row)*lda + kc0 + v_l*8);
        }
        #pragma unroll
        for (int i=0;i<4;i++){
            int row = row_l + 64*i;
            uint32_t o = SWZ(row*128 + v_l*16);
            CP_ASYNC(sb+stg+32768+o, Bh + (size_t)(n0+row)*ldb + kc0 + v_l*8);
            CP_ASYNC(sb+stg+65536+o, Bl + (size_t)(n0+row)*ldb + kc0 + v_l*8);
        }
        CP_COMMIT();
    };

    issue(0, 0);
    if (nch > 1) issue(1, 1);

    for (int ci=0; ci<nch; ci++){
        if (ci+1 < nch) { CP_WAIT(1); } else { CP_WAIT(0); }
        __syncthreads();
        int stg = (ci&1)*G5_STG;

        #pragma unroll
        for (int ks=0; ks<4; ks++){
            int colb = ks*32 + ((lid>>4)&1)*16;
            uint32_t ah[4][4], al[4][4];
            #pragma unroll
            for (int mt=0; mt<4; mt++){
                int row = mbase + mt*16 + (lid & 15);
                uint32_t off = SWZ(row*128 + colb);
                ldm_x4(ah[mt][0],ah[mt][1],ah[mt][2],ah[mt][3], sb+stg+off);
                ldm_x4(al[mt][0],al[mt][1],al[mt][2],al[mt][3], sb+stg+16384+off);
            }
            uint32_t bh[4][2], bl[4][2];
            #pragma unroll
            for (int g=0; g<2; g++){
                int row = nbase + g*16 + (lid & 7) + ((lid>>4)&1)*8;
                int cb2 = ks*32 + ((lid>>3)&1)*16;
                uint32_t off = SWZ(row*128 + cb2);
                uint32_t r0,r1,r2,r3;
                ldm_x4(r0,r1,r2,r3, sb+stg+32768+off);
                bh[2*g][0]=r0; bh[2*g][1]=r1; bh[2*g+1][0]=r2; bh[2*g+1][1]=r3;
                ldm_x4(r0,r1,r2,r3, sb+stg+65536+off);
                bl[2*g][0]=r0; bl[2*g][1]=r1; bl[2*g+1][0]=r2; bl[2*g+1][1]=r3;
            }
            #pragma unroll
            for (int mt=0; mt<4; mt++)
                #pragma unroll
                for (int nt=0; nt<4; nt++){
                    mma16816(acc[mt][nt], ah[mt], bh[nt]);
                    mma16816(acc[mt][nt], ah[mt], bl[nt]);
                    mma16816(acc[mt][nt], al[mt], bh[nt]);
                }
        }
        __syncthreads();
        if (ci+2 < nch) issue(ci+2, ci&1);
    }

    float* buf = (float*)smemc;              // 128 x BUFP
    int tg = lid >> 2, t4 = lid & 3;
    #pragma unroll
    for (int mt=0; mt<4; mt++)
        #pragma unroll
        for (int nt=0; nt<4; nt++)
            #pragma unroll
            for (int r=0; r<4; r++){
                int m = mbase + mt*16 + tg + (r>=2 ? 8 : 0);
                int c = nbase + nt*8 + t4*2 + (r&1);
                buf[m*BUFP + c] = acc[mt][nt][r];
            }
    __syncthreads();

    // wait-pre-epilogue (amem: mix=AO produced by fa peer CTAs)
    if (wflag && wpos == 2){
        if (tid == 0){ while (atomicAdd(wflag, 0) < wcnt) {} }
        __syncthreads();
        __threadfence();
    }

    float gate = 0.f;
    if (mode == EP_AMEM) gate = 1.f/(1.f + __expf(-betas[hh]));

    #pragma unroll 4
    for (int e=0; e<64; e++){
        int flat = e*512 + tid;
        int row = flat >> 8, col = flat & 255;
        float v = buf[row*BUFP + col];
        int m = m0 + row, c = n0 + col;
        size_t idx = coff + (size_t)m*ldc + c;
        if (mode == EP_F32) {
            if (C) C[idx] = v;
        } else if (mode == EP_SIGQK) {
            store_split(O1h, O1l, idx, v);
            float sg = v > 0.f ? v + 1.f : __expf(v);
            store_split(O2h, O2l, idx, sg);
            buf[row*BUFP + col] = sg;
        } else if (mode == EP_BIAS) {
            C[idx] = v + bias[c];
        } else if (mode == EP_AMEM) {
            float rinv = 1.f/(rowdiv[(size_t)z*S_ + m] + 1e-6f);
            float val = gate*(v*rinv) + (1.f-gate)*mix[idx];
            store_split(O1h, O1l, idx, val);
        } else if (mode == EP_DELTA) {
            float rinv = 1.f/(rowdiv[(size_t)z*S_ + m] + 1e-6f);
            float u = mix[idx] - v*rinv;
            if (C) C[idx] = u;
            buf[row*BUFP + col] = u;
        } else {
            float mv = mix[(size_t)hh*D_*D_ + (size_t)m*D_ + c];
            C[idx] = mv + v;
        }
    }

    // ---- fused rowdot for sigma projections ----
    if (mode == EP_SIGQK && Zout){
        __syncthreads();
        int bp = m0 >> 11, hp = n0 >> 8;
        int s0 = m0 & 2047;
        float* Zp = Zout + ((size_t)(bp*H_ + hp))*S_ + s0;
        const float* zvp = zdotv + hp*D_;
        int row = tid >> 2, q = tid & 3;
        float acc2 = 0.f;
        #pragma unroll 16
        for (int c = q*64; c < q*64 + 64; c++)
            acc2 += buf[row*BUFP + c] * zvp[c];
        acc2 += __shfl_xor_sync(0xffffffffu, acc2, 1);
        acc2 += __shfl_xor_sync(0xffffffffu, acc2, 2);
        if (q == 0) Zp[row] = acc2;
    }

    if (tmode){
        __syncthreads();
        size_t tbase; int sofs;
        if (tmode == 1){
            int b = m0 >> 11;
            int s0 = m0 & 2047;
            int h = n0 >> 8;
            tbase = ((size_t)(b*H_ + h))*D_*S_;
            sofs = s0;
        } else {
            tbase = (size_t)z*D_*S_;
            sofs = m0;
        }
        #pragma unroll 4
        for (int e=0; e<32; e++){
            int flat = e*512 + tid;
            int d = flat >> 6;
            int s = (flat & 63)*2;
            float v0 = buf[(s+0)*BUFP + d];
            float v1 = buf[(s+1)*BUFP + d];
            bf16 h0 = __float2bfloat16(v0);
            bf16 h1 = __float2bfloat16(v1);
            bf16 l0 = __float2bfloat16(v0 - __bfloat162float(h0));
            bf16 l1 = __float2bfloat16(v1 - __bfloat162float(h1));
            size_t o = tbase + (size_t)d*S_ + sofs + s;
            *(__nv_bfloat162*)(Th + o) = __nv_bfloat162(h0, h1);
            *(__nv_bfloat162*)(Tl + o) = __nv_bfloat162(l0, l1);
        }
    }

    if (doneflag){
        __threadfence();
        __syncthreads();
        if (tid == 0) atomicAdd(doneflag, 1);
    }
}

// ================= merged projections: Q (0-255) | K (256-511) | V (512-767) =================
__global__ void __launch_bounds__(512,1) fused_proj(
    const bf16* __restrict__ HSh, const bf16* __restrict__ HSl,
    const bf16* __restrict__ WqTh, const bf16* __restrict__ WqTl,
    const bf16* __restrict__ WkTh, const bf16* __restrict__ WkTl,
    const bf16* __restrict__ WvTh, const bf16* __restrict__ WvTl,
    bf16* __restrict__ Qh, bf16* __restrict__ Ql,
    bf16* __restrict__ SQh, bf16* __restrict__ SQl,
    bf16* __restrict__ Kh, bf16* __restrict__ Kl,
    bf16* __restrict__ SKh, bf16* __restrict__ SKl,
    bf16* __restrict__ SKTh, bf16* __restrict__ SKTl,
    float* __restrict__ Vf, bf16* __restrict__ VTh, bf16* __restrict__ VTl,
    const float* __restrict__ zv, float* __restrict__ Zq, float* __restrict__ Zk)
{
    extern __shared__ char smc[];
    int bid = blockIdx.x;
    int which = bid >> 8, n = bid & 255;
    int bx = n & 3, by = n >> 2;
    if (which == 0){
        tc_gemm_body(HSh,HSl,WqTh,WqTl, E_,E_,E_,E_, 0,0,0,0,0,0, EP_SIGQK,
            0, Qh,Ql, SQh,SQl, 0,0,0,0, 0,0,0, zv, Zq, 0,0,0,0, bx,by,0, smc);
    } else if (which == 1){
        tc_gemm_body(HSh,HSl,WkTh,WkTl, E_,E_,E_,E_, 0,0,0,0,0,0, EP_SIGQK,
            0, Kh,Kl, SKh,SKl, 0,0,0,0, SKTh,SKTl,1, zv, Zk, 0,0,0,0, bx,by,0, smc);
    } else {
        tc_gemm_body(HSh,HSl,WvTh,WvTl, E_,E_,E_,E_, 0,0,0,0,0,0, EP_F32,
            Vf, 0,0,0,0, 0,0,0,0, VTh,VTl,1, 0,0, 0,0,0,0, bx,by,0, smc);
    }
}

// ================= fused flash attention body (512 threads) =================
#define STG_BYTES 65536
#define FA_P     131072
#define FA_STAT  196608
#define FA_SMEM  (196608 + 3072)

__device__ void fa_body(
    const bf16* __restrict__ Qhg, const bf16* __restrict__ Qlg,
    const bf16* __restrict__ Khg, const bf16* __restrict__ Klg,
    const bf16* __restrict__ VThg, const bf16* __restrict__ VTlg,
    float* __restrict__ AO, int* faFlag, int bid, char* smc)
{
    uint32_t sb = smem_u32(smc);
    int z  = (bid>>1)&15;
    int mi = (bid&1) ? (bid>>5) : 15-(bid>>5);
    int bb = z / H_, hh = z % H_;
    int m0 = mi*128;

    int tid = threadIdx.x, wid = tid>>5, lid = tid&31;
    int wm = wid&3, wn = wid>>2;
    int tg = lid>>2, t4 = lid&3;

    const bf16* Qh_ = Qhg + (size_t)bb*S_*E_ + hh*D_;
    const bf16* Ql_ = Qlg + (size_t)bb*S_*E_ + hh*D_;
    const bf16* Kh_ = Khg + (size_t)bb*S_*E_ + hh*D_;
    const bf16* Kl_ = Klg + (size_t)bb*S_*E_ + hh*D_;
    const bf16* VTh_ = VThg + (size_t)z*D_*S_;
    const bf16* VTl_ = VTlg + (size_t)z*D_*S_;

    float* m_s = (float*)(smc + FA_STAT);
    float* l_s = (float*)(smc + FA_STAT + 512);
    float* red = (float*)(smc + FA_STAT + 1024);

    if (tid < 128){ m_s[tid] = -1e30f; l_s[tid] = 0.f; }

    float acc_o[2][8][4];
    #pragma unroll
    for (int a=0;a<2;a++)
        #pragma unroll
        for (int b=0;b<8;b++)
            #pragma unroll
            for (int r=0;r<4;r++) acc_o[a][b][r]=0.f;
    __syncthreads();

    int row_l = tid>>3, v_l = tid&7;

    for (int j=0; j<=mi; j++){
        int jb = j*128;
        float acc_s[2][4][4];
        #pragma unroll
        for (int a=0;a<2;a++)
            #pragma unroll
            for (int b=0;b<4;b++)
                #pragma unroll
                for (int r=0;r<4;r++) acc_s[a][b][r]=0.f;

        auto issueS = [&](int c, int s){
            int stg = s*STG_BYTES, kc0 = c*64;
            #pragma unroll
            for (int i=0;i<2;i++){
                int row = row_l + 64*i;
                uint32_t o = SWZ(row*128 + v_l*16);
                CP_ASYNC(sb+stg+o,       Qh_ + (size_t)(m0+row)*E_ + kc0 + v_l*8);
                CP_ASYNC(sb+stg+16384+o, Ql_ + (size_t)(m0+row)*E_ + kc0 + v_l*8);
                CP_ASYNC(sb+stg+32768+o, Kh_ + (size_t)(jb+row)*E_ + kc0 + v_l*8);
                CP_ASYNC(sb+stg+49152+o, Kl_ + (size_t)(jb+row)*E_ + kc0 + v_l*8);
            }
            CP_COMMIT();
        };
        auto issueV = [&](int kc, int s){
            int stg = s*STG_BYTES;
            #pragma unroll
            for (int i=0;i<4;i++){
                int row = row_l + 64*i;
                uint32_t o = SWZ(row*128 + v_l*16);
                CP_ASYNC(sb+stg+o,       VTh_ + (size_t)row*S_ + jb + kc*64 + v_l*8);
                CP_ASYNC(sb+stg+32768+o, VTl_ + (size_t)row*S_ + jb + kc*64 + v_l*8);
            }
            CP_COMMIT();
        };

        issueS(0,0); issueS(1,1);
        for (int c=0;c<4;c++){
            if (c<3) { CP_WAIT(1); } else { CP_WAIT(0); }
            __syncthreads();
            int stg = (c&1)*STG_BYTES;
            #pragma unroll
            for (int ks=0; ks<4; ks++){
                uint32_t bh[4][2], bl[4][2];
                #pragma unroll
                for (int g=0; g<2; g++){
                    int row = wn*32 + g*16 + (lid&7) + ((lid>>4)&1)*8;
                    int cb2 = ks*32 + ((lid>>3)&1)*16;
                    uint32_t off = SWZ(row*128 + cb2);
                    uint32_t r0,r1,r2,r3;
                    ldm_x4(r0,r1,r2,r3, sb+stg+32768+off);
                    bh[2*g][0]=r0; bh[2*g][1]=r1; bh[2*g+1][0]=r2; bh[2*g+1][1]=r3;
                    ldm_x4(r0,r1,r2,r3, sb+stg+49152+off);
                    bl[2*g][0]=r0; bl[2*g][1]=r1; bl[2*g+1][0]=r2; bl[2*g+1][1]=r3;
                }
                #pragma unroll
                for (int mt=0; mt<2; mt++){
                    int row = wm*32 + mt*16 + (lid&15);
                    uint32_t colb = ks*32 + ((lid>>4)&1)*16;
                    uint32_t off = SWZ(row*128 + colb);
                    uint32_t ah[4], al[4];
                    ldm_x4(ah[0],ah[1],ah[2],ah[3], sb+stg+off);
                    ldm_x4(al[0],al[1],al[2],al[3], sb+stg+16384+off);
                    #pragma unroll
                    for (int nt=0;nt<4;nt++){
                        mma16816(acc_s[mt][nt], ah, bh[nt]);
                        mma16816(acc_s[mt][nt], ah, bl[nt]);
                        mma16816(acc_s[mt][nt], al, bh[nt]);
                    }
                }
            }
            __syncthreads();
            if (c==0) issueS(2,0);
            else if (c==1) issueS(3,1);
        }

        issueV(0,0); issueV(1,1);

        if (j == mi){
            #pragma unroll
            for (int mt=0; mt<2; mt++)
                #pragma unroll
                for (int nt=0; nt<4; nt++)
                    #pragma unroll
                    for (int r=0;r<4;r++){
                        int srow = wm*32 + mt*16 + tg + ((r>>1)&1)*8;
                        int scol = wn*32 + nt*8 + t4*2 + (r&1);
                        if (scol > srow) acc_s[mt][nt][r] = -1e30f;
                    }
        }
        float rmax[2][2];
        #pragma unroll
        for (int mt=0; mt<2; mt++)
            #pragma unroll
            for (int hf=0; hf<2; hf++){
                float m = -1e30f;
                #pragma unroll
                for (int nt=0; nt<4; nt++){
                    m = fmaxf(m, acc_s[mt][nt][hf*2+0]);
                    m = fmaxf(m, acc_s[mt][nt][hf*2+1]);
                }
                m = fmaxf(m, __shfl_xor_sync(0xffffffffu, m, 1));
                m = fmaxf(m, __shfl_xor_sync(0xffffffffu, m, 2));
                rmax[mt][hf] = m;
            }
        if (t4 == 0){
            #pragma unroll
            for (int mt=0; mt<2; mt++)
                #pragma unroll
                for (int hf=0; hf<2; hf++)
                    red[wn*128 + wm*32 + mt*16 + tg + hf*8] = rmax[mt][hf];
        }
        __syncthreads();

        float mnew[2][2], alpha[2][2], rsum[2][2];
        #pragma unroll
        for (int mt=0; mt<2; mt++)
            #pragma unroll
            for (int hf=0; hf<2; hf++){
                int row = wm*32 + mt*16 + tg + hf*8;
                float rm = fmaxf(fmaxf(red[row], red[128+row]), fmaxf(red[256+row], red[384+row]));
                float mo = m_s[row];
                float mn = fmaxf(mo, rm);
                mnew[mt][hf] = mn;
                alpha[mt][hf] = __expf(mo - mn);
                rsum[mt][hf] = 0.f;
            }
        #pragma unroll
        for (int mt=0; mt<2; mt++)
            #pragma unroll
            for (int nt=0; nt<4; nt++)
                #pragma unroll
                for (int r=0;r<4;r++){
                    int hf = r>>1;
                    float p = __expf(acc_s[mt][nt][r] - mnew[mt][hf]);
                    acc_s[mt][nt][r] = p;
                    rsum[mt][hf] += p;
                }
        #pragma unroll
        for (int mt=0; mt<2; mt++)
            #pragma unroll
            for (int hf=0; hf<2; hf++){
                rsum[mt][hf] += __shfl_xor_sync(0xffffffffu, rsum[mt][hf], 1);
                rsum[mt][hf] += __shfl_xor_sync(0xffffffffu, rsum[mt][hf], 2);
            }
        __syncthreads();
        if (t4 == 0){
            #pragma unroll
            for (int mt=0; mt<2; mt++)
                #pragma unroll
                for (int hf=0; hf<2; hf++)
                    red[wn*128 + wm*32 + mt*16 + tg + hf*8] = rsum[mt][hf];
        }
        #pragma unroll
        for (int mt=0; mt<2; mt++)
            #pragma unroll
            for (int nt=0; nt<4; nt++)
                #pragma unroll
                for (int rp=0; rp<2; rp++){
                    int row = wm*32 + mt*16 + tg + rp*8;
                    int col = wn*32 + nt*8 + t4*2;
                    float p0 = acc_s[mt][nt][rp*2+0];
                    float p1 = acc_s[mt][nt][rp*2+1];
                    bf16 h0 = __float2bfloat16(p0);
                    bf16 h1 = __float2bfloat16(p1);
                    bf16 l0 = __float2bfloat16(p0 - __bfloat162float(h0));
                    bf16 l1 = __float2bfloat16(p1 - __bfloat162float(h1));
                    uint32_t o = (uint32_t)(col>>6)*16384u + SWZ((uint32_t)row*128 + (col&63)*2);
                    *(__nv_bfloat162*)(smc + FA_P + o)         = __nv_bfloat162(h0, h1);
                    *(__nv_bfloat162*)(smc + FA_P + 32768 + o) = __nv_bfloat162(l0, l1);
                }
        #pragma unroll
        for (int mt=0; mt<2; mt++)
            #pragma unroll
            for (int nt=0; nt<8; nt++)
                #pragma unroll
                for (int r=0;r<4;r++)
                    acc_o[mt][nt][r] *= alpha[mt][r>>1];
        __syncthreads();
        if (wn == 0 && t4 == 0){
            #pragma unroll
            for (int mt=0; mt<2; mt++)
                #pragma unroll
                for (int hf=0; hf<2; hf++){
                    int row = wm*32 + mt*16 + tg + hf*8;
                    float rs = red[row] + red[128+row] + red[256+row] + red[384+row];
                    l_s[row] = l_s[row]*alpha[mt][hf] + rs;
                    m_s[row] = mnew[mt][hf];
                }
        }

        for (int kc=0; kc<2; kc++){
            if (kc==0) { CP_WAIT(1); } else { CP_WAIT(0); }
            __syncthreads();
            int stg = kc*STG_BYTES;
            uint32_t pb = FA_P + kc*16384;
            #pragma unroll
            for (int ks=0; ks<4; ks++){
                uint32_t bh[8][2], bl[8][2];
                #pragma unroll
                for (int g=0; g<4; g++){
                    int row = wn*64 + g*16 + (lid&7) + ((lid>>4)&1)*8;
                    int cb2 = ks*32 + ((lid>>3)&1)*16;
                    uint32_t off = SWZ(row*128 + cb2);
                    uint32_t r0,r1,r2,r3;
                    ldm_x4(r0,r1,r2,r3, sb+stg+off);
                    bh[2*g][0]=r0; bh[2*g][1]=r1; bh[2*g+1][0]=r2; bh[2*g+1][1]=r3;
                    ldm_x4(r0,r1,r2,r3, sb+stg+32768+off);
                    bl[2*g][0]=r0; bl[2*g][1]=r1; bl[2*g+1][0]=r2; bl[2*g+1][1]=r3;
                }
                #pragma unroll
                for (int mt=0; mt<2; mt++){
                    int row = wm*32 + mt*16 + (lid&15);
                    uint32_t colb = ks*32 + ((lid>>4)&1)*16;
                    uint32_t off = SWZ(row*128 + colb);
                    uint32_t ah[4], al[4];
                    ldm_x4(ah[0],ah[1],ah[2],ah[3], sb+pb+off);
                    ldm_x4(al[0],al[1],al[2],al[3], sb+pb+32768+off);
                    #pragma unroll
                    for (int nt=0;nt<8;nt++){
                        mma16816(acc_o[mt][nt], ah, bh[nt]);
                        mma16816(acc_o[mt][nt], ah, bl[nt]);
                        mma16816(acc_o[mt][nt], al, bh[nt]);
                    }
                }
            }
            __syncthreads();
        }
    }

    __syncthreads();
    float* AOp = AO + (size_t)bb*S_*E_ + hh*D_;
    #pragma unroll
    for (int mt=0; mt<2; mt++)
        #pragma unroll
        for (int hf=0; hf<2; hf++){
            int row = wm*32 + mt*16 + tg + hf*8;
            float linv = 1.f/l_s[row];
            #pragma unroll
            for (int nt=0; nt<8; nt++){
                int col = wn*64 + nt*8 + t4*2;
                float2 v;
                v.x = acc_o[mt][nt][hf*2+0]*linv;
                v.y = acc_o[mt][nt][hf*2+1]*linv;
                *(float2*)(AOp + (size_t)(m0+row)*E_ + col) = v;
            }
        }

    __threadfence();
    __syncthreads();
    if (tid == 0) atomicAdd(&faFlag[z*16 + mi], 1);
}

// ====== mega: fa 0-255 | delta 256-511 | znew 512-1023 | memupd 1024-1055 | amem 1056-1311 | outproj 1312-1567 ======
__global__ void __launch_bounds__(512,1) fused_mega(
    const bf16* __restrict__ Qh, const bf16* __restrict__ Ql,
    const bf16* __restrict__ Kh, const bf16* __restrict__ Kl,
    const bf16* __restrict__ VTh, const bf16* __restrict__ VTl,
    float* __restrict__ AO,
    const bf16* __restrict__ SKh, const bf16* __restrict__ SKl,
    const bf16* __restrict__ SQh, const bf16* __restrict__ SQl,
    const bf16* __restrict__ memTh, const bf16* __restrict__ memTl,
    const float* __restrict__ Zk, const float* __restrict__ Zq,
    const float* __restrict__ Vf,
    bf16* __restrict__ UTh, bf16* __restrict__ UTl,
    const bf16* __restrict__ SKTh, const bf16* __restrict__ SKTl,
    const float* __restrict__ zvec, float* __restrict__ zout,
    const float* __restrict__ betas,
    bf16* __restrict__ ABh, bf16* __restrict__ ABl,
    const float* __restrict__ memp, float* __restrict__ memout,
    const bf16* __restrict__ WoTh, const bf16* __restrict__ WoTl,
    const float* __restrict__ bo, float* __restrict__ outp,
    int* faFlag, int* dCnt, int* aCnt)
{
    extern __shared__ char smc[];
    int bid = blockIdx.x;
    if (bid < 256){
        fa_body(Qh,Ql,Kh,Kl,VTh,VTl, AO, faFlag, bid, smc);
    } else if (bid < 512){
        int n = bid - 256;
        int z = n >> 4;
        tc_gemm_body(SKh,SKl,memTh,memTl, D_, E_,D_,E_,
            (long)S_*E_, D_, 0, (long)D_*D_, (long)S_*E_, (long)D_,
            EP_DELTA, 0, 0,0,0,0, Zk, Vf, 0, 0, UTh,UTl,2, 0,0,
            0,0,0, &dCnt[z],
            0, n & 15, z, smc);
    } else if (bid < 1024){
        if (threadIdx.x < 256){
            int w = threadIdx.x >> 5, lane = threadIdx.x & 31;
            int r = (bid - 512)*8 + w;
            int z = r / D_, d = r % D_;
            const bf16* ph = SKTh + (size_t)r*S_;
            const bf16* pl = SKTl + (size_t)r*S_;
            float acc = 0.f;
            #pragma unroll 4
            for (int s=lane; s<S_; s+=32)
                acc += __bfloat162float(ph[s]) + __bfloat162float(pl[s]);
            #pragma unroll
            for (int o=16;o;o>>=1) acc += __shfl_xor_sync(0xffffffffu, acc, o);
            if (lane==0) zout[r] = zvec[(z%H_)*D_ + d] + acc;
        }
    } else if (bid < 1056){
        int n = bid - 1024;
        int z = n >> 1;
        tc_gemm_body(SKTh,SKTl,UTh,UTl, S_, S_,S_,D_,
            (long)H_*D_*S_, (long)D_*S_, (long)H_*D_*S_, (long)D_*S_, (long)H_*D_*D_, (long)D_*D_,
            EP_MEMUPD, memout, 0,0,0,0, 0, memp, 0, 0, 0,0,0, 0,0,
            &dCnt[z], 16, 1, 0,
            0, n & 1, z, smc);
    } else if (bid < 1312){
        int n = bid - 1056;
        int z = n >> 4, my = n & 15;
        tc_gemm_body(SQh,SQl,memTh,memTl, D_, E_,D_,E_,
            (long)S_*E_, D_, 0, (long)D_*D_, (long)S_*E_, (long)D_,
            EP_AMEM, 0, ABh,ABl, 0,0, Zq, AO, betas, 0, 0,0,0, 0,0,
            &faFlag[z*16 + my], 1, 2, &aCnt[(z/H_)*16 + my],
            0, my, z, smc);
    } else {
        int n = bid - 1312;
        int bx = n & 3, by = n >> 2;        // by in 0..63; flag idx == by
        tc_gemm_body(ABh,ABl,WoTh,WoTl, E_,E_,E_,E_, 0,0,0,0,0,0,
            EP_BIAS, outp, 0,0,0,0, 0,0,0, bo, 0,0,0, 0,0,
            &aCnt[by], 4, 1, 0,
            bx, by, 0, smc);
    }
}

// ================= merged prep: split | transW x4 | transMem | flag-zero =================
__global__ void __launch_bounds__(256) prep_kernel(
    const float* __restrict__ hs,
    const float* __restrict__ Wq, const float* __restrict__ Wk,
    const float* __restrict__ Wv, const float* __restrict__ Wo,
    const float* __restrict__ memp,
    bf16* __restrict__ HSh, bf16* __restrict__ HSl,
    bf16* __restrict__ WqTh, bf16* __restrict__ WqTl,
    bf16* __restrict__ WkTh, bf16* __restrict__ WkTl,
    bf16* __restrict__ WvTh, bf16* __restrict__ WvTl,
    bf16* __restrict__ WoTh, bf16* __restrict__ WoTl,
    bf16* __restrict__ memTh, bf16* __restrict__ memTl,
    int* faFlag, int* dCnt, int* aCnt)
{
    __shared__ float t[32][33];
    int bid = blockIdx.x, tid = threadIdx.x;
    if (bid < 8192){
        int i = bid*256 + tid;
        float4 v = ((const float4*)hs)[i];
        size_t o = (size_t)i*4;
        store_split(HSh, HSl, o+0, v.x); store_split(HSh, HSl, o+1, v.y);
        store_split(HSh, HSl, o+2, v.z); store_split(HSh, HSl, o+3, v.w);
    } else if (bid < 12288){
        int n = bid - 8192;
        int w = n >> 10, inner = n & 1023;
        const float* W = (w==0) ? Wq : (w==1) ? Wk : (w==2) ? Wv : Wo;
        bf16* Th = (w==0) ? WqTh : (w==1) ? WkTh : (w==2) ? WvTh : WoTh;
        bf16* Tl = (w==0) ? WqTl : (w==1) ? WkTl : (w==2) ? WvTl : WoTl;
        int k0 = (inner & 31)*32, n0 = (inner >> 5)*32;
        int tx = tid & 31, ty = tid >> 5;
        #pragma unroll
        for (int i=0;i<32;i+=8) t[ty+i][tx] = W[(size_t)(k0+ty+i)*E_ + n0+tx];
        __syncthreads();
        #pragma unroll
        for (int i=0;i<32;i+=8){
            size_t o = (size_t)(n0+ty+i)*E_ + k0+tx;
            store_split(Th, Tl, o, t[tx][ty+i]);
        }
    } else if (bid < 12544){
        int n = bid - 12288;
        int h = n >> 6;
        int d0 = ((n >> 3) & 7)*32, e0 = (n & 7)*32;
        int tx = tid & 31, ty = tid >> 5;
        #pragma unroll
        for (int i=0;i<32;i+=8) t[ty+i][tx] = memp[(size_t)h*D_*D_ + (size_t)(d0+ty+i)*D_ + e0+tx];
        __syncthreads();
        #pragma unroll
        for (int i=0;i<32;i+=8){
            size_t o = (size_t)h*D_*D_ + (size_t)(e0+ty+i)*D_ + d0+tx;
            store_split(memTh, memTl, o, t[tx][ty+i]);
        }
    } else {
        if (tid < 256) faFlag[tid] = 0;
        if (tid < BH_) dCnt[tid] = 0;
        if (tid >= 32 && tid < 96) aCnt[tid-32] = 0;
    }
}

// ================= launch =================
extern "C" void kernel_launch(void* const* d_in, const int* in_sizes, int n_in,
                              void* d_out, int out_size)
{
    const float* hs    = (const float*)d_in[0];
    const float* Wq    = (const float*)d_in[1];
    const float* Wk    = (const float*)d_in[2];
    const float* Wv    = (const float*)d_in[3];
    const float* Wo    = (const float*)d_in[4];
    const float* bo    = (const float*)d_in[5];
    const float* betas = (const float*)d_in[6];
    const float* memp  = (const float*)d_in[7];
    const float* zv    = (const float*)d_in[8];
    float* out = (float*)d_out;

    cudaFuncSetAttribute(fused_proj, cudaFuncAttributeMaxDynamicSharedMemorySize, G5_SMEM);
    cudaFuncSetAttribute(fused_mega, cudaFuncAttributeMaxDynamicSharedMemorySize, FA_SMEM);

#define GS(var, sym) cudaGetSymbolAddress((void**)&var, sym)
    bf16 *HSh,*HSl,*WqTh,*WqTl,*WkTh,*WkTl,*WvTh,*WvTl,*WoTh,*WoTl,*memTh,*memTl;
    bf16 *Qh,*Ql,*Kh,*Kl,*SQh,*SQl,*SKh,*SKl,*ABh,*ABl,*VTh,*VTl,*UTh,*UTl,*SKTh,*SKTl;
    float *Vf,*AO,*Zq,*Zk;
    int *faFlag,*dCnt,*aCnt;
    GS(HSh,g_HSh); GS(HSl,g_HSl);
    GS(WqTh,g_WqTh); GS(WqTl,g_WqTl); GS(WkTh,g_WkTh); GS(WkTl,g_WkTl);
    GS(WvTh,g_WvTh); GS(WvTl,g_WvTl); GS(WoTh,g_WoTh); GS(WoTl,g_WoTl);
    GS(memTh,g_memTh); GS(memTl,g_memTl);
    GS(Qh,g_Qh); GS(Ql,g_Ql); GS(Kh,g_Kh); GS(Kl,g_Kl);
    GS(SQh,g_SQh); GS(SQl,g_SQl); GS(SKh,g_SKh); GS(SKl,g_SKl);
    GS(ABh,g_ABh); GS(ABl,g_ABl);
    GS(VTh,g_VTh); GS(VTl,g_VTl); GS(UTh,g_UTh); GS(UTl,g_UTl);
    GS(SKTh,g_SKTh); GS(SKTl,g_SKTl);
    GS(Vf,g_Vf); GS(AO,g_AO);
    GS(Zq,g_Zq); GS(Zk,g_Zk);
    GS(faFlag,g_faFlag); GS(dCnt,g_dCnt); GS(aCnt,g_aCnt);

    const long OUT_MEM = (long)B_*S_*E_;
    const long OUT_Z   = OUT_MEM + (long)B_*H_*D_*D_;
    dim3 t256(256), t512(512);

    // prep: split HS + transpose/split weights + mem + zero flags
    prep_kernel<<<12545, t256>>>(hs, Wq, Wk, Wv, Wo, memp,
        HSh, HSl, WqTh, WqTl, WkTh, WkTl, WvTh, WvTl, WoTh, WoTl, memTh, memTl,
        faFlag, dCnt, aCnt);

    // merged projections Q|K|V with fused sigma rowdots and transposed outputs
    fused_proj<<<768, t512, G5_SMEM>>>(HSh,HSl, WqTh,WqTl, WkTh,WkTl, WvTh,WvTl,
        Qh,Ql, SQh,SQl, Kh,Kl, SKh,SKl, SKTh,SKTl, Vf, VTh,VTl, zv, Zq, Zk);

    // mega: fa ∥ delta ∥ znew ∥ memupd(waits delta) ∥ amem(waits fa) ∥ outproj(waits amem)
    fused_mega<<<1568, t512, FA_SMEM>>>(
        Qh,Ql,Kh,Kl,VTh,VTl, AO,
        SKh,SKl, SQh,SQl, memTh,memTl, Zk, Zq, Vf,
        UTh,UTl, SKTh,SKTl, zv, out+OUT_Z,
        betas, ABh,ABl, memp, out+OUT_MEM,
        WoTh,WoTl, bo, out,
        faFlag, dCnt, aCnt);
}